// round 1
// baseline (speedup 1.0000x reference)
#include <cuda_runtime.h>
#include <cuda_bf16.h>
#include <math.h>

// Problem constants
#define BB   8
#define HH   128
#define WW   128
#define NN   (HH*WW)          // 16384
#define CC   64
#define NR   256              // (H/8)*(W/8)
#define HID  256
#define EPSV 1e-5f
#define QSCALE 0.125f         // hd^-0.5, hd=64

// ---------------- scratch (device globals; no allocs allowed) ----------------
__device__ float g_h  [BB*NN*CC];    // LN1 output            33.5 MB
__device__ float g_q  [BB*NN*CC];    // scaled q              33.5 MB
__device__ float g_k  [BB*NR*CC];    // keys                  tiny
__device__ float g_v  [BB*NR*CC];    // values                tiny
__device__ float g_x2 [BB*NN*CC];    // x + proj(attn)        33.5 MB
__device__ float g_f  [(size_t)BB*NN*HID]; // fc1 out         134 MB
__device__ float g_g  [(size_t)BB*NN*HID]; // dwconv+gelu out 134 MB

// =====================================================================
// K1: LN1 + q = (h@q_w + q_b)*scale ; store h and q
// grid 2048, block 256 (8 warps, warp-per-row, 8 iterations)
// =====================================================================
__global__ __launch_bounds__(256) void k1_ln_q(
    const float* __restrict__ x, const float* __restrict__ g1,
    const float* __restrict__ b1, const float* __restrict__ qw,
    const float* __restrict__ qb)
{
    __shared__ float qws[64*64];
    __shared__ float hsh[8][64];
    int tid = threadIdx.x;
    for (int i = tid; i < 4096; i += 256) qws[i] = qw[i];
    __syncthreads();
    int warp = tid >> 5, lane = tid & 31;
    const float2* x2p = (const float2*)x;
    float2 gg = ((const float2*)g1)[lane];
    float2 bb = ((const float2*)b1)[lane];
    float2 qbb = ((const float2*)qb)[lane];
    for (int it = 0; it < 8; ++it) {
        int row = blockIdx.x*64 + it*8 + warp;
        float2 v = x2p[row*32 + lane];
        float s = v.x + v.y, ss = v.x*v.x + v.y*v.y;
        #pragma unroll
        for (int o = 16; o; o >>= 1) {
            s  += __shfl_xor_sync(0xffffffffu, s,  o);
            ss += __shfl_xor_sync(0xffffffffu, ss, o);
        }
        float mean = s * (1.f/64.f);
        float var  = ss * (1.f/64.f) - mean*mean;
        float rstd = rsqrtf(var + EPSV);
        float2 hv;
        hv.x = (v.x - mean)*rstd*gg.x + bb.x;
        hv.y = (v.y - mean)*rstd*gg.y + bb.y;
        ((float2*)g_h)[row*32 + lane] = hv;
        hsh[warp][2*lane]   = hv.x;
        hsh[warp][2*lane+1] = hv.y;
        __syncwarp();
        float2 acc = make_float2(0.f, 0.f);
        #pragma unroll
        for (int j = 0; j < 64; ++j) {
            float hj = hsh[warp][j];
            float2 w = ((const float2*)qws)[j*32 + lane];
            acc.x += hj*w.x; acc.y += hj*w.y;
        }
        acc.x = (acc.x + qbb.x) * QSCALE;
        acc.y = (acc.y + qbb.y) * QSCALE;
        ((float2*)g_q)[row*32 + lane] = acc;
        __syncwarp();
    }
}

// =====================================================================
// K2: sr conv (8x8, stride 8) + LN + kv projection -> g_k, g_v
// grid 256, block 128 (2 groups x 64 threads, 8 output rows per block)
// dyn smem: 8*4096 floats = 128 KB
// =====================================================================
__global__ __launch_bounds__(128) void k2_sr_kv(
    const float* __restrict__ srw, const float* __restrict__ srb,
    const float* __restrict__ sng, const float* __restrict__ snb,
    const float* __restrict__ kvw, const float* __restrict__ kvb)
{
    extern __shared__ float sm[];   // p_sh[8][4096]
    int tid = threadIdx.x;
    int basepos = blockIdx.x * 8;
    int b   = basepos >> 8;
    int rem = basepos & 255;
    int oh  = rem >> 4, ow0 = rem & 15;

    // stage 8 patches (each 8x8x64 = 4096 floats)
    for (int r = 0; r < 8; ++r) {
        size_t base = ((size_t)b*NN + (size_t)(oh*8)*WW + (size_t)(ow0+r)*8) * CC;
        const float4* src = (const float4*)g_h;
        size_t base4 = base >> 2;
        float4* dst = (float4*)(sm + r*4096);
        for (int k4 = tid; k4 < 1024; k4 += 128) {
            int i = k4 >> 7;       // patch row i (0..7), 128 float4 per row
            int rk = k4 & 127;
            dst[k4] = src[base4 + (size_t)i*2048 + rk];
        }
    }
    __syncthreads();

    int grp = tid >> 6, c = tid & 63;
    int r0 = grp * 4;
    float acc[4] = {0.f,0.f,0.f,0.f};
    #pragma unroll 8
    for (int t = 0; t < 4096; ++t) {
        float w = srw[t*64 + c];
        #pragma unroll
        for (int rr = 0; rr < 4; ++rr)
            acc[rr] += sm[(r0+rr)*4096 + t] * w;
    }
    __syncthreads();
    float* xr = sm;   // reuse: 8 rows x 64
    float sb = srb[c];
    for (int rr = 0; rr < 4; ++rr) xr[(r0+rr)*64 + c] = acc[rr] + sb;
    __syncthreads();

    // LN over each of 8 rows: warp wi handles rows 2wi, 2wi+1
    int warp = tid >> 5, lane = tid & 31;
    float2 sg = ((const float2*)sng)[lane];
    float2 sbb = ((const float2*)snb)[lane];
    #pragma unroll
    for (int rr = 0; rr < 2; ++rr) {
        int r = warp*2 + rr;
        float2 v = ((float2*)xr)[r*32 + lane];
        float s = v.x + v.y, ss = v.x*v.x + v.y*v.y;
        #pragma unroll
        for (int o = 16; o; o >>= 1) {
            s  += __shfl_xor_sync(0xffffffffu, s,  o);
            ss += __shfl_xor_sync(0xffffffffu, ss, o);
        }
        float mean = s*(1.f/64.f);
        float rstd = rsqrtf(ss*(1.f/64.f) - mean*mean + EPSV);
        float2 nv;
        nv.x = (v.x-mean)*rstd*sg.x + sbb.x;
        nv.y = (v.y-mean)*rstd*sg.y + sbb.y;
        ((float2*)xr)[r*32 + lane] = nv;
    }
    __syncthreads();

    // kv projection: thread tid handles kv output channel tid (0..127) for 8 rows
    float ak[8];
    float kb = kvb[tid];
    #pragma unroll
    for (int r = 0; r < 8; ++r) ak[r] = kb;
    #pragma unroll 4
    for (int j = 0; j < 64; ++j) {
        float w = kvw[j*128 + tid];
        #pragma unroll
        for (int r = 0; r < 8; ++r) ak[r] += xr[r*64 + j] * w;
    }
    for (int r = 0; r < 8; ++r) {
        int pos = basepos + r;
        if (tid < 64) g_k[pos*64 + tid]        = ak[r];
        else          g_v[pos*64 + (tid-64)]   = ak[r];
    }
}

// =====================================================================
// K3: fused attention (softmax over 256 keys) + proj + residual -> g_x2
// grid 512 (= 8 batches * 64 tiles of 256 queries), block 256 (8 warps)
// each warp: 32 queries in 8 groups of 4 (register-batched)
// dyn smem: K(256x68) + V(256x64) + P(8*4*256) + Q(8*4*64) + PW(64x64)
//         = 48128 floats = 188 KB
// =====================================================================
__global__ __launch_bounds__(256) void k3_attn(
    const float* __restrict__ x, const float* __restrict__ pw,
    const float* __restrict__ pb)
{
    extern __shared__ float sm3[];
    float* Ks = sm3;               // 256*68
    float* Vs = Ks + 256*68;       // 256*64
    float* Ps = Vs + 256*64;       // 8192
    float* Qs = Ps + 8192;         // 2048
    float* PW = Qs + 2048;         // 4096
    int tid = threadIdx.x;
    int b    = blockIdx.x >> 6;
    int tile = blockIdx.x & 63;

    for (int idx = tid; idx < NR*CC; idx += 256) {
        int m = idx >> 6, c = idx & 63;
        Ks[m*68 + c] = g_k[b*NR*CC + idx];
        Vs[idx]      = g_v[b*NR*CC + idx];
    }
    for (int i = tid; i < 4096; i += 256) PW[i] = pw[i];
    __syncthreads();

    int warp = tid >> 5, lane = tid & 31;
    float2 pbb = ((const float2*)pb)[lane];
    const float2* PW2 = (const float2*)PW;
    const float2* V2  = (const float2*)Vs;

    for (int grpi = 0; grpi < 8; ++grpi) {
        int q0 = tile*256 + warp*32 + grpi*4;          // query within batch
        size_t qbase = ((size_t)b*NN + q0) * CC;
        float4* qs4 = (float4*)(Qs + warp*256);
        const float4* qg4 = (const float4*)(g_q + qbase);
        qs4[lane]      = qg4[lane];
        qs4[lane + 32] = qg4[lane + 32];
        __syncwarp();

        float s[8][4];
        #pragma unroll
        for (int j = 0; j < 8; ++j)
            #pragma unroll
            for (int qq = 0; qq < 4; ++qq) s[j][qq] = 0.f;

        const float4* Qw4 = (const float4*)(Qs + warp*256);
        #pragma unroll 4
        for (int d4 = 0; d4 < 16; ++d4) {
            float4 qv0 = Qw4[0*16 + d4];
            float4 qv1 = Qw4[1*16 + d4];
            float4 qv2 = Qw4[2*16 + d4];
            float4 qv3 = Qw4[3*16 + d4];
            #pragma unroll
            for (int j = 0; j < 8; ++j) {
                float4 k4 = *(const float4*)&Ks[(lane + 32*j)*68 + d4*4];
                s[j][0] += k4.x*qv0.x + k4.y*qv0.y + k4.z*qv0.z + k4.w*qv0.w;
                s[j][1] += k4.x*qv1.x + k4.y*qv1.y + k4.z*qv1.z + k4.w*qv1.w;
                s[j][2] += k4.x*qv2.x + k4.y*qv2.y + k4.z*qv2.z + k4.w*qv2.w;
                s[j][3] += k4.x*qv3.x + k4.y*qv3.y + k4.z*qv3.z + k4.w*qv3.w;
            }
        }

        // softmax per query (q already scaled)
        #pragma unroll
        for (int qq = 0; qq < 4; ++qq) {
            float mx = s[0][qq];
            #pragma unroll
            for (int j = 1; j < 8; ++j) mx = fmaxf(mx, s[j][qq]);
            #pragma unroll
            for (int o = 16; o; o >>= 1) mx = fmaxf(mx, __shfl_xor_sync(0xffffffffu, mx, o));
            float sum = 0.f;
            #pragma unroll
            for (int j = 0; j < 8; ++j) { s[j][qq] = __expf(s[j][qq] - mx); sum += s[j][qq]; }
            #pragma unroll
            for (int o = 16; o; o >>= 1) sum += __shfl_xor_sync(0xffffffffu, sum, o);
            float inv = __frcp_rn(sum);
            #pragma unroll
            for (int j = 0; j < 8; ++j)
                Ps[(warp*4 + qq)*256 + 32*j + lane] = s[j][qq] * inv;
        }
        __syncwarp();

        // PV: lane owns dims (2*lane, 2*lane+1)
        float2 o[4];
        #pragma unroll
        for (int qq = 0; qq < 4; ++qq) o[qq] = make_float2(0.f, 0.f);
        #pragma unroll 4
        for (int m = 0; m < 256; ++m) {
            float2 v2 = V2[m*32 + lane];
            #pragma unroll
            for (int qq = 0; qq < 4; ++qq) {
                float pm = Ps[(warp*4 + qq)*256 + m];
                o[qq].x += pm*v2.x; o[qq].y += pm*v2.y;
            }
        }
        __syncwarp();
        // stage o (reuse Qs)
        #pragma unroll
        for (int qq = 0; qq < 4; ++qq) {
            Qs[warp*256 + qq*64 + 2*lane]     = o[qq].x;
            Qs[warp*256 + qq*64 + 2*lane + 1] = o[qq].y;
        }
        __syncwarp();

        // proj + residual
        float2 op[4];
        #pragma unroll
        for (int qq = 0; qq < 4; ++qq) op[qq] = make_float2(0.f, 0.f);
        #pragma unroll 4
        for (int j = 0; j < 64; ++j) {
            float2 w2 = PW2[j*32 + lane];
            #pragma unroll
            for (int qq = 0; qq < 4; ++qq) {
                float oj = Qs[warp*256 + qq*64 + j];
                op[qq].x += oj*w2.x; op[qq].y += oj*w2.y;
            }
        }
        #pragma unroll
        for (int qq = 0; qq < 4; ++qq) {
            size_t row = (size_t)b*NN + q0 + qq;
            float2 xin = ((const float2*)x)[row*32 + lane];
            float2 ov;
            ov.x = xin.x + op[qq].x + pbb.x;
            ov.y = xin.y + op[qq].y + pbb.y;
            ((float2*)g_x2)[row*32 + lane] = ov;
        }
        __syncwarp();
    }
}

// =====================================================================
// K4: LN2 + fc1 (64 -> 256) -> g_f
// grid 512, block 256; dyn smem = 64*256 + 8*64 floats = 66 KB
// =====================================================================
__global__ __launch_bounds__(256) void k4_ln_fc1(
    const float* __restrict__ g2, const float* __restrict__ b2,
    const float* __restrict__ w1, const float* __restrict__ fb1)
{
    extern __shared__ float sm4[];
    float* Wsh = sm4;            // 16384
    float* hn  = sm4 + 16384;    // 512
    int tid = threadIdx.x;
    for (int i = tid; i < 16384; i += 256) Wsh[i] = w1[i];
    __syncthreads();
    int warp = tid >> 5, lane = tid & 31;
    float fb = fb1[tid];
    float2 gg = ((const float2*)g2)[lane];
    float2 bb = ((const float2*)b2)[lane];
    int rowbase = blockIdx.x * 256;
    for (int ch = 0; ch < 32; ++ch) {
        int r8 = rowbase + ch*8;
        {
            int row = r8 + warp;
            float2 v = ((const float2*)g_x2)[row*32 + lane];
            float s = v.x + v.y, ss = v.x*v.x + v.y*v.y;
            #pragma unroll
            for (int o = 16; o; o >>= 1) {
                s  += __shfl_xor_sync(0xffffffffu, s,  o);
                ss += __shfl_xor_sync(0xffffffffu, ss, o);
            }
            float mean = s*(1.f/64.f);
            float rstd = rsqrtf(ss*(1.f/64.f) - mean*mean + EPSV);
            hn[warp*64 + 2*lane]     = (v.x-mean)*rstd*gg.x + bb.x;
            hn[warp*64 + 2*lane + 1] = (v.y-mean)*rstd*gg.y + bb.y;
        }
        __syncthreads();
        float acc[8] = {0,0,0,0,0,0,0,0};
        #pragma unroll 4
        for (int j = 0; j < 64; ++j) {
            float w = Wsh[j*256 + tid];
            #pragma unroll
            for (int r = 0; r < 8; ++r) acc[r] += hn[r*64 + j] * w;
        }
        #pragma unroll
        for (int r = 0; r < 8; ++r)
            g_f[(size_t)(r8 + r)*HID + tid] = acc[r] + fb;
        __syncthreads();
    }
}

// =====================================================================
// K5: depthwise 3x3 SAME + exact GELU -> g_g
// grid 131072, block 256
// =====================================================================
__global__ __launch_bounds__(256) void k5_dw_gelu(const float* __restrict__ dww)
{
    int n = blockIdx.x;
    int c = threadIdx.x;
    int w = n & 127, h = (n >> 7) & 127, b = n >> 14;
    float acc = 0.f;
    #pragma unroll
    for (int dh = -1; dh <= 1; ++dh) {
        int hh = h + dh;
        if (hh < 0 || hh > 127) continue;
        #pragma unroll
        for (int dw = -1; dw <= 1; ++dw) {
            int wv = w + dw;
            if (wv < 0 || wv > 127) continue;
            acc += g_f[((size_t)b*NN + hh*WW + wv)*HID + c]
                 * dww[((dh+1)*3 + (dw+1))*HID + c];
        }
    }
    g_g[(size_t)n*HID + c] = acc * normcdff(acc);
}

// =====================================================================
// K6: fc2 (256 -> 64) + residual -> out
// grid 512, block 256; dyn smem = 256*64 + 8*256 floats = 72 KB
// =====================================================================
__global__ __launch_bounds__(256) void k6_fc2(
    const float* __restrict__ w2, const float* __restrict__ b2,
    float* __restrict__ out)
{
    extern __shared__ float sm6[];
    float* Wsh = sm6;            // 16384
    float* gs  = sm6 + 16384;    // 2048
    int tid = threadIdx.x;
    for (int i = tid; i < 16384; i += 256) Wsh[i] = w2[i];
    __syncthreads();
    int c = tid & 63, rg = tid >> 6;
    float bc = b2[c];
    int rowbase = blockIdx.x * 256;
    for (int ch = 0; ch < 32; ++ch) {
        int r8 = rowbase + ch*8;
        #pragma unroll
        for (int r = 0; r < 8; ++r)
            gs[r*256 + tid] = g_g[(size_t)(r8 + r)*HID + tid];
        __syncthreads();
        float a0 = 0.f, a1 = 0.f;
        #pragma unroll 4
        for (int j = 0; j < 256; ++j) {
            float w = Wsh[j*64 + c];
            a0 += gs[rg*256 + j] * w;
            a1 += gs[(rg+4)*256 + j] * w;
        }
        int row0 = r8 + rg, row1 = r8 + rg + 4;
        out[row0*64 + c] = g_x2[row0*64 + c] + a0 + bc;
        out[row1*64 + c] = g_x2[row1*64 + c] + a1 + bc;
        __syncthreads();
    }
}

// =====================================================================
extern "C" void kernel_launch(void* const* d_in, const int* in_sizes, int n_in,
                              void* d_out, int out_size)
{
    const float* x     = (const float*)d_in[0];
    const float* ln1_g = (const float*)d_in[3];
    const float* ln1_b = (const float*)d_in[4];
    const float* q_w   = (const float*)d_in[5];
    const float* q_b   = (const float*)d_in[6];
    const float* kv_w  = (const float*)d_in[7];
    const float* kv_b  = (const float*)d_in[8];
    const float* pr_w  = (const float*)d_in[9];
    const float* pr_b  = (const float*)d_in[10];
    const float* sr_w  = (const float*)d_in[11];
    const float* sr_b  = (const float*)d_in[12];
    const float* srn_g = (const float*)d_in[13];
    const float* srn_b = (const float*)d_in[14];
    const float* ln2_g = (const float*)d_in[15];
    const float* ln2_b = (const float*)d_in[16];
    const float* fc1_w = (const float*)d_in[17];
    const float* fc1_b = (const float*)d_in[18];
    const float* dw_w  = (const float*)d_in[19];
    const float* fc2_w = (const float*)d_in[20];
    const float* fc2_b = (const float*)d_in[21];
    float* out = (float*)d_out;

    const int K2_SMEM = 8*4096*4;          // 131072 B
    const int K3_SMEM = (256*68 + 256*64 + 8192 + 2048 + 4096) * 4;  // 192512 B
    const int K4_SMEM = (16384 + 512) * 4; // 67584 B
    const int K6_SMEM = (16384 + 2048) * 4;// 73728 B

    cudaFuncSetAttribute(k2_sr_kv,  cudaFuncAttributeMaxDynamicSharedMemorySize, K2_SMEM);
    cudaFuncSetAttribute(k3_attn,   cudaFuncAttributeMaxDynamicSharedMemorySize, K3_SMEM);
    cudaFuncSetAttribute(k4_ln_fc1, cudaFuncAttributeMaxDynamicSharedMemorySize, K4_SMEM);
    cudaFuncSetAttribute(k6_fc2,    cudaFuncAttributeMaxDynamicSharedMemorySize, K6_SMEM);

    k1_ln_q  <<<2048, 256>>>(x, ln1_g, ln1_b, q_w, q_b);
    k2_sr_kv <<<256, 128, K2_SMEM>>>(sr_w, sr_b, srn_g, srn_b, kv_w, kv_b);
    k3_attn  <<<512, 256, K3_SMEM>>>(x, pr_w, pr_b);
    k4_ln_fc1<<<512, 256, K4_SMEM>>>(ln2_g, ln2_b, fc1_w, fc1_b);
    k5_dw_gelu<<<BB*NN, 256>>>(dw_w);
    k6_fc2   <<<512, 256, K6_SMEM>>>(fc2_w, fc2_b, out);
}

// round 3
// speedup vs baseline: 1.4852x; 1.4852x over previous
#include <cuda_runtime.h>
#include <cuda_bf16.h>
#include <math.h>

// Problem constants
#define BB   8
#define HH   128
#define WW   128
#define NN   (HH*WW)          // 16384
#define CC   64
#define NR   256              // (H/8)*(W/8)
#define HID  256
#define EPSV 1e-5f
#define QSCALE 0.125f         // hd^-0.5, hd=64

// ---------------- scratch (device globals; no allocs allowed) ----------------
__device__ float g_h  [BB*NN*CC];
__device__ float g_q  [BB*NN*CC];
__device__ float g_k  [BB*NR*CC];
__device__ float g_v  [BB*NR*CC];
__device__ float g_x2 [BB*NN*CC];
__device__ float g_f  [(size_t)BB*NN*HID];
__device__ float g_g  [(size_t)BB*NN*HID];

// packed f32x2 FMA (FFMA2) — ptxas never emits this from C++; PTX only
__device__ __forceinline__ float2 ffma2(const float2 a, const float2 b, const float2 c) {
    float2 d;
    asm("fma.rn.f32x2 %0, %1, %2, %3;"
        : "=l"(reinterpret_cast<unsigned long long&>(d))
        : "l"(reinterpret_cast<const unsigned long long&>(a)),
          "l"(reinterpret_cast<const unsigned long long&>(b)),
          "l"(reinterpret_cast<const unsigned long long&>(c)));
    return d;
}
__device__ __forceinline__ float2 dup2(float s) { return make_float2(s, s); }

// =====================================================================
// K1: LN1 + q = (h@q_w + q_b)*scale ; store h and q
// grid 2048, block 256; tile = 64 rows. thread: 8 rows x 1 col-pair.
// =====================================================================
__global__ __launch_bounds__(256) void k1_ln_q(
    const float* __restrict__ x, const float* __restrict__ g1,
    const float* __restrict__ b1, const float* __restrict__ qw,
    const float* __restrict__ qb)
{
    __shared__ float qws[64*64];     // [k][c]
    __shared__ float hnT[64*68];     // [k][row] (pad 68)
    int tid = threadIdx.x;
    for (int i = tid; i < 4096; i += 256) qws[i] = qw[i];
    int warp = tid >> 5, lane = tid & 31;
    int rowbase = blockIdx.x * 64;
    float2 gg = ((const float2*)g1)[lane];
    float2 bbv = ((const float2*)b1)[lane];
    #pragma unroll
    for (int i = 0; i < 8; ++i) {
        int lr = warp*8 + i;
        int row = rowbase + lr;
        float2 v = ((const float2*)x)[row*32 + lane];
        float s = v.x + v.y, ss = v.x*v.x + v.y*v.y;
        #pragma unroll
        for (int o = 16; o; o >>= 1) {
            s  += __shfl_xor_sync(0xffffffffu, s,  o);
            ss += __shfl_xor_sync(0xffffffffu, ss, o);
        }
        float mean = s * (1.f/64.f);
        float rstd = rsqrtf(ss*(1.f/64.f) - mean*mean + EPSV);
        float2 hv;
        hv.x = (v.x - mean)*rstd*gg.x + bbv.x;
        hv.y = (v.y - mean)*rstd*gg.y + bbv.y;
        ((float2*)g_h)[row*32 + lane] = hv;
        hnT[(2*lane)*68 + lr]   = hv.x;
        hnT[(2*lane+1)*68 + lr] = hv.y;
    }
    __syncthreads();

    int cg = tid & 31, rg = tid >> 5;
    float2 acc[8];
    #pragma unroll
    for (int r = 0; r < 8; ++r) acc[r] = make_float2(0.f, 0.f);
    #pragma unroll 8
    for (int k = 0; k < 64; ++k) {
        float4 a0 = *(const float4*)&hnT[k*68 + rg*8];
        float4 a1 = *(const float4*)&hnT[k*68 + rg*8 + 4];
        float2 w2 = *(const float2*)&qws[k*64 + 2*cg];
        acc[0] = ffma2(dup2(a0.x), w2, acc[0]);
        acc[1] = ffma2(dup2(a0.y), w2, acc[1]);
        acc[2] = ffma2(dup2(a0.z), w2, acc[2]);
        acc[3] = ffma2(dup2(a0.w), w2, acc[3]);
        acc[4] = ffma2(dup2(a1.x), w2, acc[4]);
        acc[5] = ffma2(dup2(a1.y), w2, acc[5]);
        acc[6] = ffma2(dup2(a1.z), w2, acc[6]);
        acc[7] = ffma2(dup2(a1.w), w2, acc[7]);
    }
    float2 qbp = ((const float2*)qb)[cg];
    #pragma unroll
    for (int r = 0; r < 8; ++r) {
        int row = rowbase + rg*8 + r;
        float2 o;
        o.x = (acc[r].x + qbp.x) * QSCALE;
        o.y = (acc[r].y + qbp.y) * QSCALE;
        ((float2*)g_q)[row*32 + cg] = o;
    }
}

// =====================================================================
// K2: sr conv (8x8, stride 8) + LN + kv projection -> g_k, g_v
// grid 256, block 128. conv: thread = 2 rows x 1 col-pair, FFMA2.
// dyn smem: 8*4096 floats = 128 KB
// =====================================================================
__global__ __launch_bounds__(128) void k2_sr_kv(
    const float* __restrict__ srw, const float* __restrict__ srb,
    const float* __restrict__ sng, const float* __restrict__ snb,
    const float* __restrict__ kvw, const float* __restrict__ kvb)
{
    extern __shared__ float sm[];   // p_sh[8][4096]
    int tid = threadIdx.x;
    int basepos = blockIdx.x * 8;
    int b   = basepos >> 8;
    int rem = basepos & 255;
    int oh  = rem >> 4, ow0 = rem & 15;

    for (int r = 0; r < 8; ++r) {
        size_t base = ((size_t)b*NN + (size_t)(oh*8)*WW + (size_t)(ow0+r)*8) * CC;
        const float4* src = (const float4*)g_h;
        size_t base4 = base >> 2;
        float4* dst = (float4*)(sm + r*4096);
        for (int k4 = tid; k4 < 1024; k4 += 128) {
            int i = k4 >> 7;
            int rk = k4 & 127;
            dst[k4] = src[base4 + (size_t)i*2048 + rk];
        }
    }
    __syncthreads();

    int cp = tid & 31, rg = tid >> 5;          // col-pair, row group (2 rows)
    float2 acc0 = make_float2(0.f,0.f), acc1 = make_float2(0.f,0.f);
    const float2* srw2 = (const float2*)srw;
    const float* a0p = sm + (rg*2)*4096;
    const float* a1p = sm + (rg*2+1)*4096;
    #pragma unroll 8
    for (int t = 0; t < 4096; ++t) {
        float2 w = srw2[t*32 + cp];
        acc0 = ffma2(dup2(a0p[t]), w, acc0);
        acc1 = ffma2(dup2(a1p[t]), w, acc1);
    }
    __syncthreads();
    float* xr = sm;
    float2 sbp = ((const float2*)srb)[cp];
    float2 o0, o1;
    o0.x = acc0.x + sbp.x; o0.y = acc0.y + sbp.y;
    o1.x = acc1.x + sbp.x; o1.y = acc1.y + sbp.y;
    *(float2*)&xr[(rg*2)*64 + 2*cp]   = o0;
    *(float2*)&xr[(rg*2+1)*64 + 2*cp] = o1;
    __syncthreads();

    int warp = tid >> 5, lane = tid & 31;
    float2 sg  = ((const float2*)sng)[lane];
    float2 sbb = ((const float2*)snb)[lane];
    #pragma unroll
    for (int rr = 0; rr < 2; ++rr) {
        int r = warp*2 + rr;
        float2 v = ((float2*)xr)[r*32 + lane];
        float s = v.x + v.y, ss = v.x*v.x + v.y*v.y;
        #pragma unroll
        for (int o = 16; o; o >>= 1) {
            s  += __shfl_xor_sync(0xffffffffu, s,  o);
            ss += __shfl_xor_sync(0xffffffffu, ss, o);
        }
        float mean = s*(1.f/64.f);
        float rstd = rsqrtf(ss*(1.f/64.f) - mean*mean + EPSV);
        float2 nv;
        nv.x = (v.x-mean)*rstd*sg.x + sbb.x;
        nv.y = (v.y-mean)*rstd*sg.y + sbb.y;
        ((float2*)xr)[r*32 + lane] = nv;
    }
    __syncthreads();

    float ak[8];
    float kb = kvb[tid];
    #pragma unroll
    for (int r = 0; r < 8; ++r) ak[r] = kb;
    #pragma unroll 4
    for (int j = 0; j < 64; ++j) {
        float w = kvw[j*128 + tid];
        #pragma unroll
        for (int r = 0; r < 8; ++r) ak[r] += xr[r*64 + j] * w;
    }
    for (int r = 0; r < 8; ++r) {
        int pos = basepos + r;
        if (tid < 64) g_k[pos*64 + tid]      = ak[r];
        else          g_v[pos*64 + (tid-64)] = ak[r];
    }
}

// =====================================================================
// K3: fused attention + proj + residual -> g_x2
// grid 512 (8 batches x 64 tiles of 256 q), block 256 (8 warps).
// warp: 32 queries in 8 passes of 4 (2 f32x2 pairs).
// smem floats: Ks 256*65 + Vs 256*64 + PW 4096 + QsT 8*256 + PsT 8*1024 + OsT 8*256
// =====================================================================
__global__ __launch_bounds__(256) void k3_attn(
    const float* __restrict__ x, const float* __restrict__ pw,
    const float* __restrict__ pb)
{
    extern __shared__ float sm3[];
    float* Ks  = sm3;                  // [256][65]
    float* Vs  = Ks + 256*65;          // [256][64]
    float* PW  = Vs + 256*64;          // [64][64]
    float* QsT = PW + 4096;            // [warp][64][4]
    float* PsT = QsT + 8*256;          // [warp][256][4]
    float* OsT = PsT + 8*1024;         // [warp][64][4]
    int tid = threadIdx.x;
    int b    = blockIdx.x >> 6;
    int tile = blockIdx.x & 63;

    for (int idx = tid; idx < NR*CC; idx += 256) {
        int m = idx >> 6, c = idx & 63;
        Ks[m*65 + c] = g_k[b*NR*CC + idx];
        Vs[idx]      = g_v[b*NR*CC + idx];
    }
    for (int i = tid; i < 4096; i += 256) PW[i] = pw[i];
    __syncthreads();

    int warp = tid >> 5, lane = tid & 31;
    float* QsTw = QsT + warp*256;
    float* PsTw = PsT + warp*1024;
    float* OsTw = OsT + warp*256;
    float2 pbb = ((const float2*)pb)[lane];
    const float2* PW2 = (const float2*)PW;
    const float2* V2  = (const float2*)Vs;
    const float*  KsL = Ks + lane*65;
    const float2* gq2 = (const float2*)g_q;
    const float2* x2  = (const float2*)x;

    for (int pass = 0; pass < 8; ++pass) {
        int q0 = tile*256 + warp*32 + pass*4;
        // stage 4 queries transposed: QsTw[d*4 + qi]
        #pragma unroll
        for (int qi = 0; qi < 4; ++qi) {
            float2 v = gq2[((size_t)b*NN + q0 + qi)*32 + lane];
            QsTw[(2*lane)*4 + qi]   = v.x;
            QsTw[(2*lane+1)*4 + qi] = v.y;
        }
        __syncwarp();

        // ---- QK: s[j][p], key = lane+32j, p = query pair ----
        float2 s[8][2];
        #pragma unroll
        for (int j = 0; j < 8; ++j) { s[j][0] = make_float2(0.f,0.f); s[j][1] = make_float2(0.f,0.f); }
        #pragma unroll 8
        for (int d = 0; d < 64; ++d) {
            float4 qp = *(const float4*)&QsTw[d*4];
            float2 p0 = make_float2(qp.x, qp.y);
            float2 p1 = make_float2(qp.z, qp.w);
            #pragma unroll
            for (int j = 0; j < 8; ++j) {
                float kd = KsL[j*2080 + d];
                float2 kk = dup2(kd);
                s[j][0] = ffma2(kk, p0, s[j][0]);
                s[j][1] = ffma2(kk, p1, s[j][1]);
            }
        }

        // ---- softmax (4 queries) + write PsT ----
        #pragma unroll
        for (int p = 0; p < 2; ++p) {
            float mxx = s[0][p].x, mxy = s[0][p].y;
            #pragma unroll
            for (int j = 1; j < 8; ++j) { mxx = fmaxf(mxx, s[j][p].x); mxy = fmaxf(mxy, s[j][p].y); }
            #pragma unroll
            for (int o = 16; o; o >>= 1) {
                mxx = fmaxf(mxx, __shfl_xor_sync(0xffffffffu, mxx, o));
                mxy = fmaxf(mxy, __shfl_xor_sync(0xffffffffu, mxy, o));
            }
            float sx = 0.f, sy = 0.f;
            #pragma unroll
            for (int j = 0; j < 8; ++j) {
                s[j][p].x = __expf(s[j][p].x - mxx); sx += s[j][p].x;
                s[j][p].y = __expf(s[j][p].y - mxy); sy += s[j][p].y;
            }
            #pragma unroll
            for (int o = 16; o; o >>= 1) {
                sx += __shfl_xor_sync(0xffffffffu, sx, o);
                sy += __shfl_xor_sync(0xffffffffu, sy, o);
            }
            float ix = __frcp_rn(sx), iy = __frcp_rn(sy);
            #pragma unroll
            for (int j = 0; j < 8; ++j) {
                PsTw[(32*j+lane)*4 + 2*p]     = s[j][p].x * ix;
                PsTw[(32*j+lane)*4 + 2*p + 1] = s[j][p].y * iy;
            }
        }
        __syncwarp();

        // ---- PV: lane owns dim pair (2lane,2lane+1) for 4 queries ----
        float2 o[4];
        #pragma unroll
        for (int qi = 0; qi < 4; ++qi) o[qi] = make_float2(0.f,0.f);
        #pragma unroll 4
        for (int m = 0; m < 256; ++m) {
            float4 pp = *(const float4*)&PsTw[m*4];
            float2 v2 = V2[m*32 + lane];
            o[0] = ffma2(dup2(pp.x), v2, o[0]);
            o[1] = ffma2(dup2(pp.y), v2, o[1]);
            o[2] = ffma2(dup2(pp.z), v2, o[2]);
            o[3] = ffma2(dup2(pp.w), v2, o[3]);
        }
        #pragma unroll
        for (int qi = 0; qi < 4; ++qi) {
            OsTw[(2*lane)*4 + qi]   = o[qi].x;
            OsTw[(2*lane+1)*4 + qi] = o[qi].y;
        }
        __syncwarp();

        // ---- proj: lane owns out-dim pair ----
        float2 op[4];
        #pragma unroll
        for (int qi = 0; qi < 4; ++qi) op[qi] = make_float2(0.f,0.f);
        #pragma unroll 8
        for (int j = 0; j < 64; ++j) {
            float4 of = *(const float4*)&OsTw[j*4];
            float2 w2 = PW2[j*32 + lane];
            op[0] = ffma2(dup2(of.x), w2, op[0]);
            op[1] = ffma2(dup2(of.y), w2, op[1]);
            op[2] = ffma2(dup2(of.z), w2, op[2]);
            op[3] = ffma2(dup2(of.w), w2, op[3]);
        }
        #pragma unroll
        for (int qi = 0; qi < 4; ++qi) {
            size_t row = (size_t)b*NN + q0 + qi;
            float2 xin = x2[row*32 + lane];
            float2 ov;
            ov.x = xin.x + op[qi].x + pbb.x;
            ov.y = xin.y + op[qi].y + pbb.y;
            ((float2*)g_x2)[row*32 + lane] = ov;
        }
        __syncwarp();
    }
}

// =====================================================================
// K4: LN2 + fc1 (64 -> 256) -> g_f
// grid 2048, block 256; tile 64 rows x 256 cols, thread 8x8.
// dyn smem: Wsh 64*256 + hnT 64*68
// =====================================================================
__global__ __launch_bounds__(256) void k4_ln_fc1(
    const float* __restrict__ g2, const float* __restrict__ b2,
    const float* __restrict__ w1, const float* __restrict__ fb1)
{
    extern __shared__ float sm4[];
    float* Wsh = sm4;              // [64][256]
    float* hnT = sm4 + 16384;      // [64][68]
    int tid = threadIdx.x;
    for (int i = tid; i < 16384; i += 256) Wsh[i] = w1[i];
    int warp = tid >> 5, lane = tid & 31;
    int rowbase = blockIdx.x * 64;
    float2 gg = ((const float2*)g2)[lane];
    float2 bb = ((const float2*)b2)[lane];
    #pragma unroll
    for (int i = 0; i < 8; ++i) {
        int lr = warp*8 + i;
        int row = rowbase + lr;
        float2 v = ((const float2*)g_x2)[row*32 + lane];
        float s = v.x + v.y, ss = v.x*v.x + v.y*v.y;
        #pragma unroll
        for (int o = 16; o; o >>= 1) {
            s  += __shfl_xor_sync(0xffffffffu, s,  o);
            ss += __shfl_xor_sync(0xffffffffu, ss, o);
        }
        float mean = s*(1.f/64.f);
        float rstd = rsqrtf(ss*(1.f/64.f) - mean*mean + EPSV);
        hnT[(2*lane)*68 + lr]   = (v.x-mean)*rstd*gg.x + bb.x;
        hnT[(2*lane+1)*68 + lr] = (v.y-mean)*rstd*gg.y + bb.y;
    }
    __syncthreads();

    int cg = tid & 31, rg = tid >> 5;
    float2 acc[8][4];
    #pragma unroll
    for (int r = 0; r < 8; ++r)
        #pragma unroll
        for (int p = 0; p < 4; ++p) acc[r][p] = make_float2(0.f,0.f);
    #pragma unroll 4
    for (int k = 0; k < 64; ++k) {
        float4 a0 = *(const float4*)&hnT[k*68 + rg*8];
        float4 a1 = *(const float4*)&hnT[k*68 + rg*8 + 4];
        float4 b0 = *(const float4*)&Wsh[k*256 + cg*8];
        float4 b1 = *(const float4*)&Wsh[k*256 + cg*8 + 4];
        float2 w0 = make_float2(b0.x, b0.y), w1p = make_float2(b0.z, b0.w);
        float2 w2 = make_float2(b1.x, b1.y), w3  = make_float2(b1.z, b1.w);
        float a[8] = {a0.x,a0.y,a0.z,a0.w,a1.x,a1.y,a1.z,a1.w};
        #pragma unroll
        for (int r = 0; r < 8; ++r) {
            float2 ad = dup2(a[r]);
            acc[r][0] = ffma2(ad, w0,  acc[r][0]);
            acc[r][1] = ffma2(ad, w1p, acc[r][1]);
            acc[r][2] = ffma2(ad, w2,  acc[r][2]);
            acc[r][3] = ffma2(ad, w3,  acc[r][3]);
        }
    }
    float4 fba = *(const float4*)&fb1[cg*8];
    float4 fbb = *(const float4*)&fb1[cg*8 + 4];
    #pragma unroll
    for (int r = 0; r < 8; ++r) {
        size_t row = rowbase + rg*8 + r;
        float4 o0 = make_float4(acc[r][0].x + fba.x, acc[r][0].y + fba.y,
                                acc[r][1].x + fba.z, acc[r][1].y + fba.w);
        float4 o1 = make_float4(acc[r][2].x + fbb.x, acc[r][2].y + fbb.y,
                                acc[r][3].x + fbb.z, acc[r][3].y + fbb.w);
        *(float4*)&g_f[row*HID + cg*8]     = o0;
        *(float4*)&g_f[row*HID + cg*8 + 4] = o1;
    }
}

// =====================================================================
// K5: depthwise 3x3 SAME + exact GELU -> g_g
// grid 32768, block 256 (4 pixels x 64 channel-quads)
// =====================================================================
__global__ __launch_bounds__(256) void k5_dw_gelu(const float* __restrict__ dww)
{
    int px = blockIdx.x * 4 + (threadIdx.x >> 6);
    int c4 = (threadIdx.x & 63) * 4;
    int w = px & 127, h = (px >> 7) & 127, b = px >> 14;
    float4 acc = make_float4(0.f,0.f,0.f,0.f);
    #pragma unroll
    for (int dh = -1; dh <= 1; ++dh) {
        int hh = h + dh;
        if (hh < 0 || hh > 127) continue;
        #pragma unroll
        for (int dw = -1; dw <= 1; ++dw) {
            int wv = w + dw;
            if (wv < 0 || wv > 127) continue;
            float4 f  = *(const float4*)&g_f[((size_t)b*NN + hh*WW + wv)*HID + c4];
            float4 wt = *(const float4*)&dww[((dh+1)*3 + (dw+1))*HID + c4];
            acc.x += f.x*wt.x; acc.y += f.y*wt.y;
            acc.z += f.z*wt.z; acc.w += f.w*wt.w;
        }
    }
    float4 o;
    o.x = acc.x * normcdff(acc.x);
    o.y = acc.y * normcdff(acc.y);
    o.z = acc.z * normcdff(acc.z);
    o.w = acc.w * normcdff(acc.w);
    *(float4*)&g_g[(size_t)px*HID + c4] = o;
}

// =====================================================================
// K6: fc2 (256 -> 64) + residual -> out
// grid 1024, block 256; tile 128 rows x 64 cols, thread 8x4, K chunked.
// dyn smem: As 128*68 + Ws 64*64
// =====================================================================
__global__ __launch_bounds__(256) void k6_fc2(
    const float* __restrict__ w2, const float* __restrict__ b2,
    float* __restrict__ out)
{
    extern __shared__ float sm6[];
    float* As = sm6;               // [128][68]
    float* Ws = sm6 + 128*68;      // [64][64]
    int tid = threadIdx.x;
    int rowbase = blockIdx.x * 128;
    int cg = tid & 15, rg = tid >> 4;
    float2 acc[8][2];
    #pragma unroll
    for (int r = 0; r < 8; ++r) { acc[r][0] = make_float2(0.f,0.f); acc[r][1] = make_float2(0.f,0.f); }

    for (int kc = 0; kc < 4; ++kc) {
        for (int idx = tid; idx < 128*16; idx += 256) {
            int row = idx >> 4, q = idx & 15;
            *(float4*)&As[row*68 + q*4] =
                *(const float4*)&g_g[(size_t)(rowbase+row)*HID + kc*64 + q*4];
        }
        for (int idx = tid; idx < 64*16; idx += 256) {
            int k = idx >> 4, q = idx & 15;
            *(float4*)&Ws[k*64 + q*4] = *(const float4*)&w2[(kc*64 + k)*64 + q*4];
        }
        __syncthreads();
        #pragma unroll 8
        for (int k = 0; k < 64; ++k) {
            float4 bv = *(const float4*)&Ws[k*64 + cg*4];
            float2 w0 = make_float2(bv.x, bv.y), w1p = make_float2(bv.z, bv.w);
            #pragma unroll
            for (int r = 0; r < 8; ++r) {
                float2 ad = dup2(As[(rg*8 + r)*68 + k]);
                acc[r][0] = ffma2(ad, w0,  acc[r][0]);
                acc[r][1] = ffma2(ad, w1p, acc[r][1]);
            }
        }
        __syncthreads();
    }
    float4 bb = *(const float4*)&b2[cg*4];
    #pragma unroll
    for (int r = 0; r < 8; ++r) {
        size_t row = rowbase + rg*8 + r;
        float4 res = *(const float4*)&g_x2[row*64 + cg*4];
        float4 o = make_float4(res.x + acc[r][0].x + bb.x,
                               res.y + acc[r][0].y + bb.y,
                               res.z + acc[r][1].x + bb.z,
                               res.w + acc[r][1].y + bb.w);
        *(float4*)&out[row*64 + cg*4] = o;
    }
}

// =====================================================================
extern "C" void kernel_launch(void* const* d_in, const int* in_sizes, int n_in,
                              void* d_out, int out_size)
{
    const float* x     = (const float*)d_in[0];
    const float* ln1_g = (const float*)d_in[3];
    const float* ln1_b = (const float*)d_in[4];
    const float* q_w   = (const float*)d_in[5];
    const float* q_b   = (const float*)d_in[6];
    const float* kv_w  = (const float*)d_in[7];
    const float* kv_b  = (const float*)d_in[8];
    const float* pr_w  = (const float*)d_in[9];
    const float* pr_b  = (const float*)d_in[10];
    const float* sr_w  = (const float*)d_in[11];
    const float* sr_b  = (const float*)d_in[12];
    const float* srn_g = (const float*)d_in[13];
    const float* srn_b = (const float*)d_in[14];
    const float* ln2_g = (const float*)d_in[15];
    const float* ln2_b = (const float*)d_in[16];
    const float* fc1_w = (const float*)d_in[17];
    const float* fc1_b = (const float*)d_in[18];
    const float* dw_w  = (const float*)d_in[19];
    const float* fc2_w = (const float*)d_in[20];
    const float* fc2_b = (const float*)d_in[21];
    float* out = (float*)d_out;

    const int K2_SMEM = 8*4096*4;                                   // 131072 B
    const int K3_SMEM = (256*65 + 256*64 + 4096 + 8*256 + 8*1024 + 8*256) * 4; // 197632 B
    const int K4_SMEM = (16384 + 64*68) * 4;                        // 82944 B
    const int K6_SMEM = (128*68 + 64*64) * 4;                       // 51200 B

    cudaFuncSetAttribute(k2_sr_kv,  cudaFuncAttributeMaxDynamicSharedMemorySize, K2_SMEM);
    cudaFuncSetAttribute(k3_attn,   cudaFuncAttributeMaxDynamicSharedMemorySize, K3_SMEM);
    cudaFuncSetAttribute(k4_ln_fc1, cudaFuncAttributeMaxDynamicSharedMemorySize, K4_SMEM);
    cudaFuncSetAttribute(k6_fc2,    cudaFuncAttributeMaxDynamicSharedMemorySize, K6_SMEM);

    k1_ln_q  <<<2048, 256>>>(x, ln1_g, ln1_b, q_w, q_b);
    k2_sr_kv <<<256, 128, K2_SMEM>>>(sr_w, sr_b, srn_g, srn_b, kv_w, kv_b);
    k3_attn  <<<512, 256, K3_SMEM>>>(x, pr_w, pr_b);
    k4_ln_fc1<<<2048, 256, K4_SMEM>>>(ln2_g, ln2_b, fc1_w, fc1_b);
    k5_dw_gelu<<<32768, 256>>>(dw_w);
    k6_fc2   <<<1024, 256, K6_SMEM>>>(fc2_w, fc2_b, out);
}

// round 4
// speedup vs baseline: 1.5342x; 1.0330x over previous
#include <cuda_runtime.h>
#include <cuda_bf16.h>
#include <math.h>

#define BB   8
#define HH   128
#define WW   128
#define NN   (HH*WW)          // 16384
#define CC   64
#define NR   256
#define HID  256
#define EPSV 1e-5f
#define QSCALE 0.125f

__device__ float g_h  [BB*NN*CC];
__device__ float g_q  [BB*NN*CC];
__device__ float g_k  [BB*NR*CC];
__device__ float g_v  [BB*NR*CC];
__device__ float g_x2 [BB*NN*CC];
__device__ float g_f  [(size_t)BB*NN*HID];
__device__ float g_g  [(size_t)BB*NN*HID];

__device__ __forceinline__ float2 ffma2(const float2 a, const float2 b, const float2 c) {
    float2 d;
    asm("fma.rn.f32x2 %0, %1, %2, %3;"
        : "=l"(reinterpret_cast<unsigned long long&>(d))
        : "l"(reinterpret_cast<const unsigned long long&>(a)),
          "l"(reinterpret_cast<const unsigned long long&>(b)),
          "l"(reinterpret_cast<const unsigned long long&>(c)));
    return d;
}
__device__ __forceinline__ float2 dup2(float s) { return make_float2(s, s); }

// =====================================================================
// K1: LN1 + q-proj. grid 1024, block 256. tile 128 rows x 64 cols.
// thread micro-tile 8 rows x 4 cols. dyn smem 50176 B.
// =====================================================================
__global__ __launch_bounds__(256) void k1_ln_q(
    const float* __restrict__ x, const float* __restrict__ g1,
    const float* __restrict__ b1, const float* __restrict__ qw,
    const float* __restrict__ qb)
{
    extern __shared__ float sm1[];
    float* qws = sm1;           // [64][64]
    float* hnT = sm1 + 4096;    // [64][132]
    int tid = threadIdx.x, warp = tid >> 5, lane = tid & 31;
    int rowbase = blockIdx.x * 128;
    for (int i = tid; i < 4096; i += 256) qws[i] = qw[i];
    float2 gg = ((const float2*)g1)[lane];
    float2 bbv = ((const float2*)b1)[lane];
    #pragma unroll
    for (int i = 0; i < 16; ++i) {
        int lr = warp*16 + i;
        int row = rowbase + lr;
        float2 v = ((const float2*)x)[row*32 + lane];
        float s = v.x + v.y, ss = v.x*v.x + v.y*v.y;
        #pragma unroll
        for (int o = 16; o; o >>= 1) {
            s  += __shfl_xor_sync(0xffffffffu, s,  o);
            ss += __shfl_xor_sync(0xffffffffu, ss, o);
        }
        float mean = s * (1.f/64.f);
        float rstd = rsqrtf(ss*(1.f/64.f) - mean*mean + EPSV);
        float2 hv;
        hv.x = (v.x - mean)*rstd*gg.x + bbv.x;
        hv.y = (v.y - mean)*rstd*gg.y + bbv.y;
        ((float2*)g_h)[row*32 + lane] = hv;
        hnT[(2*lane)*132 + lr]   = hv.x;
        hnT[(2*lane+1)*132 + lr] = hv.y;
    }
    __syncthreads();

    int tx = tid & 15, ty = tid >> 4;
    float2 acc[8][2];
    #pragma unroll
    for (int r = 0; r < 8; ++r) { acc[r][0] = make_float2(0.f,0.f); acc[r][1] = make_float2(0.f,0.f); }
    #pragma unroll 4
    for (int k = 0; k < 64; ++k) {
        float4 a0 = *(const float4*)&hnT[k*132 + ty*8];
        float4 a1 = *(const float4*)&hnT[k*132 + ty*8 + 4];
        float4 w4 = *(const float4*)&qws[k*64 + tx*4];
        float2 w0 = make_float2(w4.x, w4.y), w1p = make_float2(w4.z, w4.w);
        float a[8] = {a0.x,a0.y,a0.z,a0.w,a1.x,a1.y,a1.z,a1.w};
        #pragma unroll
        for (int r = 0; r < 8; ++r) {
            float2 ad = dup2(a[r]);
            acc[r][0] = ffma2(ad, w0,  acc[r][0]);
            acc[r][1] = ffma2(ad, w1p, acc[r][1]);
        }
    }
    float4 qb4 = *(const float4*)&qb[tx*4];
    #pragma unroll
    for (int r = 0; r < 8; ++r) {
        int row = rowbase + ty*8 + r;
        float4 o = make_float4((acc[r][0].x + qb4.x)*QSCALE,
                               (acc[r][0].y + qb4.y)*QSCALE,
                               (acc[r][1].x + qb4.z)*QSCALE,
                               (acc[r][1].y + qb4.w)*QSCALE);
        *(float4*)&g_q[(size_t)row*64 + tx*4] = o;
    }
}

// =====================================================================
// K2: sr conv (8x8/s8) + LN + kv proj. grid 256, block 256. smem 128 KB.
// =====================================================================
__global__ __launch_bounds__(256) void k2_sr_kv(
    const float* __restrict__ srw, const float* __restrict__ srb,
    const float* __restrict__ sng, const float* __restrict__ snb,
    const float* __restrict__ kvw, const float* __restrict__ kvb)
{
    extern __shared__ float sm[];   // 8 patches x 4096
    int tid = threadIdx.x;
    int basepos = blockIdx.x * 8;
    int b   = basepos >> 8;
    int rem = basepos & 255;
    int oh  = rem >> 4, ow0 = rem & 15;

    for (int r = 0; r < 8; ++r) {
        size_t base4 = (((size_t)b*NN + (size_t)(oh*8)*WW + (size_t)(ow0+r)*8) * CC) >> 2;
        const float4* src = (const float4*)g_h;
        float4* dst = (float4*)(sm + r*4096);
        for (int k4 = tid; k4 < 1024; k4 += 256) {
            int i = k4 >> 7, rk = k4 & 127;
            dst[k4] = src[base4 + (size_t)i*2048 + rk];
        }
    }
    __syncthreads();

    int cp = tid & 31, r = tid >> 5;
    float2 acc = make_float2(0.f, 0.f);
    const float2* srw2 = (const float2*)srw;
    const float* ap = sm + r*4096;
    #pragma unroll 8
    for (int t = 0; t < 4096; ++t)
        acc = ffma2(dup2(ap[t]), srw2[t*32 + cp], acc);
    __syncthreads();
    float* xr = sm;
    float2 sbp = ((const float2*)srb)[cp];
    acc.x += sbp.x; acc.y += sbp.y;
    ((float2*)xr)[r*32 + cp] = acc;
    __syncthreads();

    int warp = tid >> 5, lane = tid & 31;
    {
        float2 sg  = ((const float2*)sng)[lane];
        float2 sbb = ((const float2*)snb)[lane];
        float2 v = ((float2*)xr)[warp*32 + lane];
        float s = v.x + v.y, ss = v.x*v.x + v.y*v.y;
        #pragma unroll
        for (int o = 16; o; o >>= 1) {
            s  += __shfl_xor_sync(0xffffffffu, s,  o);
            ss += __shfl_xor_sync(0xffffffffu, ss, o);
        }
        float mean = s*(1.f/64.f);
        float rstd = rsqrtf(ss*(1.f/64.f) - mean*mean + EPSV);
        float2 nv;
        nv.x = (v.x-mean)*rstd*sg.x + sbb.x;
        nv.y = (v.y-mean)*rstd*sg.y + sbb.y;
        ((float2*)xr)[warp*32 + lane] = nv;
    }
    __syncthreads();

    int ch = tid & 127, rh = tid >> 7;
    float ak[4];
    float kb = kvb[ch];
    #pragma unroll
    for (int rr = 0; rr < 4; ++rr) ak[rr] = kb;
    #pragma unroll 4
    for (int j = 0; j < 64; ++j) {
        float w = kvw[j*128 + ch];
        #pragma unroll
        for (int rr = 0; rr < 4; ++rr) ak[rr] += xr[(rh*4+rr)*64 + j] * w;
    }
    #pragma unroll
    for (int rr = 0; rr < 4; ++rr) {
        int pos = basepos + rh*4 + rr;
        if (ch < 64) g_k[pos*64 + ch]      = ak[rr];
        else         g_v[pos*64 + ch - 64] = ak[rr];
    }
}

// =====================================================================
// K3: fused attention + proj + residual. grid 512, block 256.
// K transposed in smem; 8 queries/warp-pass; FFMA2 over key pairs.
// dyn smem = 213504 B.
// =====================================================================
__global__ __launch_bounds__(256) void k3_attn(
    const float* __restrict__ x, const float* __restrict__ pw,
    const float* __restrict__ pb)
{
    extern __shared__ float sm3[];
    float* KsT = sm3;               // [64][258]
    float* Vs  = KsT + 64*258;      // [256][64]
    float* PW  = Vs + 16384;        // [64][64]
    float* WSb = PW + 4096;         // per-warp: 2048 floats each
    int tid = threadIdx.x;
    int b    = blockIdx.x >> 6;
    int tile = blockIdx.x & 63;

    for (int idx = tid; idx < NR*CC; idx += 256) {
        int m = idx >> 6, d = idx & 63;
        KsT[d*258 + m] = g_k[b*NR*CC + idx];
        Vs[idx]        = g_v[b*NR*CC + idx];
    }
    for (int i = tid; i < 4096; i += 256) PW[i] = pw[i];
    __syncthreads();

    int warp = tid >> 5, lane = tid & 31;
    float* QsT = WSb + warp*2048;   // [64][12]
    float* PsT = QsT + 768;         // [256][4]
    float* OsT = PsT + 1024;        // [64][4]
    int dq = lane & 15, mh = lane >> 4;
    const float2* gq2 = (const float2*)g_q;
    float4 pb4 = *(const float4*)&pb[dq*4];

    for (int pass = 0; pass < 4; ++pass) {
        int q0 = tile*256 + warp*32 + pass*8;
        // stage 8 queries transposed
        #pragma unroll
        for (int qi = 0; qi < 8; ++qi) {
            float2 v = gq2[((size_t)b*NN + q0 + qi)*32 + lane];
            QsT[(2*lane)*12 + qi]   = v.x;
            QsT[(2*lane+1)*12 + qi] = v.y;
        }
        __syncwarp();

        // QK: s[j][qi] = float2 over key pair (64j+2lane, +1)
        float2 s[4][8];
        #pragma unroll
        for (int j = 0; j < 4; ++j)
            #pragma unroll
            for (int qi = 0; qi < 8; ++qi) s[j][qi] = make_float2(0.f, 0.f);
        #pragma unroll 4
        for (int d = 0; d < 64; ++d) {
            float4 qA = *(const float4*)&QsT[d*12];
            float4 qB = *(const float4*)&QsT[d*12 + 4];
            float qv[8] = {qA.x,qA.y,qA.z,qA.w,qB.x,qB.y,qB.z,qB.w};
            #pragma unroll
            for (int j = 0; j < 4; ++j) {
                float2 kk = *(const float2*)&KsT[d*258 + j*64 + 2*lane];
                #pragma unroll
                for (int qi = 0; qi < 8; ++qi)
                    s[j][qi] = ffma2(kk, dup2(qv[qi]), s[j][qi]);
            }
        }

        // softmax per query (over 256 keys: 4 pairs local + warp reduce)
        #pragma unroll
        for (int qi = 0; qi < 8; ++qi) {
            float mx = fmaxf(s[0][qi].x, s[0][qi].y);
            #pragma unroll
            for (int j = 1; j < 4; ++j) mx = fmaxf(mx, fmaxf(s[j][qi].x, s[j][qi].y));
            #pragma unroll
            for (int o = 16; o; o >>= 1) mx = fmaxf(mx, __shfl_xor_sync(0xffffffffu, mx, o));
            float sum = 0.f;
            #pragma unroll
            for (int j = 0; j < 4; ++j) {
                s[j][qi].x = __expf(s[j][qi].x - mx); sum += s[j][qi].x;
                s[j][qi].y = __expf(s[j][qi].y - mx); sum += s[j][qi].y;
            }
            #pragma unroll
            for (int o = 16; o; o >>= 1) sum += __shfl_xor_sync(0xffffffffu, sum, o);
            float inv = __frcp_rn(sum);
            #pragma unroll
            for (int j = 0; j < 4; ++j) { s[j][qi].x *= inv; s[j][qi].y *= inv; }
        }

        // two halves of 4 queries: PV + proj
        #pragma unroll
        for (int h = 0; h < 2; ++h) {
            int qh = h*4;
            #pragma unroll
            for (int j = 0; j < 4; ++j) {
                float4 fa = make_float4(s[j][qh+0].x, s[j][qh+1].x, s[j][qh+2].x, s[j][qh+3].x);
                float4 fb = make_float4(s[j][qh+0].y, s[j][qh+1].y, s[j][qh+2].y, s[j][qh+3].y);
                *(float4*)&PsT[(j*64 + 2*lane)*4]     = fa;
                *(float4*)&PsT[(j*64 + 2*lane + 1)*4] = fb;
            }
            __syncwarp();

            // PV: lane = (dq dims 4dq..+3, mh m-parity)
            float2 oa[4][2];
            #pragma unroll
            for (int qi = 0; qi < 4; ++qi) { oa[qi][0] = make_float2(0.f,0.f); oa[qi][1] = make_float2(0.f,0.f); }
            #pragma unroll 4
            for (int mm = 0; mm < 128; ++mm) {
                int m = 2*mm + mh;
                float4 p4 = *(const float4*)&PsT[m*4];
                float4 v4 = *(const float4*)&Vs[m*64 + dq*4];
                float2 vlo = make_float2(v4.x, v4.y), vhi = make_float2(v4.z, v4.w);
                float pv[4] = {p4.x, p4.y, p4.z, p4.w};
                #pragma unroll
                for (int qi = 0; qi < 4; ++qi) {
                    float2 pd = dup2(pv[qi]);
                    oa[qi][0] = ffma2(pd, vlo, oa[qi][0]);
                    oa[qi][1] = ffma2(pd, vhi, oa[qi][1]);
                }
            }
            __syncwarp();
            // reduce across mh
            #pragma unroll
            for (int qi = 0; qi < 4; ++qi)
                #pragma unroll
                for (int p = 0; p < 2; ++p) {
                    unsigned long long u = *(unsigned long long*)&oa[qi][p];
                    u = __shfl_xor_sync(0xffffffffu, u, 16);
                    float2 t = *(float2*)&u;
                    oa[qi][p].x += t.x; oa[qi][p].y += t.y;
                }
            // stage O transposed (split stores by mh)
            {
                int qi0 = mh*2;
                #pragma unroll
                for (int t = 0; t < 2; ++t) {
                    int qi = qi0 + t;
                    OsT[(4*dq+0)*4 + qi] = oa[qi][0].x;
                    OsT[(4*dq+1)*4 + qi] = oa[qi][0].y;
                    OsT[(4*dq+2)*4 + qi] = oa[qi][1].x;
                    OsT[(4*dq+3)*4 + qi] = oa[qi][1].y;
                }
            }
            __syncwarp();

            // proj: lane = (dq out-dims, mh j-parity)
            float2 pa[4][2];
            #pragma unroll
            for (int qi = 0; qi < 4; ++qi) { pa[qi][0] = make_float2(0.f,0.f); pa[qi][1] = make_float2(0.f,0.f); }
            #pragma unroll 4
            for (int jj = 0; jj < 32; ++jj) {
                int j = 2*jj + mh;
                float4 o4 = *(const float4*)&OsT[j*4];
                float4 w4 = *(const float4*)&PW[j*64 + dq*4];
                float2 wlo = make_float2(w4.x, w4.y), whi = make_float2(w4.z, w4.w);
                float ov[4] = {o4.x, o4.y, o4.z, o4.w};
                #pragma unroll
                for (int qi = 0; qi < 4; ++qi) {
                    float2 od = dup2(ov[qi]);
                    pa[qi][0] = ffma2(od, wlo, pa[qi][0]);
                    pa[qi][1] = ffma2(od, whi, pa[qi][1]);
                }
            }
            #pragma unroll
            for (int qi = 0; qi < 4; ++qi)
                #pragma unroll
                for (int p = 0; p < 2; ++p) {
                    unsigned long long u = *(unsigned long long*)&pa[qi][p];
                    u = __shfl_xor_sync(0xffffffffu, u, 16);
                    float2 t = *(float2*)&u;
                    pa[qi][p].x += t.x; pa[qi][p].y += t.y;
                }
            // epilogue: each lane stores 2 queries (split by mh)
            #pragma unroll
            for (int t = 0; t < 2; ++t) {
                int qi = mh*2 + t;
                size_t row = (size_t)b*NN + q0 + qh + qi;
                float4 xv = *(const float4*)&x[row*64 + dq*4];
                float4 ov = make_float4(xv.x + pa[qi][0].x + pb4.x,
                                        xv.y + pa[qi][0].y + pb4.y,
                                        xv.z + pa[qi][1].x + pb4.z,
                                        xv.w + pa[qi][1].y + pb4.w);
                *(float4*)&g_x2[row*64 + dq*4] = ov;
            }
            __syncwarp();
        }
        __syncwarp();
    }
}

// =====================================================================
// K4: LN2 + fc1. grid 2048 (1024 rowblocks x 2 colblocks), block 256.
// tile 128x128, micro 8x8. dyn smem 66560 B.
// =====================================================================
__global__ __launch_bounds__(256) void k4_ln_fc1(
    const float* __restrict__ g2, const float* __restrict__ b2,
    const float* __restrict__ w1, const float* __restrict__ fb1)
{
    extern __shared__ float sm4[];
    float* Wsh = sm4;            // [64][128]
    float* hnT = sm4 + 8192;     // [64][132]
    int tid = threadIdx.x, warp = tid >> 5, lane = tid & 31;
    int cb = blockIdx.x & 1;
    int rowbase = (blockIdx.x >> 1) * 128;
    for (int idx = tid; idx < 8192; idx += 256) {
        int k = idx >> 7, c = idx & 127;
        Wsh[idx] = w1[k*256 + cb*128 + c];
    }
    float2 gg = ((const float2*)g2)[lane];
    float2 bb = ((const float2*)b2)[lane];
    #pragma unroll
    for (int i = 0; i < 16; ++i) {
        int lr = warp*16 + i;
        int row = rowbase + lr;
        float2 v = ((const float2*)g_x2)[row*32 + lane];
        float s = v.x + v.y, ss = v.x*v.x + v.y*v.y;
        #pragma unroll
        for (int o = 16; o; o >>= 1) {
            s  += __shfl_xor_sync(0xffffffffu, s,  o);
            ss += __shfl_xor_sync(0xffffffffu, ss, o);
        }
        float mean = s*(1.f/64.f);
        float rstd = rsqrtf(ss*(1.f/64.f) - mean*mean + EPSV);
        hnT[(2*lane)*132 + lr]   = (v.x-mean)*rstd*gg.x + bb.x;
        hnT[(2*lane+1)*132 + lr] = (v.y-mean)*rstd*gg.y + bb.y;
    }
    __syncthreads();

    int tx = tid & 15, ty = tid >> 4;
    float2 acc[8][4];
    #pragma unroll
    for (int r = 0; r < 8; ++r)
        #pragma unroll
        for (int p = 0; p < 4; ++p) acc[r][p] = make_float2(0.f,0.f);
    #pragma unroll 4
    for (int k = 0; k < 64; ++k) {
        float4 a0 = *(const float4*)&hnT[k*132 + ty*8];
        float4 a1 = *(const float4*)&hnT[k*132 + ty*8 + 4];
        float4 wb0 = *(const float4*)&Wsh[k*128 + tx*8];
        float4 wb1 = *(const float4*)&Wsh[k*128 + tx*8 + 4];
        float2 w0 = make_float2(wb0.x, wb0.y), w1p = make_float2(wb0.z, wb0.w);
        float2 w2 = make_float2(wb1.x, wb1.y), w3  = make_float2(wb1.z, wb1.w);
        float a[8] = {a0.x,a0.y,a0.z,a0.w,a1.x,a1.y,a1.z,a1.w};
        #pragma unroll
        for (int r = 0; r < 8; ++r) {
            float2 ad = dup2(a[r]);
            acc[r][0] = ffma2(ad, w0,  acc[r][0]);
            acc[r][1] = ffma2(ad, w1p, acc[r][1]);
            acc[r][2] = ffma2(ad, w2,  acc[r][2]);
            acc[r][3] = ffma2(ad, w3,  acc[r][3]);
        }
    }
    float4 fba = *(const float4*)&fb1[cb*128 + tx*8];
    float4 fbb = *(const float4*)&fb1[cb*128 + tx*8 + 4];
    #pragma unroll
    for (int r = 0; r < 8; ++r) {
        size_t row = rowbase + ty*8 + r;
        float4 o0 = make_float4(acc[r][0].x + fba.x, acc[r][0].y + fba.y,
                                acc[r][1].x + fba.z, acc[r][1].y + fba.w);
        float4 o1 = make_float4(acc[r][2].x + fbb.x, acc[r][2].y + fbb.y,
                                acc[r][3].x + fbb.z, acc[r][3].y + fbb.w);
        *(float4*)&g_f[row*HID + cb*128 + tx*8]     = o0;
        *(float4*)&g_f[row*HID + cb*128 + tx*8 + 4] = o1;
    }
}

// =====================================================================
// K5: depthwise 3x3 SAME + exact GELU. grid 32768, block 256.
// =====================================================================
__global__ __launch_bounds__(256) void k5_dw_gelu(const float* __restrict__ dww)
{
    int px = blockIdx.x * 4 + (threadIdx.x >> 6);
    int c4 = (threadIdx.x & 63) * 4;
    int w = px & 127, h = (px >> 7) & 127, b = px >> 14;
    float4 acc = make_float4(0.f,0.f,0.f,0.f);
    #pragma unroll
    for (int dh = -1; dh <= 1; ++dh) {
        int hh = h + dh;
        if (hh < 0 || hh > 127) continue;
        #pragma unroll
        for (int dw = -1; dw <= 1; ++dw) {
            int wv = w + dw;
            if (wv < 0 || wv > 127) continue;
            float4 f  = *(const float4*)&g_f[((size_t)b*NN + hh*WW + wv)*HID + c4];
            float4 wt = *(const float4*)&dww[((dh+1)*3 + (dw+1))*HID + c4];
            acc.x += f.x*wt.x; acc.y += f.y*wt.y;
            acc.z += f.z*wt.z; acc.w += f.w*wt.w;
        }
    }
    float4 o;
    o.x = acc.x * normcdff(acc.x);
    o.y = acc.y * normcdff(acc.y);
    o.z = acc.z * normcdff(acc.z);
    o.w = acc.w * normcdff(acc.w);
    *(float4*)&g_g[(size_t)px*HID + c4] = o;
}

// =====================================================================
// K6: fc2 (256->64) + residual. grid 1024, block 256.
// tile 128x64, micro 8x4, k-vectorized A loads. dyn smem 100352 B.
// =====================================================================
__global__ __launch_bounds__(256) void k6_fc2(
    const float* __restrict__ w2, const float* __restrict__ b2,
    float* __restrict__ out)
{
    extern __shared__ float sm6[];
    float* As = sm6;               // [128][68]
    float* Ws = sm6 + 128*68;      // [256][64]
    int tid = threadIdx.x;
    int rowbase = blockIdx.x * 128;
    int tx = tid & 15, ty = tid >> 4;
    for (int i = tid; i < 16384; i += 256) Ws[i] = w2[i];
    float2 acc[8][2];
    #pragma unroll
    for (int r = 0; r < 8; ++r) { acc[r][0] = make_float2(0.f,0.f); acc[r][1] = make_float2(0.f,0.f); }

    for (int kc = 0; kc < 4; ++kc) {
        if (kc) __syncthreads();
        for (int idx = tid; idx < 2048; idx += 256) {
            int row = idx >> 4, q = idx & 15;
            *(float4*)&As[row*68 + q*4] =
                *(const float4*)&g_g[(size_t)(rowbase+row)*HID + kc*64 + q*4];
        }
        __syncthreads();
        #pragma unroll 2
        for (int k4i = 0; k4i < 16; ++k4i) {
            float4 a4[8];
            #pragma unroll
            for (int r = 0; r < 8; ++r)
                a4[r] = *(const float4*)&As[(ty*8 + r)*68 + k4i*4];
            #pragma unroll
            for (int kk = 0; kk < 4; ++kk) {
                float4 w4 = *(const float4*)&Ws[(kc*64 + k4i*4 + kk)*64 + tx*4];
                float2 wlo = make_float2(w4.x, w4.y), whi = make_float2(w4.z, w4.w);
                #pragma unroll
                for (int r = 0; r < 8; ++r) {
                    float av = ((const float*)&a4[r])[kk];
                    float2 ad = dup2(av);
                    acc[r][0] = ffma2(ad, wlo, acc[r][0]);
                    acc[r][1] = ffma2(ad, whi, acc[r][1]);
                }
            }
        }
    }
    float4 bb = *(const float4*)&b2[tx*4];
    #pragma unroll
    for (int r = 0; r < 8; ++r) {
        size_t row = rowbase + ty*8 + r;
        float4 res = *(const float4*)&g_x2[row*64 + tx*4];
        float4 o = make_float4(res.x + acc[r][0].x + bb.x,
                               res.y + acc[r][0].y + bb.y,
                               res.z + acc[r][1].x + bb.z,
                               res.w + acc[r][1].y + bb.w);
        *(float4*)&out[row*64 + tx*4] = o;
    }
}

// =====================================================================
extern "C" void kernel_launch(void* const* d_in, const int* in_sizes, int n_in,
                              void* d_out, int out_size)
{
    const float* x     = (const float*)d_in[0];
    const float* ln1_g = (const float*)d_in[3];
    const float* ln1_b = (const float*)d_in[4];
    const float* q_w   = (const float*)d_in[5];
    const float* q_b   = (const float*)d_in[6];
    const float* kv_w  = (const float*)d_in[7];
    const float* kv_b  = (const float*)d_in[8];
    const float* pr_w  = (const float*)d_in[9];
    const float* pr_b  = (const float*)d_in[10];
    const float* sr_w  = (const float*)d_in[11];
    const float* sr_b  = (const float*)d_in[12];
    const float* srn_g = (const float*)d_in[13];
    const float* srn_b = (const float*)d_in[14];
    const float* ln2_g = (const float*)d_in[15];
    const float* ln2_b = (const float*)d_in[16];
    const float* fc1_w = (const float*)d_in[17];
    const float* fc1_b = (const float*)d_in[18];
    const float* dw_w  = (const float*)d_in[19];
    const float* fc2_w = (const float*)d_in[20];
    const float* fc2_b = (const float*)d_in[21];
    float* out = (float*)d_out;

    const int K1_SMEM = (4096 + 64*132) * 4;                    // 50176
    const int K2_SMEM = 8*4096*4;                               // 131072
    const int K3_SMEM = (64*258 + 16384 + 4096 + 8*2048) * 4;   // 213504
    const int K4_SMEM = (8192 + 64*132) * 4;                    // 66560
    const int K6_SMEM = (128*68 + 16384) * 4;                   // 100352

    cudaFuncSetAttribute(k1_ln_q,   cudaFuncAttributeMaxDynamicSharedMemorySize, K1_SMEM);
    cudaFuncSetAttribute(k2_sr_kv,  cudaFuncAttributeMaxDynamicSharedMemorySize, K2_SMEM);
    cudaFuncSetAttribute(k3_attn,   cudaFuncAttributeMaxDynamicSharedMemorySize, K3_SMEM);
    cudaFuncSetAttribute(k4_ln_fc1, cudaFuncAttributeMaxDynamicSharedMemorySize, K4_SMEM);
    cudaFuncSetAttribute(k6_fc2,    cudaFuncAttributeMaxDynamicSharedMemorySize, K6_SMEM);

    k1_ln_q  <<<1024, 256, K1_SMEM>>>(x, ln1_g, ln1_b, q_w, q_b);
    k2_sr_kv <<<256, 256, K2_SMEM>>>(sr_w, sr_b, srn_g, srn_b, kv_w, kv_b);
    k3_attn  <<<512, 256, K3_SMEM>>>(x, pr_w, pr_b);
    k4_ln_fc1<<<2048, 256, K4_SMEM>>>(ln2_g, ln2_b, fc1_w, fc1_b);
    k5_dw_gelu<<<32768, 256>>>(dw_w);
    k6_fc2   <<<1024, 256, K6_SMEM>>>(fc2_w, fc2_b, out);
}

// round 6
// speedup vs baseline: 1.5725x; 1.0249x over previous
#include <cuda_runtime.h>
#include <cuda_bf16.h>
#include <math.h>

#define BB   8
#define HH   128
#define WW   128
#define NN   (HH*WW)          // 16384
#define CC   64
#define NR   256
#define HID  256
#define EPSV 1e-5f
#define QSCALE 0.125f

__device__ float g_h  [BB*NN*CC];
__device__ float g_q  [BB*NN*CC];
__device__ float g_k  [BB*NR*CC];
__device__ float g_v  [BB*NR*CC];
__device__ float g_x2 [BB*NN*CC];
__device__ float g_f  [(size_t)BB*NN*HID];
__device__ float g_g  [(size_t)BB*NN*HID];

__device__ __forceinline__ float2 ffma2(const float2 a, const float2 b, const float2 c) {
    float2 d;
    asm("fma.rn.f32x2 %0, %1, %2, %3;"
        : "=l"(reinterpret_cast<unsigned long long&>(d))
        : "l"(reinterpret_cast<const unsigned long long&>(a)),
          "l"(reinterpret_cast<const unsigned long long&>(b)),
          "l"(reinterpret_cast<const unsigned long long&>(c)));
    return d;
}
__device__ __forceinline__ float2 dup2(float s) { return make_float2(s, s); }

// tf32 round (RNA) kept in f32 container
__device__ __forceinline__ float tf32f(float f) {
    unsigned u;
    asm("cvt.rna.tf32.f32 %0, %1;" : "=r"(u) : "f"(f));
    return __uint_as_float(u);
}

// mma.sync m16n8k8 tf32: D += A(16x8,row) * B(8x8,col)
__device__ __forceinline__ void mma_tf32(float* c, const unsigned* a, float2 b) {
    unsigned b0 = __float_as_uint(b.x), b1 = __float_as_uint(b.y);
    asm volatile("mma.sync.aligned.m16n8k8.row.col.f32.tf32.tf32.f32 "
        "{%0,%1,%2,%3}, {%4,%5,%6,%7}, {%8,%9}, {%0,%1,%2,%3};"
        : "+f"(c[0]), "+f"(c[1]), "+f"(c[2]), "+f"(c[3])
        : "r"(a[0]), "r"(a[1]), "r"(a[2]), "r"(a[3]), "r"(b0), "r"(b1));
}

// =====================================================================
// K1: LN1 + q-proj. grid 1024, block 256. (unchanged)
// =====================================================================
__global__ __launch_bounds__(256) void k1_ln_q(
    const float* __restrict__ x, const float* __restrict__ g1,
    const float* __restrict__ b1, const float* __restrict__ qw,
    const float* __restrict__ qb)
{
    extern __shared__ float sm1[];
    float* qws = sm1;           // [64][64]
    float* hnT = sm1 + 4096;    // [64][132]
    int tid = threadIdx.x, warp = tid >> 5, lane = tid & 31;
    int rowbase = blockIdx.x * 128;
    for (int i = tid; i < 4096; i += 256) qws[i] = qw[i];
    float2 gg = ((const float2*)g1)[lane];
    float2 bbv = ((const float2*)b1)[lane];
    #pragma unroll
    for (int i = 0; i < 16; ++i) {
        int lr = warp*16 + i;
        int row = rowbase + lr;
        float2 v = ((const float2*)x)[row*32 + lane];
        float s = v.x + v.y, ss = v.x*v.x + v.y*v.y;
        #pragma unroll
        for (int o = 16; o; o >>= 1) {
            s  += __shfl_xor_sync(0xffffffffu, s,  o);
            ss += __shfl_xor_sync(0xffffffffu, ss, o);
        }
        float mean = s * (1.f/64.f);
        float rstd = rsqrtf(ss*(1.f/64.f) - mean*mean + EPSV);
        float2 hv;
        hv.x = (v.x - mean)*rstd*gg.x + bbv.x;
        hv.y = (v.y - mean)*rstd*gg.y + bbv.y;
        ((float2*)g_h)[row*32 + lane] = hv;
        hnT[(2*lane)*132 + lr]   = hv.x;
        hnT[(2*lane+1)*132 + lr] = hv.y;
    }
    __syncthreads();

    int tx = tid & 15, ty = tid >> 4;
    float2 acc[8][2];
    #pragma unroll
    for (int r = 0; r < 8; ++r) { acc[r][0] = make_float2(0.f,0.f); acc[r][1] = make_float2(0.f,0.f); }
    #pragma unroll 4
    for (int k = 0; k < 64; ++k) {
        float4 a0 = *(const float4*)&hnT[k*132 + ty*8];
        float4 a1 = *(const float4*)&hnT[k*132 + ty*8 + 4];
        float4 w4 = *(const float4*)&qws[k*64 + tx*4];
        float2 w0 = make_float2(w4.x, w4.y), w1p = make_float2(w4.z, w4.w);
        float a[8] = {a0.x,a0.y,a0.z,a0.w,a1.x,a1.y,a1.z,a1.w};
        #pragma unroll
        for (int r = 0; r < 8; ++r) {
            float2 ad = dup2(a[r]);
            acc[r][0] = ffma2(ad, w0,  acc[r][0]);
            acc[r][1] = ffma2(ad, w1p, acc[r][1]);
        }
    }
    float4 qb4 = *(const float4*)&qb[tx*4];
    #pragma unroll
    for (int r = 0; r < 8; ++r) {
        int row = rowbase + ty*8 + r;
        float4 o = make_float4((acc[r][0].x + qb4.x)*QSCALE,
                               (acc[r][0].y + qb4.y)*QSCALE,
                               (acc[r][1].x + qb4.z)*QSCALE,
                               (acc[r][1].y + qb4.w)*QSCALE);
        *(float4*)&g_q[(size_t)row*64 + tx*4] = o;
    }
}

// =====================================================================
// K2: sr conv (8x8/s8) + LN + kv proj. grid 256, block 256. (unchanged)
// =====================================================================
__global__ __launch_bounds__(256) void k2_sr_kv(
    const float* __restrict__ srw, const float* __restrict__ srb,
    const float* __restrict__ sng, const float* __restrict__ snb,
    const float* __restrict__ kvw, const float* __restrict__ kvb)
{
    extern __shared__ float sm[];   // 8 patches x 4096
    int tid = threadIdx.x;
    int basepos = blockIdx.x * 8;
    int b   = basepos >> 8;
    int rem = basepos & 255;
    int oh  = rem >> 4, ow0 = rem & 15;

    for (int r = 0; r < 8; ++r) {
        size_t base4 = (((size_t)b*NN + (size_t)(oh*8)*WW + (size_t)(ow0+r)*8) * CC) >> 2;
        const float4* src = (const float4*)g_h;
        float4* dst = (float4*)(sm + r*4096);
        for (int k4 = tid; k4 < 1024; k4 += 256) {
            int i = k4 >> 7, rk = k4 & 127;
            dst[k4] = src[base4 + (size_t)i*2048 + rk];
        }
    }
    __syncthreads();

    int cp = tid & 31, r = tid >> 5;
    float2 acc = make_float2(0.f, 0.f);
    const float2* srw2 = (const float2*)srw;
    const float* ap = sm + r*4096;
    #pragma unroll 8
    for (int t = 0; t < 4096; ++t)
        acc = ffma2(dup2(ap[t]), srw2[t*32 + cp], acc);
    __syncthreads();
    float* xr = sm;
    float2 sbp = ((const float2*)srb)[cp];
    acc.x += sbp.x; acc.y += sbp.y;
    ((float2*)xr)[r*32 + cp] = acc;
    __syncthreads();

    int warp = tid >> 5, lane = tid & 31;
    {
        float2 sg  = ((const float2*)sng)[lane];
        float2 sbb = ((const float2*)snb)[lane];
        float2 v = ((float2*)xr)[warp*32 + lane];
        float s = v.x + v.y, ss = v.x*v.x + v.y*v.y;
        #pragma unroll
        for (int o = 16; o; o >>= 1) {
            s  += __shfl_xor_sync(0xffffffffu, s,  o);
            ss += __shfl_xor_sync(0xffffffffu, ss, o);
        }
        float mean = s*(1.f/64.f);
        float rstd = rsqrtf(ss*(1.f/64.f) - mean*mean + EPSV);
        float2 nv;
        nv.x = (v.x-mean)*rstd*sg.x + sbb.x;
        nv.y = (v.y-mean)*rstd*sg.y + sbb.y;
        ((float2*)xr)[warp*32 + lane] = nv;
    }
    __syncthreads();

    int ch = tid & 127, rh = tid >> 7;
    float ak[4];
    float kb = kvb[ch];
    #pragma unroll
    for (int rr = 0; rr < 4; ++rr) ak[rr] = kb;
    #pragma unroll 4
    for (int j = 0; j < 64; ++j) {
        float w = kvw[j*128 + ch];
        #pragma unroll
        for (int rr = 0; rr < 4; ++rr) ak[rr] += xr[(rh*4+rr)*64 + j] * w;
    }
    #pragma unroll
    for (int rr = 0; rr < 4; ++rr) {
        int pos = basepos + rh*4 + rr;
        if (ch < 64) g_k[pos*64 + ch]      = ak[rr];
        else         g_v[pos*64 + ch - 64] = ak[rr];
    }
}

// =====================================================================
// K3: fused attention + proj + residual. grid 512, block 256. (unchanged)
// =====================================================================
__global__ __launch_bounds__(256) void k3_attn(
    const float* __restrict__ x, const float* __restrict__ pw,
    const float* __restrict__ pb)
{
    extern __shared__ float sm3[];
    float* KsT = sm3;               // [64][258]
    float* Vs  = KsT + 64*258;      // [256][64]
    float* PW  = Vs + 16384;        // [64][64]
    float* WSb = PW + 4096;         // per-warp: 2048 floats each
    int tid = threadIdx.x;
    int b    = blockIdx.x >> 6;
    int tile = blockIdx.x & 63;

    for (int idx = tid; idx < NR*CC; idx += 256) {
        int m = idx >> 6, d = idx & 63;
        KsT[d*258 + m] = g_k[b*NR*CC + idx];
        Vs[idx]        = g_v[b*NR*CC + idx];
    }
    for (int i = tid; i < 4096; i += 256) PW[i] = pw[i];
    __syncthreads();

    int warp = tid >> 5, lane = tid & 31;
    float* QsT = WSb + warp*2048;   // [64][12]
    float* PsT = QsT + 768;         // [256][4]
    float* OsT = PsT + 1024;        // [64][4]
    int dq = lane & 15, mh = lane >> 4;
    const float2* gq2 = (const float2*)g_q;
    float4 pb4 = *(const float4*)&pb[dq*4];

    for (int pass = 0; pass < 4; ++pass) {
        int q0 = tile*256 + warp*32 + pass*8;
        #pragma unroll
        for (int qi = 0; qi < 8; ++qi) {
            float2 v = gq2[((size_t)b*NN + q0 + qi)*32 + lane];
            QsT[(2*lane)*12 + qi]   = v.x;
            QsT[(2*lane+1)*12 + qi] = v.y;
        }
        __syncwarp();

        float2 s[4][8];
        #pragma unroll
        for (int j = 0; j < 4; ++j)
            #pragma unroll
            for (int qi = 0; qi < 8; ++qi) s[j][qi] = make_float2(0.f, 0.f);
        #pragma unroll 4
        for (int d = 0; d < 64; ++d) {
            float4 qA = *(const float4*)&QsT[d*12];
            float4 qB = *(const float4*)&QsT[d*12 + 4];
            float qv[8] = {qA.x,qA.y,qA.z,qA.w,qB.x,qB.y,qB.z,qB.w};
            #pragma unroll
            for (int j = 0; j < 4; ++j) {
                float2 kk = *(const float2*)&KsT[d*258 + j*64 + 2*lane];
                #pragma unroll
                for (int qi = 0; qi < 8; ++qi)
                    s[j][qi] = ffma2(kk, dup2(qv[qi]), s[j][qi]);
            }
        }

        #pragma unroll
        for (int qi = 0; qi < 8; ++qi) {
            float mx = fmaxf(s[0][qi].x, s[0][qi].y);
            #pragma unroll
            for (int j = 1; j < 4; ++j) mx = fmaxf(mx, fmaxf(s[j][qi].x, s[j][qi].y));
            #pragma unroll
            for (int o = 16; o; o >>= 1) mx = fmaxf(mx, __shfl_xor_sync(0xffffffffu, mx, o));
            float sum = 0.f;
            #pragma unroll
            for (int j = 0; j < 4; ++j) {
                s[j][qi].x = __expf(s[j][qi].x - mx); sum += s[j][qi].x;
                s[j][qi].y = __expf(s[j][qi].y - mx); sum += s[j][qi].y;
            }
            #pragma unroll
            for (int o = 16; o; o >>= 1) sum += __shfl_xor_sync(0xffffffffu, sum, o);
            float inv = __frcp_rn(sum);
            #pragma unroll
            for (int j = 0; j < 4; ++j) { s[j][qi].x *= inv; s[j][qi].y *= inv; }
        }

        #pragma unroll
        for (int h = 0; h < 2; ++h) {
            int qh = h*4;
            #pragma unroll
            for (int j = 0; j < 4; ++j) {
                float4 fa = make_float4(s[j][qh+0].x, s[j][qh+1].x, s[j][qh+2].x, s[j][qh+3].x);
                float4 fb = make_float4(s[j][qh+0].y, s[j][qh+1].y, s[j][qh+2].y, s[j][qh+3].y);
                *(float4*)&PsT[(j*64 + 2*lane)*4]     = fa;
                *(float4*)&PsT[(j*64 + 2*lane + 1)*4] = fb;
            }
            __syncwarp();

            float2 oa[4][2];
            #pragma unroll
            for (int qi = 0; qi < 4; ++qi) { oa[qi][0] = make_float2(0.f,0.f); oa[qi][1] = make_float2(0.f,0.f); }
            #pragma unroll 4
            for (int mm = 0; mm < 128; ++mm) {
                int m = 2*mm + mh;
                float4 p4 = *(const float4*)&PsT[m*4];
                float4 v4 = *(const float4*)&Vs[m*64 + dq*4];
                float2 vlo = make_float2(v4.x, v4.y), vhi = make_float2(v4.z, v4.w);
                float pv[4] = {p4.x, p4.y, p4.z, p4.w};
                #pragma unroll
                for (int qi = 0; qi < 4; ++qi) {
                    float2 pd = dup2(pv[qi]);
                    oa[qi][0] = ffma2(pd, vlo, oa[qi][0]);
                    oa[qi][1] = ffma2(pd, vhi, oa[qi][1]);
                }
            }
            __syncwarp();
            #pragma unroll
            for (int qi = 0; qi < 4; ++qi)
                #pragma unroll
                for (int p = 0; p < 2; ++p) {
                    unsigned long long u = *(unsigned long long*)&oa[qi][p];
                    u = __shfl_xor_sync(0xffffffffu, u, 16);
                    float2 t = *(float2*)&u;
                    oa[qi][p].x += t.x; oa[qi][p].y += t.y;
                }
            {
                int qi0 = mh*2;
                #pragma unroll
                for (int t = 0; t < 2; ++t) {
                    int qi = qi0 + t;
                    OsT[(4*dq+0)*4 + qi] = oa[qi][0].x;
                    OsT[(4*dq+1)*4 + qi] = oa[qi][0].y;
                    OsT[(4*dq+2)*4 + qi] = oa[qi][1].x;
                    OsT[(4*dq+3)*4 + qi] = oa[qi][1].y;
                }
            }
            __syncwarp();

            float2 pa[4][2];
            #pragma unroll
            for (int qi = 0; qi < 4; ++qi) { pa[qi][0] = make_float2(0.f,0.f); pa[qi][1] = make_float2(0.f,0.f); }
            #pragma unroll 4
            for (int jj = 0; jj < 32; ++jj) {
                int j = 2*jj + mh;
                float4 o4 = *(const float4*)&OsT[j*4];
                float4 w4 = *(const float4*)&PW[j*64 + dq*4];
                float2 wlo = make_float2(w4.x, w4.y), whi = make_float2(w4.z, w4.w);
                float ov[4] = {o4.x, o4.y, o4.z, o4.w};
                #pragma unroll
                for (int qi = 0; qi < 4; ++qi) {
                    float2 od = dup2(ov[qi]);
                    pa[qi][0] = ffma2(od, wlo, pa[qi][0]);
                    pa[qi][1] = ffma2(od, whi, pa[qi][1]);
                }
            }
            #pragma unroll
            for (int qi = 0; qi < 4; ++qi)
                #pragma unroll
                for (int p = 0; p < 2; ++p) {
                    unsigned long long u = *(unsigned long long*)&pa[qi][p];
                    u = __shfl_xor_sync(0xffffffffu, u, 16);
                    float2 t = *(float2*)&u;
                    pa[qi][p].x += t.x; pa[qi][p].y += t.y;
                }
            #pragma unroll
            for (int t = 0; t < 2; ++t) {
                int qi = mh*2 + t;
                size_t row = (size_t)b*NN + q0 + qh + qi;
                float4 xv = *(const float4*)&x[row*64 + dq*4];
                float4 ov = make_float4(xv.x + pa[qi][0].x + pb4.x,
                                        xv.y + pa[qi][0].y + pb4.y,
                                        xv.z + pa[qi][1].x + pb4.z,
                                        xv.w + pa[qi][1].y + pb4.w);
                *(float4*)&g_x2[row*64 + dq*4] = ov;
            }
            __syncwarp();
        }
        __syncwarp();
    }
}

// =====================================================================
// K4: LN2 + fc1 via mma.sync tf32. grid 2048 (1024 rb x 2 cb), block 256.
// warp tile 32x64 (2 m16 x 8 n8), K=64 (8 kchunks). dyn smem 67584 B.
// =====================================================================
__global__ __launch_bounds__(256) void k4_ln_fc1(
    const float* __restrict__ g2, const float* __restrict__ b2,
    const float* __restrict__ w1, const float* __restrict__ fb1)
{
    extern __shared__ float sm4[];
    float* WF = sm4;            // B fragments: [16 nt][8 kc][32 lane][2]
    float* As = sm4 + 8192;     // [128][68] row-major tf32 values
    int tid = threadIdx.x, warp = tid >> 5, lane = tid & 31;
    int gid = lane >> 2, tig = lane & 3;
    int cb = blockIdx.x & 1;
    int rowbase = (blockIdx.x >> 1) * 128;

    for (int idx = tid; idx < 8192; idx += 256) {
        int nt = idx >> 9, kc = (idx >> 6) & 7, ln = (idx >> 1) & 31, j = idx & 1;
        int k = kc*8 + (ln & 3) + j*4;
        int col = cb*128 + nt*8 + (ln >> 2);
        WF[idx] = tf32f(w1[k*256 + col]);
    }

    float2 gg = ((const float2*)g2)[lane];
    float2 bb = ((const float2*)b2)[lane];
    #pragma unroll
    for (int i = 0; i < 16; ++i) {
        int lr = warp*16 + i;
        int row = rowbase + lr;
        float2 v = ((const float2*)g_x2)[row*32 + lane];
        float s = v.x + v.y, ss = v.x*v.x + v.y*v.y;
        #pragma unroll
        for (int o = 16; o; o >>= 1) {
            s  += __shfl_xor_sync(0xffffffffu, s,  o);
            ss += __shfl_xor_sync(0xffffffffu, ss, o);
        }
        float mean = s*(1.f/64.f);
        float rstd = rsqrtf(ss*(1.f/64.f) - mean*mean + EPSV);
        float2 st;
        st.x = tf32f((v.x-mean)*rstd*gg.x + bb.x);
        st.y = tf32f((v.y-mean)*rstd*gg.y + bb.y);
        *(float2*)&As[lr*68 + 2*lane] = st;
    }
    __syncthreads();

    int wy = warp >> 1, wx = warp & 1;
    float acc[2][8][4];
    #pragma unroll
    for (int mt = 0; mt < 2; ++mt)
        #pragma unroll
        for (int nt = 0; nt < 8; ++nt)
            #pragma unroll
            for (int r = 0; r < 4; ++r) acc[mt][nt][r] = 0.f;

    #pragma unroll
    for (int kc = 0; kc < 8; ++kc) {
        unsigned a[2][4];
        #pragma unroll
        for (int mt = 0; mt < 2; ++mt) {
            const float* ap = As + (wy*32 + mt*16 + gid)*68 + kc*8;
            a[mt][0] = __float_as_uint(ap[tig]);
            a[mt][1] = __float_as_uint(ap[8*68 + tig]);
            a[mt][2] = __float_as_uint(ap[tig + 4]);
            a[mt][3] = __float_as_uint(ap[8*68 + tig + 4]);
        }
        #pragma unroll
        for (int nt = 0; nt < 8; ++nt) {
            float2 bv = *(const float2*)&WF[((wx*8 + nt)*8 + kc)*64 + lane*2];
            mma_tf32(acc[0][nt], a[0], bv);
            mma_tf32(acc[1][nt], a[1], bv);
        }
    }

    #pragma unroll
    for (int mt = 0; mt < 2; ++mt)
        #pragma unroll
        for (int nt = 0; nt < 8; ++nt) {
            int col = cb*128 + (wx*8 + nt)*8 + tig*2;
            float2 fbv = *(const float2*)&fb1[col];
            int row = rowbase + wy*32 + mt*16 + gid;
            float2 o0 = make_float2(acc[mt][nt][0] + fbv.x, acc[mt][nt][1] + fbv.y);
            float2 o1 = make_float2(acc[mt][nt][2] + fbv.x, acc[mt][nt][3] + fbv.y);
            *(float2*)&g_f[(size_t)row*HID + col]      = o0;
            *(float2*)&g_f[(size_t)(row+8)*HID + col]  = o1;
        }
}

// =====================================================================
// K5: depthwise 3x3 SAME + GELU, smem-tiled rolling conv.
// block = (b, 4 h-rows, 32 channels). grid 2048, block 256. smem 98304 B.
// =====================================================================
__global__ __launch_bounds__(256) void k5_dw_gelu(const float* __restrict__ dww)
{
    extern __shared__ float s5[];   // [6][128][32]
    int tid = threadIdx.x;
    int blk = blockIdx.x;
    int ct = blk & 7, ht = (blk >> 3) & 31, b = blk >> 8;
    int c0 = ct * 32, h0 = ht * 4;
    #pragma unroll
    for (int r = 0; r < 6; ++r) {
        int h = h0 - 1 + r;
        float4* dst = (float4*)(s5 + r*4096);
        if ((unsigned)h < 128u) {
            const float4* src = (const float4*)(g_f + ((size_t)b*NN + (size_t)h*WW)*HID + c0);
            for (int i = tid; i < 1024; i += 256) {
                int w = i >> 3, cq = i & 7;
                dst[i] = src[w*64 + cq];
            }
        } else {
            float4 z = make_float4(0.f,0.f,0.f,0.f);
            for (int i = tid; i < 1024; i += 256) dst[i] = z;
        }
    }
    __syncthreads();

    int cp = tid & 15, wi = tid >> 4;
    float2 wt[9];
    #pragma unroll
    for (int t = 0; t < 9; ++t)
        wt[t] = *(const float2*)&dww[t*HID + c0 + 2*cp];
    const int coff = 2*cp;

    #pragma unroll
    for (int ro = 0; ro < 4; ++ro) {
        const float* r0p = s5 + ro*4096 + coff;
        const float* r1p = r0p + 4096;
        const float* r2p = r1p + 4096;
        int w = wi * 8;
        float2 L0, L1, L2, C0, C1, C2;
        if (w == 0) {
            L0 = L1 = L2 = make_float2(0.f, 0.f);
        } else {
            L0 = *(const float2*)&r0p[(w-1)*32];
            L1 = *(const float2*)&r1p[(w-1)*32];
            L2 = *(const float2*)&r2p[(w-1)*32];
        }
        C0 = *(const float2*)&r0p[w*32];
        C1 = *(const float2*)&r1p[w*32];
        C2 = *(const float2*)&r2p[w*32];
        #pragma unroll
        for (int k = 0; k < 8; ++k) {
            float2 N0, N1, N2;
            if (w + 1 < 128) {
                N0 = *(const float2*)&r0p[(w+1)*32];
                N1 = *(const float2*)&r1p[(w+1)*32];
                N2 = *(const float2*)&r2p[(w+1)*32];
            } else {
                N0 = N1 = N2 = make_float2(0.f, 0.f);
            }
            float2 acc = make_float2(0.f, 0.f);
            acc = ffma2(L0, wt[0], acc); acc = ffma2(C0, wt[1], acc); acc = ffma2(N0, wt[2], acc);
            acc = ffma2(L1, wt[3], acc); acc = ffma2(C1, wt[4], acc); acc = ffma2(N1, wt[5], acc);
            acc = ffma2(L2, wt[6], acc); acc = ffma2(C2, wt[7], acc); acc = ffma2(N2, wt[8], acc);
            float2 o;
            o.x = acc.x * normcdff(acc.x);
            o.y = acc.y * normcdff(acc.y);
            *(float2*)&g_g[((size_t)b*NN + (size_t)(h0+ro)*WW + w)*HID + c0 + coff] = o;
            L0 = C0; L1 = C1; L2 = C2;
            C0 = N0; C1 = N1; C2 = N2;
            ++w;
        }
    }
}

// =====================================================================
// K6: fc2 (256->64) + residual via mma.sync tf32. grid 1024, block 256.
// warp tile 16x64 (1 m16 x 8 n8), K staged in 4 blocks of 64. smem 100352 B.
// =====================================================================
__global__ __launch_bounds__(256) void k6_fc2(
    const float* __restrict__ w2, const float* __restrict__ b2,
    float* __restrict__ out)
{
    extern __shared__ float sm6[];
    float* WF = sm6;             // [8 nt][32 kc][32 lane][2] = 16384
    float* As = sm6 + 16384;     // [128][68]
    int tid = threadIdx.x, warp = tid >> 5, lane = tid & 31;
    int gid = lane >> 2, tig = lane & 3;
    int rowbase = blockIdx.x * 128;

    for (int idx = tid; idx < 16384; idx += 256) {
        int nt = idx >> 11, kc = (idx >> 6) & 31, ln = (idx >> 1) & 31, j = idx & 1;
        int k = kc*8 + (ln & 3) + j*4;
        int col = nt*8 + (ln >> 2);
        WF[idx] = tf32f(w2[k*64 + col]);
    }

    float acc[8][4];
    #pragma unroll
    for (int nt = 0; nt < 8; ++nt)
        #pragma unroll
        for (int r = 0; r < 4; ++r) acc[nt][r] = 0.f;

    for (int kblk = 0; kblk < 4; ++kblk) {
        __syncthreads();
        for (int i = tid; i < 2048; i += 256) {
            int row = i >> 4, q = i & 15;
            float4 v = *(const float4*)&g_g[(size_t)(rowbase+row)*HID + kblk*64 + q*4];
            v.x = tf32f(v.x); v.y = tf32f(v.y); v.z = tf32f(v.z); v.w = tf32f(v.w);
            *(float4*)&As[row*68 + q*4] = v;
        }
        __syncthreads();
        #pragma unroll
        for (int kc = 0; kc < 8; ++kc) {
            unsigned a[4];
            const float* ap = As + (warp*16 + gid)*68 + kc*8;
            a[0] = __float_as_uint(ap[tig]);
            a[1] = __float_as_uint(ap[8*68 + tig]);
            a[2] = __float_as_uint(ap[tig + 4]);
            a[3] = __float_as_uint(ap[8*68 + tig + 4]);
            #pragma unroll
            for (int nt = 0; nt < 8; ++nt) {
                float2 bv = *(const float2*)&WF[(nt*32 + kblk*8 + kc)*64 + lane*2];
                mma_tf32(acc[nt], a, bv);
            }
        }
    }

    #pragma unroll
    for (int nt = 0; nt < 8; ++nt) {
        int col = nt*8 + tig*2;
        float2 bbv = *(const float2*)&b2[col];
        int row = rowbase + warp*16 + gid;
        float2 r0 = *(const float2*)&g_x2[(size_t)row*CC + col];
        float2 r1 = *(const float2*)&g_x2[(size_t)(row+8)*CC + col];
        float2 o0 = make_float2(r0.x + acc[nt][0] + bbv.x, r0.y + acc[nt][1] + bbv.y);
        float2 o1 = make_float2(r1.x + acc[nt][2] + bbv.x, r1.y + acc[nt][3] + bbv.y);
        *(float2*)&out[(size_t)row*CC + col]     = o0;
        *(float2*)&out[(size_t)(row+8)*CC + col] = o1;
    }
}

// =====================================================================
extern "C" void kernel_launch(void* const* d_in, const int* in_sizes, int n_in,
                              void* d_out, int out_size)
{
    const float* x     = (const float*)d_in[0];
    const float* ln1_g = (const float*)d_in[3];
    const float* ln1_b = (const float*)d_in[4];
    const float* q_w   = (const float*)d_in[5];
    const float* q_b   = (const float*)d_in[6];
    const float* kv_w  = (const float*)d_in[7];
    const float* kv_b  = (const float*)d_in[8];
    const float* pr_w  = (const float*)d_in[9];
    const float* pr_b  = (const float*)d_in[10];
    const float* sr_w  = (const float*)d_in[11];
    const float* sr_b  = (const float*)d_in[12];
    const float* srn_g = (const float*)d_in[13];
    const float* srn_b = (const float*)d_in[14];
    const float* ln2_g = (const float*)d_in[15];
    const float* ln2_b = (const float*)d_in[16];
    const float* fc1_w = (const float*)d_in[17];
    const float* fc1_b = (const float*)d_in[18];
    const float* dw_w  = (const float*)d_in[19];
    const float* fc2_w = (const float*)d_in[20];
    const float* fc2_b = (const float*)d_in[21];
    float* out = (float*)d_out;

    const int K1_SMEM = (4096 + 64*132) * 4;                    // 50176
    const int K2_SMEM = 8*4096*4;                               // 131072
    const int K3_SMEM = (64*258 + 16384 + 4096 + 8*2048) * 4;   // 213504
    const int K4_SMEM = (8192 + 128*68) * 4;                    // 67584
    const int K5_SMEM = 6*128*32*4;                             // 98304
    const int K6_SMEM = (16384 + 128*68) * 4;                   // 100352

    cudaFuncSetAttribute(k1_ln_q,   cudaFuncAttributeMaxDynamicSharedMemorySize, K1_SMEM);
    cudaFuncSetAttribute(k2_sr_kv,  cudaFuncAttributeMaxDynamicSharedMemorySize, K2_SMEM);
    cudaFuncSetAttribute(k3_attn,   cudaFuncAttributeMaxDynamicSharedMemorySize, K3_SMEM);
    cudaFuncSetAttribute(k4_ln_fc1, cudaFuncAttributeMaxDynamicSharedMemorySize, K4_SMEM);
    cudaFuncSetAttribute(k5_dw_gelu,cudaFuncAttributeMaxDynamicSharedMemorySize, K5_SMEM);
    cudaFuncSetAttribute(k6_fc2,    cudaFuncAttributeMaxDynamicSharedMemorySize, K6_SMEM);

    k1_ln_q  <<<1024, 256, K1_SMEM>>>(x, ln1_g, ln1_b, q_w, q_b);
    k2_sr_kv <<<256, 256, K2_SMEM>>>(sr_w, sr_b, srn_g, srn_b, kv_w, kv_b);
    k3_attn  <<<512, 256, K3_SMEM>>>(x, pr_w, pr_b);
    k4_ln_fc1<<<2048, 256, K4_SMEM>>>(ln2_g, ln2_b, fc1_w, fc1_b);
    k5_dw_gelu<<<2048, 256, K5_SMEM>>>(dw_w);
    k6_fc2   <<<1024, 256, K6_SMEM>>>(fc2_w, fc2_b, out);
}

// round 7
// speedup vs baseline: 1.8247x; 1.1604x over previous
#include <cuda_runtime.h>
#include <cuda_bf16.h>
#include <math.h>

#define BB   8
#define HH   128
#define WW   128
#define NN   (HH*WW)          // 16384
#define CC   64
#define NR   256
#define HID  256
#define EPSV 1e-5f
#define QSCALE 0.125f

__device__ float g_h  [BB*NN*CC];
__device__ float g_q  [BB*NN*CC];
__device__ float g_k  [BB*NR*CC];
__device__ float g_v  [BB*NR*CC];
__device__ float g_x2 [BB*NN*CC];
__device__ float g_f  [(size_t)BB*NN*HID];
__device__ float g_g  [(size_t)BB*NN*HID];
// fragment-packed operands for k3
__device__ float g_kf [BB*16384];
__device__ float g_vf [BB*16384];
__device__ float g_pwf[4096];

__device__ __forceinline__ float2 ffma2(const float2 a, const float2 b, const float2 c) {
    float2 d;
    asm("fma.rn.f32x2 %0, %1, %2, %3;"
        : "=l"(reinterpret_cast<unsigned long long&>(d))
        : "l"(reinterpret_cast<const unsigned long long&>(a)),
          "l"(reinterpret_cast<const unsigned long long&>(b)),
          "l"(reinterpret_cast<const unsigned long long&>(c)));
    return d;
}
__device__ __forceinline__ float2 dup2(float s) { return make_float2(s, s); }

__device__ __forceinline__ float tf32f(float f) {
    unsigned u;
    asm("cvt.rna.tf32.f32 %0, %1;" : "=r"(u) : "f"(f));
    return __uint_as_float(u);
}

// mma.sync m16n8k8 tf32: D += A(16x8,row) * B(8x8,col)
__device__ __forceinline__ void mma_tf32(float* c, const unsigned* a, float2 b) {
    unsigned b0 = __float_as_uint(b.x), b1 = __float_as_uint(b.y);
    asm volatile("mma.sync.aligned.m16n8k8.row.col.f32.tf32.tf32.f32 "
        "{%0,%1,%2,%3}, {%4,%5,%6,%7}, {%8,%9}, {%0,%1,%2,%3};"
        : "+f"(c[0]), "+f"(c[1]), "+f"(c[2]), "+f"(c[3])
        : "r"(a[0]), "r"(a[1]), "r"(a[2]), "r"(a[3]), "r"(b0), "r"(b1));
}

// =====================================================================
// K1: LN1 + q-proj. grid 1024, block 256. (unchanged)
// =====================================================================
__global__ __launch_bounds__(256) void k1_ln_q(
    const float* __restrict__ x, const float* __restrict__ g1,
    const float* __restrict__ b1, const float* __restrict__ qw,
    const float* __restrict__ qb)
{
    extern __shared__ float sm1[];
    float* qws = sm1;           // [64][64]
    float* hnT = sm1 + 4096;    // [64][132]
    int tid = threadIdx.x, warp = tid >> 5, lane = tid & 31;
    int rowbase = blockIdx.x * 128;
    for (int i = tid; i < 4096; i += 256) qws[i] = qw[i];
    float2 gg = ((const float2*)g1)[lane];
    float2 bbv = ((const float2*)b1)[lane];
    #pragma unroll
    for (int i = 0; i < 16; ++i) {
        int lr = warp*16 + i;
        int row = rowbase + lr;
        float2 v = ((const float2*)x)[row*32 + lane];
        float s = v.x + v.y, ss = v.x*v.x + v.y*v.y;
        #pragma unroll
        for (int o = 16; o; o >>= 1) {
            s  += __shfl_xor_sync(0xffffffffu, s,  o);
            ss += __shfl_xor_sync(0xffffffffu, ss, o);
        }
        float mean = s * (1.f/64.f);
        float rstd = rsqrtf(ss*(1.f/64.f) - mean*mean + EPSV);
        float2 hv;
        hv.x = (v.x - mean)*rstd*gg.x + bbv.x;
        hv.y = (v.y - mean)*rstd*gg.y + bbv.y;
        ((float2*)g_h)[row*32 + lane] = hv;
        hnT[(2*lane)*132 + lr]   = hv.x;
        hnT[(2*lane+1)*132 + lr] = hv.y;
    }
    __syncthreads();

    int tx = tid & 15, ty = tid >> 4;
    float2 acc[8][2];
    #pragma unroll
    for (int r = 0; r < 8; ++r) { acc[r][0] = make_float2(0.f,0.f); acc[r][1] = make_float2(0.f,0.f); }
    #pragma unroll 4
    for (int k = 0; k < 64; ++k) {
        float4 a0 = *(const float4*)&hnT[k*132 + ty*8];
        float4 a1 = *(const float4*)&hnT[k*132 + ty*8 + 4];
        float4 w4 = *(const float4*)&qws[k*64 + tx*4];
        float2 w0 = make_float2(w4.x, w4.y), w1p = make_float2(w4.z, w4.w);
        float a[8] = {a0.x,a0.y,a0.z,a0.w,a1.x,a1.y,a1.z,a1.w};
        #pragma unroll
        for (int r = 0; r < 8; ++r) {
            float2 ad = dup2(a[r]);
            acc[r][0] = ffma2(ad, w0,  acc[r][0]);
            acc[r][1] = ffma2(ad, w1p, acc[r][1]);
        }
    }
    float4 qb4 = *(const float4*)&qb[tx*4];
    #pragma unroll
    for (int r = 0; r < 8; ++r) {
        int row = rowbase + ty*8 + r;
        float4 o = make_float4((acc[r][0].x + qb4.x)*QSCALE,
                               (acc[r][0].y + qb4.y)*QSCALE,
                               (acc[r][1].x + qb4.z)*QSCALE,
                               (acc[r][1].y + qb4.w)*QSCALE);
        *(float4*)&g_q[(size_t)row*64 + tx*4] = o;
    }
}

// =====================================================================
// K2: sr conv (8x8/s8) + LN + kv proj. grid 256, block 256. (unchanged)
// =====================================================================
__global__ __launch_bounds__(256) void k2_sr_kv(
    const float* __restrict__ srw, const float* __restrict__ srb,
    const float* __restrict__ sng, const float* __restrict__ snb,
    const float* __restrict__ kvw, const float* __restrict__ kvb)
{
    extern __shared__ float sm[];   // 8 patches x 4096
    int tid = threadIdx.x;
    int basepos = blockIdx.x * 8;
    int b   = basepos >> 8;
    int rem = basepos & 255;
    int oh  = rem >> 4, ow0 = rem & 15;

    for (int r = 0; r < 8; ++r) {
        size_t base4 = (((size_t)b*NN + (size_t)(oh*8)*WW + (size_t)(ow0+r)*8) * CC) >> 2;
        const float4* src = (const float4*)g_h;
        float4* dst = (float4*)(sm + r*4096);
        for (int k4 = tid; k4 < 1024; k4 += 256) {
            int i = k4 >> 7, rk = k4 & 127;
            dst[k4] = src[base4 + (size_t)i*2048 + rk];
        }
    }
    __syncthreads();

    int cp = tid & 31, r = tid >> 5;
    float2 acc = make_float2(0.f, 0.f);
    const float2* srw2 = (const float2*)srw;
    const float* ap = sm + r*4096;
    #pragma unroll 8
    for (int t = 0; t < 4096; ++t)
        acc = ffma2(dup2(ap[t]), srw2[t*32 + cp], acc);
    __syncthreads();
    float* xr = sm;
    float2 sbp = ((const float2*)srb)[cp];
    acc.x += sbp.x; acc.y += sbp.y;
    ((float2*)xr)[r*32 + cp] = acc;
    __syncthreads();

    int warp = tid >> 5, lane = tid & 31;
    {
        float2 sg  = ((const float2*)sng)[lane];
        float2 sbb = ((const float2*)snb)[lane];
        float2 v = ((float2*)xr)[warp*32 + lane];
        float s = v.x + v.y, ss = v.x*v.x + v.y*v.y;
        #pragma unroll
        for (int o = 16; o; o >>= 1) {
            s  += __shfl_xor_sync(0xffffffffu, s,  o);
            ss += __shfl_xor_sync(0xffffffffu, ss, o);
        }
        float mean = s*(1.f/64.f);
        float rstd = rsqrtf(ss*(1.f/64.f) - mean*mean + EPSV);
        float2 nv;
        nv.x = (v.x-mean)*rstd*sg.x + sbb.x;
        nv.y = (v.y-mean)*rstd*sg.y + sbb.y;
        ((float2*)xr)[warp*32 + lane] = nv;
    }
    __syncthreads();

    int ch = tid & 127, rh = tid >> 7;
    float ak[4];
    float kb = kvb[ch];
    #pragma unroll
    for (int rr = 0; rr < 4; ++rr) ak[rr] = kb;
    #pragma unroll 4
    for (int j = 0; j < 64; ++j) {
        float w = kvw[j*128 + ch];
        #pragma unroll
        for (int rr = 0; rr < 4; ++rr) ak[rr] += xr[(rh*4+rr)*64 + j] * w;
    }
    #pragma unroll
    for (int rr = 0; rr < 4; ++rr) {
        int pos = basepos + rh*4 + rr;
        if (ch < 64) g_k[pos*64 + ch]      = ak[rr];
        else         g_v[pos*64 + ch - 64] = ak[rr];
    }
}

// =====================================================================
// K2b: repack K, V, proj_w into mma B-fragment order. grid 64, block 256.
// =====================================================================
__global__ __launch_bounds__(256) void k2b_pack(const float* __restrict__ pw)
{
    int t = blockIdx.x*256 + threadIdx.x;   // 0..16383
    {   // KF: [nt32][kc8][ln32][2] ; elem = K[key=nt*8+(ln>>2)][d=kc*8+(ln&3)+4j]
        int j = t & 1, ln = (t>>1)&31, kc = (t>>6)&7, nt = t>>9;
        int key = nt*8 + (ln>>2), d = kc*8 + (ln&3) + 4*j;
        #pragma unroll
        for (int b = 0; b < 8; ++b)
            g_kf[b*16384 + t] = g_k[(b*256+key)*64 + d];
    }
    {   // VF: [nt8][kc32][ln32][2] ; elem = V[key=kc*8+(ln&3)+4j][col=nt*8+(ln>>2)]
        int j = t & 1, ln = (t>>1)&31, kc = (t>>6)&31, nt = t>>11;
        int key = kc*8 + (ln&3) + 4*j, col = nt*8 + (ln>>2);
        #pragma unroll
        for (int b = 0; b < 8; ++b)
            g_vf[b*16384 + t] = g_v[(b*256+key)*64 + col];
    }
    if (t < 4096) {  // PWF: [nt8][kc8][ln32][2]
        int j = t & 1, ln = (t>>1)&31, kc = (t>>6)&7, nt = t>>9;
        int k = kc*8 + (ln&3) + 4*j, col = nt*8 + (ln>>2);
        g_pwf[t] = pw[k*64 + col];
    }
}

// =====================================================================
// K3: attention via tf32 mma. grid 2048 (8 b x 256 tiles of 64 q), block 256.
// dyn smem = (16384 + 16384 + 64*268 + 64*68) * 4 = 217088 B.
// =====================================================================
__global__ __launch_bounds__(256) void k3_attn(
    const float* __restrict__ x, const float* __restrict__ pb)
{
    extern __shared__ float sm3[];
    float* KF = sm3;                  // 16384 (reused as WF[4096] after QK)
    float* VF = sm3 + 16384;          // 16384
    float* S  = sm3 + 32768;          // [64][268]
    float* Qs = sm3 + 32768 + 17152;  // [64][68] (reused as Os after QK)
    float* WF = KF;
    float* Os = Qs;

    int tid = threadIdx.x, warp = tid >> 5, lane = tid & 31;
    int gid = lane >> 2, tig = lane & 3;
    int b = blockIdx.x >> 8, tile = blockIdx.x & 255;
    int q0 = tile * 64;

    // ---- stage KF, VF, Q ----
    {
        const float4* kf4 = (const float4*)(g_kf + b*16384);
        const float4* vf4 = (const float4*)(g_vf + b*16384);
        float4* KF4 = (float4*)KF;
        float4* VF4 = (float4*)VF;
        #pragma unroll 4
        for (int i = tid; i < 4096; i += 256) { KF4[i] = kf4[i]; VF4[i] = vf4[i]; }
        const float4* q4 = (const float4*)(g_q + ((size_t)b*NN + q0)*64);
        #pragma unroll
        for (int i = tid; i < 1024; i += 256) {
            int r = i >> 4, c = i & 15;
            *(float4*)&Qs[r*68 + c*4] = q4[i];
        }
    }
    __syncthreads();

    int wy = warp >> 1, wx = warp & 1;

    // ---- QK: warp tile m16 (rows wy*16) x n128 (cols wx*128) ----
    {
        float acc[16][4];
        #pragma unroll
        for (int nt = 0; nt < 16; ++nt)
            #pragma unroll
            for (int r = 0; r < 4; ++r) acc[nt][r] = 0.f;
        #pragma unroll
        for (int kc = 0; kc < 8; ++kc) {
            unsigned a[4];
            const float* ap = Qs + (wy*16 + gid)*68 + kc*8;
            a[0] = __float_as_uint(ap[tig]);
            a[1] = __float_as_uint(ap[8*68 + tig]);
            a[2] = __float_as_uint(ap[tig + 4]);
            a[3] = __float_as_uint(ap[8*68 + tig + 4]);
            #pragma unroll
            for (int nt = 0; nt < 16; ++nt) {
                float2 bv = *(const float2*)&KF[((wx*16 + nt)*8 + kc)*64 + lane*2];
                mma_tf32(acc[nt], a, bv);
            }
        }
        int r0 = wy*16 + gid;
        #pragma unroll
        for (int nt = 0; nt < 16; ++nt) {
            int cb = wx*128 + nt*8 + tig*2;
            *(float2*)&S[r0*268 + cb]     = make_float2(acc[nt][0], acc[nt][1]);
            *(float2*)&S[(r0+8)*268 + cb] = make_float2(acc[nt][2], acc[nt][3]);
        }
    }
    __syncthreads();

    // ---- load proj weight frags into KF region; softmax ----
    {
        const float4* w4 = (const float4*)g_pwf;
        float4* WF4 = (float4*)WF;
        #pragma unroll
        for (int i = tid; i < 1024; i += 256) WF4[i] = w4[i];
    }
    {
        float4* S4 = (float4*)S;       // row stride 67 float4
        #pragma unroll
        for (int i = 0; i < 8; ++i) {
            int r = warp*8 + i;
            float4 v0 = S4[r*67 + lane*2];
            float4 v1 = S4[r*67 + lane*2 + 1];
            float mx = fmaxf(fmaxf(fmaxf(v0.x, v0.y), fmaxf(v0.z, v0.w)),
                             fmaxf(fmaxf(v1.x, v1.y), fmaxf(v1.z, v1.w)));
            #pragma unroll
            for (int o = 16; o; o >>= 1) mx = fmaxf(mx, __shfl_xor_sync(0xffffffffu, mx, o));
            v0.x = __expf(v0.x - mx); v0.y = __expf(v0.y - mx);
            v0.z = __expf(v0.z - mx); v0.w = __expf(v0.w - mx);
            v1.x = __expf(v1.x - mx); v1.y = __expf(v1.y - mx);
            v1.z = __expf(v1.z - mx); v1.w = __expf(v1.w - mx);
            float sum = v0.x + v0.y + v0.z + v0.w + v1.x + v1.y + v1.z + v1.w;
            #pragma unroll
            for (int o = 16; o; o >>= 1) sum += __shfl_xor_sync(0xffffffffu, sum, o);
            float inv = __frcp_rn(sum);
            v0.x *= inv; v0.y *= inv; v0.z *= inv; v0.w *= inv;
            v1.x *= inv; v1.y *= inv; v1.z *= inv; v1.w *= inv;
            S4[r*67 + lane*2]     = v0;
            S4[r*67 + lane*2 + 1] = v1;
        }
    }
    __syncthreads();

    // ---- PV: warp tile m16 (rows wy*16) x n32 (cols wx*32), K=256 ----
    float accO[4][4];
    #pragma unroll
    for (int nt = 0; nt < 4; ++nt)
        #pragma unroll
        for (int r = 0; r < 4; ++r) accO[nt][r] = 0.f;
    #pragma unroll 4
    for (int kc = 0; kc < 32; ++kc) {
        unsigned a[4];
        const float* ap = S + (wy*16 + gid)*268 + kc*8;
        a[0] = __float_as_uint(ap[tig]);
        a[1] = __float_as_uint(ap[8*268 + tig]);
        a[2] = __float_as_uint(ap[tig + 4]);
        a[3] = __float_as_uint(ap[8*268 + tig + 4]);
        #pragma unroll
        for (int nt = 0; nt < 4; ++nt) {
            float2 bv = *(const float2*)&VF[((wx*4 + nt)*32 + kc)*64 + lane*2];
            mma_tf32(accO[nt], a, bv);
        }
    }
    {
        int r0 = wy*16 + gid;
        #pragma unroll
        for (int nt = 0; nt < 4; ++nt) {
            int cb = wx*32 + nt*8 + tig*2;
            *(float2*)&Os[r0*68 + cb]     = make_float2(accO[nt][0], accO[nt][1]);
            *(float2*)&Os[(r0+8)*68 + cb] = make_float2(accO[nt][2], accO[nt][3]);
        }
    }
    __syncthreads();

    // ---- proj: warp tile m16 x n32, K=64 ----
    float accP[4][4];
    #pragma unroll
    for (int nt = 0; nt < 4; ++nt)
        #pragma unroll
        for (int r = 0; r < 4; ++r) accP[nt][r] = 0.f;
    #pragma unroll
    for (int kc = 0; kc < 8; ++kc) {
        unsigned a[4];
        const float* ap = Os + (wy*16 + gid)*68 + kc*8;
        a[0] = __float_as_uint(ap[tig]);
        a[1] = __float_as_uint(ap[8*68 + tig]);
        a[2] = __float_as_uint(ap[tig + 4]);
        a[3] = __float_as_uint(ap[8*68 + tig + 4]);
        #pragma unroll
        for (int nt = 0; nt < 4; ++nt) {
            float2 bv = *(const float2*)&WF[((wx*4 + nt)*8 + kc)*64 + lane*2];
            mma_tf32(accP[nt], a, bv);
        }
    }

    // ---- epilogue: residual + bias ----
    #pragma unroll
    for (int nt = 0; nt < 4; ++nt) {
        int col = wx*32 + nt*8 + tig*2;
        float2 pbv = *(const float2*)&pb[col];
        size_t rowA = (size_t)b*NN + q0 + wy*16 + gid;
        size_t rowB = rowA + 8;
        float2 xa = *(const float2*)&x[rowA*64 + col];
        float2 xb = *(const float2*)&x[rowB*64 + col];
        float2 oa = make_float2(xa.x + accP[nt][0] + pbv.x, xa.y + accP[nt][1] + pbv.y);
        float2 ob = make_float2(xb.x + accP[nt][2] + pbv.x, xb.y + accP[nt][3] + pbv.y);
        *(float2*)&g_x2[rowA*64 + col] = oa;
        *(float2*)&g_x2[rowB*64 + col] = ob;
    }
}

// =====================================================================
// K4: LN2 + fc1 via mma.sync tf32. grid 2048, block 256. (unchanged)
// =====================================================================
__global__ __launch_bounds__(256) void k4_ln_fc1(
    const float* __restrict__ g2, const float* __restrict__ b2,
    const float* __restrict__ w1, const float* __restrict__ fb1)
{
    extern __shared__ float sm4[];
    float* WF = sm4;            // B fragments: [16 nt][8 kc][32 lane][2]
    float* As = sm4 + 8192;     // [128][68]
    int tid = threadIdx.x, warp = tid >> 5, lane = tid & 31;
    int gid = lane >> 2, tig = lane & 3;
    int cb = blockIdx.x & 1;
    int rowbase = (blockIdx.x >> 1) * 128;

    for (int idx = tid; idx < 8192; idx += 256) {
        int nt = idx >> 9, kc = (idx >> 6) & 7, ln = (idx >> 1) & 31, j = idx & 1;
        int k = kc*8 + (ln & 3) + j*4;
        int col = cb*128 + nt*8 + (ln >> 2);
        WF[idx] = tf32f(w1[k*256 + col]);
    }

    float2 gg = ((const float2*)g2)[lane];
    float2 bb = ((const float2*)b2)[lane];
    #pragma unroll
    for (int i = 0; i < 16; ++i) {
        int lr = warp*16 + i;
        int row = rowbase + lr;
        float2 v = ((const float2*)g_x2)[row*32 + lane];
        float s = v.x + v.y, ss = v.x*v.x + v.y*v.y;
        #pragma unroll
        for (int o = 16; o; o >>= 1) {
            s  += __shfl_xor_sync(0xffffffffu, s,  o);
            ss += __shfl_xor_sync(0xffffffffu, ss, o);
        }
        float mean = s*(1.f/64.f);
        float rstd = rsqrtf(ss*(1.f/64.f) - mean*mean + EPSV);
        float2 st;
        st.x = tf32f((v.x-mean)*rstd*gg.x + bb.x);
        st.y = tf32f((v.y-mean)*rstd*gg.y + bb.y);
        *(float2*)&As[lr*68 + 2*lane] = st;
    }
    __syncthreads();

    int wy = warp >> 1, wx = warp & 1;
    float acc[2][8][4];
    #pragma unroll
    for (int mt = 0; mt < 2; ++mt)
        #pragma unroll
        for (int nt = 0; nt < 8; ++nt)
            #pragma unroll
            for (int r = 0; r < 4; ++r) acc[mt][nt][r] = 0.f;

    #pragma unroll
    for (int kc = 0; kc < 8; ++kc) {
        unsigned a[2][4];
        #pragma unroll
        for (int mt = 0; mt < 2; ++mt) {
            const float* ap = As + (wy*32 + mt*16 + gid)*68 + kc*8;
            a[mt][0] = __float_as_uint(ap[tig]);
            a[mt][1] = __float_as_uint(ap[8*68 + tig]);
            a[mt][2] = __float_as_uint(ap[tig + 4]);
            a[mt][3] = __float_as_uint(ap[8*68 + tig + 4]);
        }
        #pragma unroll
        for (int nt = 0; nt < 8; ++nt) {
            float2 bv = *(const float2*)&WF[((wx*8 + nt)*8 + kc)*64 + lane*2];
            mma_tf32(acc[0][nt], a[0], bv);
            mma_tf32(acc[1][nt], a[1], bv);
        }
    }

    #pragma unroll
    for (int mt = 0; mt < 2; ++mt)
        #pragma unroll
        for (int nt = 0; nt < 8; ++nt) {
            int col = cb*128 + (wx*8 + nt)*8 + tig*2;
            float2 fbv = *(const float2*)&fb1[col];
            int row = rowbase + wy*32 + mt*16 + gid;
            float2 o0 = make_float2(acc[mt][nt][0] + fbv.x, acc[mt][nt][1] + fbv.y);
            float2 o1 = make_float2(acc[mt][nt][2] + fbv.x, acc[mt][nt][3] + fbv.y);
            *(float2*)&g_f[(size_t)row*HID + col]      = o0;
            *(float2*)&g_f[(size_t)(row+8)*HID + col]  = o1;
        }
}

// =====================================================================
// K5: depthwise 3x3 SAME + GELU, smem-tiled rolling conv. (unchanged)
// =====================================================================
__global__ __launch_bounds__(256) void k5_dw_gelu(const float* __restrict__ dww)
{
    extern __shared__ float s5[];   // [6][128][32]
    int tid = threadIdx.x;
    int blk = blockIdx.x;
    int ct = blk & 7, ht = (blk >> 3) & 31, b = blk >> 8;
    int c0 = ct * 32, h0 = ht * 4;
    #pragma unroll
    for (int r = 0; r < 6; ++r) {
        int h = h0 - 1 + r;
        float4* dst = (float4*)(s5 + r*4096);
        if ((unsigned)h < 128u) {
            const float4* src = (const float4*)(g_f + ((size_t)b*NN + (size_t)h*WW)*HID + c0);
            for (int i = tid; i < 1024; i += 256) {
                int w = i >> 3, cq = i & 7;
                dst[i] = src[w*64 + cq];
            }
        } else {
            float4 z = make_float4(0.f,0.f,0.f,0.f);
            for (int i = tid; i < 1024; i += 256) dst[i] = z;
        }
    }
    __syncthreads();

    int cp = tid & 15, wi = tid >> 4;
    float2 wt[9];
    #pragma unroll
    for (int t = 0; t < 9; ++t)
        wt[t] = *(const float2*)&dww[t*HID + c0 + 2*cp];
    const int coff = 2*cp;

    #pragma unroll
    for (int ro = 0; ro < 4; ++ro) {
        const float* r0p = s5 + ro*4096 + coff;
        const float* r1p = r0p + 4096;
        const float* r2p = r1p + 4096;
        int w = wi * 8;
        float2 L0, L1, L2, C0, C1, C2;
        if (w == 0) {
            L0 = L1 = L2 = make_float2(0.f, 0.f);
        } else {
            L0 = *(const float2*)&r0p[(w-1)*32];
            L1 = *(const float2*)&r1p[(w-1)*32];
            L2 = *(const float2*)&r2p[(w-1)*32];
        }
        C0 = *(const float2*)&r0p[w*32];
        C1 = *(const float2*)&r1p[w*32];
        C2 = *(const float2*)&r2p[w*32];
        #pragma unroll
        for (int k = 0; k < 8; ++k) {
            float2 N0, N1, N2;
            if (w + 1 < 128) {
                N0 = *(const float2*)&r0p[(w+1)*32];
                N1 = *(const float2*)&r1p[(w+1)*32];
                N2 = *(const float2*)&r2p[(w+1)*32];
            } else {
                N0 = N1 = N2 = make_float2(0.f, 0.f);
            }
            float2 acc = make_float2(0.f, 0.f);
            acc = ffma2(L0, wt[0], acc); acc = ffma2(C0, wt[1], acc); acc = ffma2(N0, wt[2], acc);
            acc = ffma2(L1, wt[3], acc); acc = ffma2(C1, wt[4], acc); acc = ffma2(N1, wt[5], acc);
            acc = ffma2(L2, wt[6], acc); acc = ffma2(C2, wt[7], acc); acc = ffma2(N2, wt[8], acc);
            float2 o;
            o.x = acc.x * normcdff(acc.x);
            o.y = acc.y * normcdff(acc.y);
            *(float2*)&g_g[((size_t)b*NN + (size_t)(h0+ro)*WW + w)*HID + c0 + coff] = o;
            L0 = C0; L1 = C1; L2 = C2;
            C0 = N0; C1 = N1; C2 = N2;
            ++w;
        }
    }
}

// =====================================================================
// K6: fc2 (256->64) + residual via mma.sync tf32. grid 1024, block 256.
// (unchanged)
// =====================================================================
__global__ __launch_bounds__(256) void k6_fc2(
    const float* __restrict__ w2, const float* __restrict__ b2,
    float* __restrict__ out)
{
    extern __shared__ float sm6[];
    float* WF = sm6;             // [8 nt][32 kc][32 lane][2] = 16384
    float* As = sm6 + 16384;     // [128][68]
    int tid = threadIdx.x, warp = tid >> 5, lane = tid & 31;
    int gid = lane >> 2, tig = lane & 3;
    int rowbase = blockIdx.x * 128;

    for (int idx = tid; idx < 16384; idx += 256) {
        int nt = idx >> 11, kc = (idx >> 6) & 31, ln = (idx >> 1) & 31, j = idx & 1;
        int k = kc*8 + (ln & 3) + j*4;
        int col = nt*8 + (ln >> 2);
        WF[idx] = tf32f(w2[k*64 + col]);
    }

    float acc[8][4];
    #pragma unroll
    for (int nt = 0; nt < 8; ++nt)
        #pragma unroll
        for (int r = 0; r < 4; ++r) acc[nt][r] = 0.f;

    for (int kblk = 0; kblk < 4; ++kblk) {
        __syncthreads();
        for (int i = tid; i < 2048; i += 256) {
            int row = i >> 4, q = i & 15;
            float4 v = *(const float4*)&g_g[(size_t)(rowbase+row)*HID + kblk*64 + q*4];
            v.x = tf32f(v.x); v.y = tf32f(v.y); v.z = tf32f(v.z); v.w = tf32f(v.w);
            *(float4*)&As[row*68 + q*4] = v;
        }
        __syncthreads();
        #pragma unroll
        for (int kc = 0; kc < 8; ++kc) {
            unsigned a[4];
            const float* ap = As + (warp*16 + gid)*68 + kc*8;
            a[0] = __float_as_uint(ap[tig]);
            a[1] = __float_as_uint(ap[8*68 + tig]);
            a[2] = __float_as_uint(ap[tig + 4]);
            a[3] = __float_as_uint(ap[8*68 + tig + 4]);
            #pragma unroll
            for (int nt = 0; nt < 8; ++nt) {
                float2 bv = *(const float2*)&WF[(nt*32 + kblk*8 + kc)*64 + lane*2];
                mma_tf32(acc[nt], a, bv);
            }
        }
    }

    #pragma unroll
    for (int nt = 0; nt < 8; ++nt) {
        int col = nt*8 + tig*2;
        float2 bbv = *(const float2*)&b2[col];
        int row = rowbase + warp*16 + gid;
        float2 r0 = *(const float2*)&g_x2[(size_t)row*CC + col];
        float2 r1 = *(const float2*)&g_x2[(size_t)(row+8)*CC + col];
        float2 o0 = make_float2(r0.x + acc[nt][0] + bbv.x, r0.y + acc[nt][1] + bbv.y);
        float2 o1 = make_float2(r1.x + acc[nt][2] + bbv.x, r1.y + acc[nt][3] + bbv.y);
        *(float2*)&out[(size_t)row*CC + col]     = o0;
        *(float2*)&out[(size_t)(row+8)*CC + col] = o1;
    }
}

// =====================================================================
extern "C" void kernel_launch(void* const* d_in, const int* in_sizes, int n_in,
                              void* d_out, int out_size)
{
    const float* x     = (const float*)d_in[0];
    const float* ln1_g = (const float*)d_in[3];
    const float* ln1_b = (const float*)d_in[4];
    const float* q_w   = (const float*)d_in[5];
    const float* q_b   = (const float*)d_in[6];
    const float* kv_w  = (const float*)d_in[7];
    const float* kv_b  = (const float*)d_in[8];
    const float* pr_w  = (const float*)d_in[9];
    const float* pr_b  = (const float*)d_in[10];
    const float* sr_w  = (const float*)d_in[11];
    const float* sr_b  = (const float*)d_in[12];
    const float* srn_g = (const float*)d_in[13];
    const float* srn_b = (const float*)d_in[14];
    const float* ln2_g = (const float*)d_in[15];
    const float* ln2_b = (const float*)d_in[16];
    const float* fc1_w = (const float*)d_in[17];
    const float* fc1_b = (const float*)d_in[18];
    const float* dw_w  = (const float*)d_in[19];
    const float* fc2_w = (const float*)d_in[20];
    const float* fc2_b = (const float*)d_in[21];
    float* out = (float*)d_out;

    const int K1_SMEM = (4096 + 64*132) * 4;                    // 50176
    const int K2_SMEM = 8*4096*4;                               // 131072
    const int K3_SMEM = (16384 + 16384 + 64*268 + 64*68) * 4;   // 217088
    const int K4_SMEM = (8192 + 128*68) * 4;                    // 67584
    const int K5_SMEM = 6*128*32*4;                             // 98304
    const int K6_SMEM = (16384 + 128*68) * 4;                   // 100352

    cudaFuncSetAttribute(k1_ln_q,   cudaFuncAttributeMaxDynamicSharedMemorySize, K1_SMEM);
    cudaFuncSetAttribute(k2_sr_kv,  cudaFuncAttributeMaxDynamicSharedMemorySize, K2_SMEM);
    cudaFuncSetAttribute(k3_attn,   cudaFuncAttributeMaxDynamicSharedMemorySize, K3_SMEM);
    cudaFuncSetAttribute(k4_ln_fc1, cudaFuncAttributeMaxDynamicSharedMemorySize, K4_SMEM);
    cudaFuncSetAttribute(k5_dw_gelu,cudaFuncAttributeMaxDynamicSharedMemorySize, K5_SMEM);
    cudaFuncSetAttribute(k6_fc2,    cudaFuncAttributeMaxDynamicSharedMemorySize, K6_SMEM);

    k1_ln_q  <<<1024, 256, K1_SMEM>>>(x, ln1_g, ln1_b, q_w, q_b);
    k2_sr_kv <<<256, 256, K2_SMEM>>>(sr_w, sr_b, srn_g, srn_b, kv_w, kv_b);
    k2b_pack <<<64, 256>>>(pr_w);
    k3_attn  <<<2048, 256, K3_SMEM>>>(x, pr_b);
    k4_ln_fc1<<<2048, 256, K4_SMEM>>>(ln2_g, ln2_b, fc1_w, fc1_b);
    k5_dw_gelu<<<2048, 256, K5_SMEM>>>(dw_w);
    k6_fc2   <<<1024, 256, K6_SMEM>>>(fc2_w, fc2_b, out);
}

// round 8
// speedup vs baseline: 1.8388x; 1.0077x over previous
#include <cuda_runtime.h>
#include <cuda_bf16.h>
#include <math.h>

#define BB   8
#define HH   128
#define WW   128
#define NN   (HH*WW)          // 16384
#define CC   64
#define NR   256
#define HID  256
#define EPSV 1e-5f
#define QSCALE 0.125f

__device__ float g_h  [BB*NN*CC];
__device__ float g_q  [BB*NN*CC];
__device__ float g_k  [BB*NR*CC];
__device__ float g_v  [BB*NR*CC];
__device__ float g_x2 [BB*NN*CC];
__device__ float g_f  [(size_t)BB*NN*HID];
__device__ float g_g  [(size_t)BB*NN*HID];
// fragment-packed operands for k3
__device__ float g_kf [BB*16384];
__device__ float g_vf [BB*16384];
__device__ float g_pwf[4096];

__device__ __forceinline__ float2 ffma2(const float2 a, const float2 b, const float2 c) {
    float2 d;
    asm("fma.rn.f32x2 %0, %1, %2, %3;"
        : "=l"(reinterpret_cast<unsigned long long&>(d))
        : "l"(reinterpret_cast<const unsigned long long&>(a)),
          "l"(reinterpret_cast<const unsigned long long&>(b)),
          "l"(reinterpret_cast<const unsigned long long&>(c)));
    return d;
}
__device__ __forceinline__ float2 dup2(float s) { return make_float2(s, s); }

__device__ __forceinline__ float tf32f(float f) {
    unsigned u;
    asm("cvt.rna.tf32.f32 %0, %1;" : "=r"(u) : "f"(f));
    return __uint_as_float(u);
}

// mma.sync m16n8k8 tf32: D += A(16x8,row) * B(8x8,col)
__device__ __forceinline__ void mma_tf32(float* c, const unsigned* a, float2 b) {
    unsigned b0 = __float_as_uint(b.x), b1 = __float_as_uint(b.y);
    asm volatile("mma.sync.aligned.m16n8k8.row.col.f32.tf32.tf32.f32 "
        "{%0,%1,%2,%3}, {%4,%5,%6,%7}, {%8,%9}, {%0,%1,%2,%3};"
        : "+f"(c[0]), "+f"(c[1]), "+f"(c[2]), "+f"(c[3])
        : "r"(a[0]), "r"(a[1]), "r"(a[2]), "r"(a[3]), "r"(b0), "r"(b1));
}

// =====================================================================
// K1: LN1 (fp32 h out) + q-proj via tf32 mma. grid 1024, block 256.
// dyn smem: WF 4096 + As 128*68 = 12800 floats = 51200 B.
// =====================================================================
__global__ __launch_bounds__(256) void k1_ln_q(
    const float* __restrict__ x, const float* __restrict__ g1,
    const float* __restrict__ b1, const float* __restrict__ qw,
    const float* __restrict__ qb)
{
    extern __shared__ float sm1[];
    float* WF = sm1;            // [8 nt][8 kc][32 ln][2]
    float* As = sm1 + 4096;     // [128][68]
    int tid = threadIdx.x, warp = tid >> 5, lane = tid & 31;
    int gid = lane >> 2, tig = lane & 3;
    int rowbase = blockIdx.x * 128;

    for (int idx = tid; idx < 4096; idx += 256) {
        int nt = idx >> 9, kc = (idx >> 6) & 7, ln = (idx >> 1) & 31, j = idx & 1;
        int k = kc*8 + (ln & 3) + j*4;
        int col = nt*8 + (ln >> 2);
        WF[idx] = tf32f(qw[k*64 + col]);
    }

    float2 gg = ((const float2*)g1)[lane];
    float2 bbv = ((const float2*)b1)[lane];
    #pragma unroll
    for (int i = 0; i < 16; ++i) {
        int lr = warp*16 + i;
        int row = rowbase + lr;
        float2 v = ((const float2*)x)[row*32 + lane];
        float s = v.x + v.y, ss = v.x*v.x + v.y*v.y;
        #pragma unroll
        for (int o = 16; o; o >>= 1) {
            s  += __shfl_xor_sync(0xffffffffu, s,  o);
            ss += __shfl_xor_sync(0xffffffffu, ss, o);
        }
        float mean = s * (1.f/64.f);
        float rstd = rsqrtf(ss*(1.f/64.f) - mean*mean + EPSV);
        float2 hv;
        hv.x = (v.x - mean)*rstd*gg.x + bbv.x;
        hv.y = (v.y - mean)*rstd*gg.y + bbv.y;
        ((float2*)g_h)[row*32 + lane] = hv;
        float2 st = make_float2(tf32f(hv.x), tf32f(hv.y));
        *(float2*)&As[lr*68 + 2*lane] = st;
    }
    __syncthreads();

    float acc[8][4];
    #pragma unroll
    for (int nt = 0; nt < 8; ++nt)
        #pragma unroll
        for (int r = 0; r < 4; ++r) acc[nt][r] = 0.f;
    #pragma unroll
    for (int kc = 0; kc < 8; ++kc) {
        unsigned a[4];
        const float* ap = As + (warp*16 + gid)*68 + kc*8;
        a[0] = __float_as_uint(ap[tig]);
        a[1] = __float_as_uint(ap[8*68 + tig]);
        a[2] = __float_as_uint(ap[tig + 4]);
        a[3] = __float_as_uint(ap[8*68 + tig + 4]);
        #pragma unroll
        for (int nt = 0; nt < 8; ++nt) {
            float2 bv = *(const float2*)&WF[(nt*8 + kc)*64 + lane*2];
            mma_tf32(acc[nt], a, bv);
        }
    }

    #pragma unroll
    for (int nt = 0; nt < 8; ++nt) {
        int col = nt*8 + tig*2;
        float2 qbv = *(const float2*)&qb[col];
        int row = rowbase + warp*16 + gid;
        float2 o0 = make_float2((acc[nt][0] + qbv.x)*QSCALE, (acc[nt][1] + qbv.y)*QSCALE);
        float2 o1 = make_float2((acc[nt][2] + qbv.x)*QSCALE, (acc[nt][3] + qbv.y)*QSCALE);
        *(float2*)&g_q[(size_t)row*64 + col]     = o0;
        *(float2*)&g_q[(size_t)(row+8)*64 + col] = o1;
    }
}

// =====================================================================
// K2: sr conv (8x8/s8) + LN + kv proj. grid 256, block 256. smem 128 KB.
// 4 independent accumulators to break the FFMA2 dependency chain.
// =====================================================================
__global__ __launch_bounds__(256) void k2_sr_kv(
    const float* __restrict__ srw, const float* __restrict__ srb,
    const float* __restrict__ sng, const float* __restrict__ snb,
    const float* __restrict__ kvw, const float* __restrict__ kvb)
{
    extern __shared__ float sm[];   // 8 patches x 4096
    int tid = threadIdx.x;
    int basepos = blockIdx.x * 8;
    int b   = basepos >> 8;
    int rem = basepos & 255;
    int oh  = rem >> 4, ow0 = rem & 15;

    for (int r = 0; r < 8; ++r) {
        size_t base4 = (((size_t)b*NN + (size_t)(oh*8)*WW + (size_t)(ow0+r)*8) * CC) >> 2;
        const float4* src = (const float4*)g_h;
        float4* dst = (float4*)(sm + r*4096);
        for (int k4 = tid; k4 < 1024; k4 += 256) {
            int i = k4 >> 7, rk = k4 & 127;
            dst[k4] = src[base4 + (size_t)i*2048 + rk];
        }
    }
    __syncthreads();

    int cp = tid & 31, r = tid >> 5;
    float2 a0 = make_float2(0.f,0.f), a1 = make_float2(0.f,0.f);
    float2 a2 = make_float2(0.f,0.f), a3 = make_float2(0.f,0.f);
    const float2* srw2 = (const float2*)srw;
    const float* ap = sm + r*4096;
    #pragma unroll 4
    for (int t = 0; t < 4096; t += 4) {
        a0 = ffma2(dup2(ap[t]),   srw2[(t)*32 + cp],   a0);
        a1 = ffma2(dup2(ap[t+1]), srw2[(t+1)*32 + cp], a1);
        a2 = ffma2(dup2(ap[t+2]), srw2[(t+2)*32 + cp], a2);
        a3 = ffma2(dup2(ap[t+3]), srw2[(t+3)*32 + cp], a3);
    }
    float2 acc = make_float2(a0.x+a1.x+a2.x+a3.x, a0.y+a1.y+a2.y+a3.y);
    __syncthreads();
    float* xr = sm;
    float2 sbp = ((const float2*)srb)[cp];
    acc.x += sbp.x; acc.y += sbp.y;
    ((float2*)xr)[r*32 + cp] = acc;
    __syncthreads();

    int warp = tid >> 5, lane = tid & 31;
    {
        float2 sg  = ((const float2*)sng)[lane];
        float2 sbb = ((const float2*)snb)[lane];
        float2 v = ((float2*)xr)[warp*32 + lane];
        float s = v.x + v.y, ss = v.x*v.x + v.y*v.y;
        #pragma unroll
        for (int o = 16; o; o >>= 1) {
            s  += __shfl_xor_sync(0xffffffffu, s,  o);
            ss += __shfl_xor_sync(0xffffffffu, ss, o);
        }
        float mean = s*(1.f/64.f);
        float rstd = rsqrtf(ss*(1.f/64.f) - mean*mean + EPSV);
        float2 nv;
        nv.x = (v.x-mean)*rstd*sg.x + sbb.x;
        nv.y = (v.y-mean)*rstd*sg.y + sbb.y;
        ((float2*)xr)[warp*32 + lane] = nv;
    }
    __syncthreads();

    int ch = tid & 127, rh = tid >> 7;
    float ak[4];
    float kb = kvb[ch];
    #pragma unroll
    for (int rr = 0; rr < 4; ++rr) ak[rr] = kb;
    #pragma unroll 4
    for (int j = 0; j < 64; ++j) {
        float w = kvw[j*128 + ch];
        #pragma unroll
        for (int rr = 0; rr < 4; ++rr) ak[rr] += xr[(rh*4+rr)*64 + j] * w;
    }
    #pragma unroll
    for (int rr = 0; rr < 4; ++rr) {
        int pos = basepos + rh*4 + rr;
        if (ch < 64) g_k[pos*64 + ch]      = ak[rr];
        else         g_v[pos*64 + ch - 64] = ak[rr];
    }
}

// =====================================================================
// K2b: repack K, V, proj_w into mma B-fragment order. grid 64, block 256.
// =====================================================================
__global__ __launch_bounds__(256) void k2b_pack(const float* __restrict__ pw)
{
    int t = blockIdx.x*256 + threadIdx.x;   // 0..16383
    {   // KF: [nt32][kc8][ln32][2]
        int j = t & 1, ln = (t>>1)&31, kc = (t>>6)&7, nt = t>>9;
        int key = nt*8 + (ln>>2), d = kc*8 + (ln&3) + 4*j;
        #pragma unroll
        for (int b = 0; b < 8; ++b)
            g_kf[b*16384 + t] = g_k[(b*256+key)*64 + d];
    }
    {   // VF: [nt8][kc32][ln32][2]
        int j = t & 1, ln = (t>>1)&31, kc = (t>>6)&31, nt = t>>11;
        int key = kc*8 + (ln&3) + 4*j, col = nt*8 + (ln>>2);
        #pragma unroll
        for (int b = 0; b < 8; ++b)
            g_vf[b*16384 + t] = g_v[(b*256+key)*64 + col];
    }
    if (t < 4096) {  // PWF: [nt8][kc8][ln32][2]
        int j = t & 1, ln = (t>>1)&31, kc = (t>>6)&7, nt = t>>9;
        int k = kc*8 + (ln&3) + 4*j, col = nt*8 + (ln>>2);
        g_pwf[t] = pw[k*64 + col];
    }
}

// =====================================================================
// K3: attention via tf32 mma, 4 query-tiles per block.
// grid 512 (8 b x 64 groups), block 256.
// smem floats: KF 16384 | VF 16384 | WF 4096 | S 64*260 | Qs 64*68
// total 57856 floats = 231424 B.
// =====================================================================
__global__ __launch_bounds__(256) void k3_attn(
    const float* __restrict__ x, const float* __restrict__ pb)
{
    extern __shared__ float sm3[];
    float* KF = sm3;                  // 16384
    float* VF = sm3 + 16384;          // 16384
    float* WF = sm3 + 32768;          // 4096
    float* S  = sm3 + 36864;          // [64][260]
    float* Qs = sm3 + 36864 + 16640;  // [64][68], reused as Os

    int tid = threadIdx.x, warp = tid >> 5, lane = tid & 31;
    int gid = lane >> 2, tig = lane & 3;
    int b = blockIdx.x >> 6, grp = blockIdx.x & 63;
    float* Os = Qs;

    // ---- stage KF, VF, WF once ----
    {
        const float4* kf4 = (const float4*)(g_kf + b*16384);
        const float4* vf4 = (const float4*)(g_vf + b*16384);
        float4* KF4 = (float4*)KF;
        float4* VF4 = (float4*)VF;
        #pragma unroll 4
        for (int i = tid; i < 4096; i += 256) { KF4[i] = kf4[i]; VF4[i] = vf4[i]; }
        const float4* w4 = (const float4*)g_pwf;
        float4* WF4 = (float4*)WF;
        #pragma unroll
        for (int i = tid; i < 1024; i += 256) WF4[i] = w4[i];
    }

    int wy = warp >> 1, wx = warp & 1;

    for (int it = 0; it < 4; ++it) {
        int q0 = (grp*4 + it) * 64;
        __syncthreads();
        // ---- stage Q tile ----
        {
            const float4* q4 = (const float4*)(g_q + ((size_t)b*NN + q0)*64);
            #pragma unroll
            for (int i = tid; i < 1024; i += 256) {
                int r = i >> 4, c = i & 15;
                *(float4*)&Qs[r*68 + c*4] = q4[i];
            }
        }
        __syncthreads();

        // ---- QK: warp tile m16 x n128 ----
        {
            float acc[16][4];
            #pragma unroll
            for (int nt = 0; nt < 16; ++nt)
                #pragma unroll
                for (int r = 0; r < 4; ++r) acc[nt][r] = 0.f;
            #pragma unroll
            for (int kc = 0; kc < 8; ++kc) {
                unsigned a[4];
                const float* ap = Qs + (wy*16 + gid)*68 + kc*8;
                a[0] = __float_as_uint(ap[tig]);
                a[1] = __float_as_uint(ap[8*68 + tig]);
                a[2] = __float_as_uint(ap[tig + 4]);
                a[3] = __float_as_uint(ap[8*68 + tig + 4]);
                #pragma unroll
                for (int nt = 0; nt < 16; ++nt) {
                    float2 bv = *(const float2*)&KF[((wx*16 + nt)*8 + kc)*64 + lane*2];
                    mma_tf32(acc[nt], a, bv);
                }
            }
            int r0 = wy*16 + gid;
            #pragma unroll
            for (int nt = 0; nt < 16; ++nt) {
                int cb = wx*128 + nt*8 + tig*2;
                *(float2*)&S[r0*260 + cb]     = make_float2(acc[nt][0], acc[nt][1]);
                *(float2*)&S[(r0+8)*260 + cb] = make_float2(acc[nt][2], acc[nt][3]);
            }
        }
        __syncthreads();

        // ---- softmax over 256 cols (warp per 8 rows) ----
        {
            float4* S4 = (float4*)S;       // row stride 65 float4
            #pragma unroll
            for (int i = 0; i < 8; ++i) {
                int r = warp*8 + i;
                float4 v0 = S4[r*65 + lane*2];
                float4 v1 = S4[r*65 + lane*2 + 1];
                float mx = fmaxf(fmaxf(fmaxf(v0.x, v0.y), fmaxf(v0.z, v0.w)),
                                 fmaxf(fmaxf(v1.x, v1.y), fmaxf(v1.z, v1.w)));
                #pragma unroll
                for (int o = 16; o; o >>= 1) mx = fmaxf(mx, __shfl_xor_sync(0xffffffffu, mx, o));
                v0.x = __expf(v0.x - mx); v0.y = __expf(v0.y - mx);
                v0.z = __expf(v0.z - mx); v0.w = __expf(v0.w - mx);
                v1.x = __expf(v1.x - mx); v1.y = __expf(v1.y - mx);
                v1.z = __expf(v1.z - mx); v1.w = __expf(v1.w - mx);
                float sum = v0.x + v0.y + v0.z + v0.w + v1.x + v1.y + v1.z + v1.w;
                #pragma unroll
                for (int o = 16; o; o >>= 1) sum += __shfl_xor_sync(0xffffffffu, sum, o);
                float inv = __frcp_rn(sum);
                v0.x *= inv; v0.y *= inv; v0.z *= inv; v0.w *= inv;
                v1.x *= inv; v1.y *= inv; v1.z *= inv; v1.w *= inv;
                S4[r*65 + lane*2]     = v0;
                S4[r*65 + lane*2 + 1] = v1;
            }
        }
        __syncthreads();

        // ---- PV: warp tile m16 x n32, K=256 ----
        float accO[4][4];
        #pragma unroll
        for (int nt = 0; nt < 4; ++nt)
            #pragma unroll
            for (int r = 0; r < 4; ++r) accO[nt][r] = 0.f;
        #pragma unroll 4
        for (int kc = 0; kc < 32; ++kc) {
            unsigned a[4];
            const float* ap = S + (wy*16 + gid)*260 + kc*8;
            a[0] = __float_as_uint(ap[tig]);
            a[1] = __float_as_uint(ap[8*260 + tig]);
            a[2] = __float_as_uint(ap[tig + 4]);
            a[3] = __float_as_uint(ap[8*260 + tig + 4]);
            #pragma unroll
            for (int nt = 0; nt < 4; ++nt) {
                float2 bv = *(const float2*)&VF[((wx*4 + nt)*32 + kc)*64 + lane*2];
                mma_tf32(accO[nt], a, bv);
            }
        }
        __syncthreads();   // Qs free (Q reads done in QK phase)
        {
            int r0 = wy*16 + gid;
            #pragma unroll
            for (int nt = 0; nt < 4; ++nt) {
                int cb = wx*32 + nt*8 + tig*2;
                *(float2*)&Os[r0*68 + cb]     = make_float2(accO[nt][0], accO[nt][1]);
                *(float2*)&Os[(r0+8)*68 + cb] = make_float2(accO[nt][2], accO[nt][3]);
            }
        }
        __syncthreads();

        // ---- proj: warp tile m16 x n32, K=64 ----
        float accP[4][4];
        #pragma unroll
        for (int nt = 0; nt < 4; ++nt)
            #pragma unroll
            for (int r = 0; r < 4; ++r) accP[nt][r] = 0.f;
        #pragma unroll
        for (int kc = 0; kc < 8; ++kc) {
            unsigned a[4];
            const float* ap = Os + (wy*16 + gid)*68 + kc*8;
            a[0] = __float_as_uint(ap[tig]);
            a[1] = __float_as_uint(ap[8*68 + tig]);
            a[2] = __float_as_uint(ap[tig + 4]);
            a[3] = __float_as_uint(ap[8*68 + tig + 4]);
            #pragma unroll
            for (int nt = 0; nt < 4; ++nt) {
                float2 bv = *(const float2*)&WF[((wx*4 + nt)*8 + kc)*64 + lane*2];
                mma_tf32(accP[nt], a, bv);
            }
        }

        // ---- epilogue: residual + bias ----
        #pragma unroll
        for (int nt = 0; nt < 4; ++nt) {
            int col = wx*32 + nt*8 + tig*2;
            float2 pbv = *(const float2*)&pb[col];
            size_t rowA = (size_t)b*NN + q0 + wy*16 + gid;
            size_t rowB = rowA + 8;
            float2 xa = *(const float2*)&x[rowA*64 + col];
            float2 xb = *(const float2*)&x[rowB*64 + col];
            float2 oa = make_float2(xa.x + accP[nt][0] + pbv.x, xa.y + accP[nt][1] + pbv.y);
            float2 ob = make_float2(xb.x + accP[nt][2] + pbv.x, xb.y + accP[nt][3] + pbv.y);
            *(float2*)&g_x2[rowA*64 + col] = oa;
            *(float2*)&g_x2[rowB*64 + col] = ob;
        }
    }
}

// =====================================================================
// K4: LN2 + fc1 via mma.sync tf32. grid 2048, block 256. (unchanged)
// =====================================================================
__global__ __launch_bounds__(256) void k4_ln_fc1(
    const float* __restrict__ g2, const float* __restrict__ b2,
    const float* __restrict__ w1, const float* __restrict__ fb1)
{
    extern __shared__ float sm4[];
    float* WF = sm4;            // [16 nt][8 kc][32 ln][2]
    float* As = sm4 + 8192;     // [128][68]
    int tid = threadIdx.x, warp = tid >> 5, lane = tid & 31;
    int gid = lane >> 2, tig = lane & 3;
    int cb = blockIdx.x & 1;
    int rowbase = (blockIdx.x >> 1) * 128;

    for (int idx = tid; idx < 8192; idx += 256) {
        int nt = idx >> 9, kc = (idx >> 6) & 7, ln = (idx >> 1) & 31, j = idx & 1;
        int k = kc*8 + (ln & 3) + j*4;
        int col = cb*128 + nt*8 + (ln >> 2);
        WF[idx] = tf32f(w1[k*256 + col]);
    }

    float2 gg = ((const float2*)g2)[lane];
    float2 bb = ((const float2*)b2)[lane];
    #pragma unroll
    for (int i = 0; i < 16; ++i) {
        int lr = warp*16 + i;
        int row = rowbase + lr;
        float2 v = ((const float2*)g_x2)[row*32 + lane];
        float s = v.x + v.y, ss = v.x*v.x + v.y*v.y;
        #pragma unroll
        for (int o = 16; o; o >>= 1) {
            s  += __shfl_xor_sync(0xffffffffu, s,  o);
            ss += __shfl_xor_sync(0xffffffffu, ss, o);
        }
        float mean = s*(1.f/64.f);
        float rstd = rsqrtf(ss*(1.f/64.f) - mean*mean + EPSV);
        float2 st;
        st.x = tf32f((v.x-mean)*rstd*gg.x + bb.x);
        st.y = tf32f((v.y-mean)*rstd*gg.y + bb.y);
        *(float2*)&As[lr*68 + 2*lane] = st;
    }
    __syncthreads();

    int wy = warp >> 1, wx = warp & 1;
    float acc[2][8][4];
    #pragma unroll
    for (int mt = 0; mt < 2; ++mt)
        #pragma unroll
        for (int nt = 0; nt < 8; ++nt)
            #pragma unroll
            for (int r = 0; r < 4; ++r) acc[mt][nt][r] = 0.f;

    #pragma unroll
    for (int kc = 0; kc < 8; ++kc) {
        unsigned a[2][4];
        #pragma unroll
        for (int mt = 0; mt < 2; ++mt) {
            const float* ap = As + (wy*32 + mt*16 + gid)*68 + kc*8;
            a[mt][0] = __float_as_uint(ap[tig]);
            a[mt][1] = __float_as_uint(ap[8*68 + tig]);
            a[mt][2] = __float_as_uint(ap[tig + 4]);
            a[mt][3] = __float_as_uint(ap[8*68 + tig + 4]);
        }
        #pragma unroll
        for (int nt = 0; nt < 8; ++nt) {
            float2 bv = *(const float2*)&WF[((wx*8 + nt)*8 + kc)*64 + lane*2];
            mma_tf32(acc[0][nt], a[0], bv);
            mma_tf32(acc[1][nt], a[1], bv);
        }
    }

    #pragma unroll
    for (int mt = 0; mt < 2; ++mt)
        #pragma unroll
        for (int nt = 0; nt < 8; ++nt) {
            int col = cb*128 + (wx*8 + nt)*8 + tig*2;
            float2 fbv = *(const float2*)&fb1[col];
            int row = rowbase + wy*32 + mt*16 + gid;
            float2 o0 = make_float2(acc[mt][nt][0] + fbv.x, acc[mt][nt][1] + fbv.y);
            float2 o1 = make_float2(acc[mt][nt][2] + fbv.x, acc[mt][nt][3] + fbv.y);
            *(float2*)&g_f[(size_t)row*HID + col]      = o0;
            *(float2*)&g_f[(size_t)(row+8)*HID + col]  = o1;
        }
}

// =====================================================================
// K5: depthwise 3x3 SAME + GELU, smem-tiled rolling conv. (unchanged)
// =====================================================================
__global__ __launch_bounds__(256) void k5_dw_gelu(const float* __restrict__ dww)
{
    extern __shared__ float s5[];   // [6][128][32]
    int tid = threadIdx.x;
    int blk = blockIdx.x;
    int ct = blk & 7, ht = (blk >> 3) & 31, b = blk >> 8;
    int c0 = ct * 32, h0 = ht * 4;
    #pragma unroll
    for (int r = 0; r < 6; ++r) {
        int h = h0 - 1 + r;
        float4* dst = (float4*)(s5 + r*4096);
        if ((unsigned)h < 128u) {
            const float4* src = (const float4*)(g_f + ((size_t)b*NN + (size_t)h*WW)*HID + c0);
            for (int i = tid; i < 1024; i += 256) {
                int w = i >> 3, cq = i & 7;
                dst[i] = src[w*64 + cq];
            }
        } else {
            float4 z = make_float4(0.f,0.f,0.f,0.f);
            for (int i = tid; i < 1024; i += 256) dst[i] = z;
        }
    }
    __syncthreads();

    int cp = tid & 15, wi = tid >> 4;
    float2 wt[9];
    #pragma unroll
    for (int t = 0; t < 9; ++t)
        wt[t] = *(const float2*)&dww[t*HID + c0 + 2*cp];
    const int coff = 2*cp;

    #pragma unroll
    for (int ro = 0; ro < 4; ++ro) {
        const float* r0p = s5 + ro*4096 + coff;
        const float* r1p = r0p + 4096;
        const float* r2p = r1p + 4096;
        int w = wi * 8;
        float2 L0, L1, L2, C0, C1, C2;
        if (w == 0) {
            L0 = L1 = L2 = make_float2(0.f, 0.f);
        } else {
            L0 = *(const float2*)&r0p[(w-1)*32];
            L1 = *(const float2*)&r1p[(w-1)*32];
            L2 = *(const float2*)&r2p[(w-1)*32];
        }
        C0 = *(const float2*)&r0p[w*32];
        C1 = *(const float2*)&r1p[w*32];
        C2 = *(const float2*)&r2p[w*32];
        #pragma unroll
        for (int k = 0; k < 8; ++k) {
            float2 N0, N1, N2;
            if (w + 1 < 128) {
                N0 = *(const float2*)&r0p[(w+1)*32];
                N1 = *(const float2*)&r1p[(w+1)*32];
                N2 = *(const float2*)&r2p[(w+1)*32];
            } else {
                N0 = N1 = N2 = make_float2(0.f, 0.f);
            }
            float2 acc = make_float2(0.f, 0.f);
            acc = ffma2(L0, wt[0], acc); acc = ffma2(C0, wt[1], acc); acc = ffma2(N0, wt[2], acc);
            acc = ffma2(L1, wt[3], acc); acc = ffma2(C1, wt[4], acc); acc = ffma2(N1, wt[5], acc);
            acc = ffma2(L2, wt[6], acc); acc = ffma2(C2, wt[7], acc); acc = ffma2(N2, wt[8], acc);
            float2 o;
            o.x = acc.x * normcdff(acc.x);
            o.y = acc.y * normcdff(acc.y);
            *(float2*)&g_g[((size_t)b*NN + (size_t)(h0+ro)*WW + w)*HID + c0 + coff] = o;
            L0 = C0; L1 = C1; L2 = C2;
            C0 = N0; C1 = N1; C2 = N2;
            ++w;
        }
    }
}

// =====================================================================
// K6: fc2 (256->64) + residual via mma.sync tf32. grid 1024, block 256.
// (unchanged)
// =====================================================================
__global__ __launch_bounds__(256) void k6_fc2(
    const float* __restrict__ w2, const float* __restrict__ b2,
    float* __restrict__ out)
{
    extern __shared__ float sm6[];
    float* WF = sm6;             // [8 nt][32 kc][32 ln][2] = 16384
    float* As = sm6 + 16384;     // [128][68]
    int tid = threadIdx.x, warp = tid >> 5, lane = tid & 31;
    int gid = lane >> 2, tig = lane & 3;
    int rowbase = blockIdx.x * 128;

    for (int idx = tid; idx < 16384; idx += 256) {
        int nt = idx >> 11, kc = (idx >> 6) & 31, ln = (idx >> 1) & 31, j = idx & 1;
        int k = kc*8 + (ln & 3) + j*4;
        int col = nt*8 + (ln >> 2);
        WF[idx] = tf32f(w2[k*64 + col]);
    }

    float acc[8][4];
    #pragma unroll
    for (int nt = 0; nt < 8; ++nt)
        #pragma unroll
        for (int r = 0; r < 4; ++r) acc[nt][r] = 0.f;

    for (int kblk = 0; kblk < 4; ++kblk) {
        __syncthreads();
        for (int i = tid; i < 2048; i += 256) {
            int row = i >> 4, q = i & 15;
            float4 v = *(const float4*)&g_g[(size_t)(rowbase+row)*HID + kblk*64 + q*4];
            v.x = tf32f(v.x); v.y = tf32f(v.y); v.z = tf32f(v.z); v.w = tf32f(v.w);
            *(float4*)&As[row*68 + q*4] = v;
        }
        __syncthreads();
        #pragma unroll
        for (int kc = 0; kc < 8; ++kc) {
            unsigned a[4];
            const float* ap = As + (warp*16 + gid)*68 + kc*8;
            a[0] = __float_as_uint(ap[tig]);
            a[1] = __float_as_uint(ap[8*68 + tig]);
            a[2] = __float_as_uint(ap[tig + 4]);
            a[3] = __float_as_uint(ap[8*68 + tig + 4]);
            #pragma unroll
            for (int nt = 0; nt < 8; ++nt) {
                float2 bv = *(const float2*)&WF[(nt*32 + kblk*8 + kc)*64 + lane*2];
                mma_tf32(acc[nt], a, bv);
            }
        }
    }

    #pragma unroll
    for (int nt = 0; nt < 8; ++nt) {
        int col = nt*8 + tig*2;
        float2 bbv = *(const float2*)&b2[col];
        int row = rowbase + warp*16 + gid;
        float2 r0 = *(const float2*)&g_x2[(size_t)row*CC + col];
        float2 r1 = *(const float2*)&g_x2[(size_t)(row+8)*CC + col];
        float2 o0 = make_float2(r0.x + acc[nt][0] + bbv.x, r0.y + acc[nt][1] + bbv.y);
        float2 o1 = make_float2(r1.x + acc[nt][2] + bbv.x, r1.y + acc[nt][3] + bbv.y);
        *(float2*)&out[(size_t)row*CC + col]     = o0;
        *(float2*)&out[(size_t)(row+8)*CC + col] = o1;
    }
}

// =====================================================================
extern "C" void kernel_launch(void* const* d_in, const int* in_sizes, int n_in,
                              void* d_out, int out_size)
{
    const float* x     = (const float*)d_in[0];
    const float* ln1_g = (const float*)d_in[3];
    const float* ln1_b = (const float*)d_in[4];
    const float* q_w   = (const float*)d_in[5];
    const float* q_b   = (const float*)d_in[6];
    const float* kv_w  = (const float*)d_in[7];
    const float* kv_b  = (const float*)d_in[8];
    const float* pr_w  = (const float*)d_in[9];
    const float* pr_b  = (const float*)d_in[10];
    const float* sr_w  = (const float*)d_in[11];
    const float* sr_b  = (const float*)d_in[12];
    const float* srn_g = (const float*)d_in[13];
    const float* srn_b = (const float*)d_in[14];
    const float* ln2_g = (const float*)d_in[15];
    const float* ln2_b = (const float*)d_in[16];
    const float* fc1_w = (const float*)d_in[17];
    const float* fc1_b = (const float*)d_in[18];
    const float* dw_w  = (const float*)d_in[19];
    const float* fc2_w = (const float*)d_in[20];
    const float* fc2_b = (const float*)d_in[21];
    float* out = (float*)d_out;

    const int K1_SMEM = (4096 + 128*68) * 4;                    // 51200
    const int K2_SMEM = 8*4096*4;                               // 131072
    const int K3_SMEM = (16384 + 16384 + 4096 + 64*260 + 64*68) * 4;  // 231424
    const int K4_SMEM = (8192 + 128*68) * 4;                    // 67584
    const int K5_SMEM = 6*128*32*4;                             // 98304
    const int K6_SMEM = (16384 + 128*68) * 4;                   // 100352

    cudaFuncSetAttribute(k1_ln_q,   cudaFuncAttributeMaxDynamicSharedMemorySize, K1_SMEM);
    cudaFuncSetAttribute(k2_sr_kv,  cudaFuncAttributeMaxDynamicSharedMemorySize, K2_SMEM);
    cudaFuncSetAttribute(k3_attn,   cudaFuncAttributeMaxDynamicSharedMemorySize, K3_SMEM);
    cudaFuncSetAttribute(k4_ln_fc1, cudaFuncAttributeMaxDynamicSharedMemorySize, K4_SMEM);
    cudaFuncSetAttribute(k5_dw_gelu,cudaFuncAttributeMaxDynamicSharedMemorySize, K5_SMEM);
    cudaFuncSetAttribute(k6_fc2,    cudaFuncAttributeMaxDynamicSharedMemorySize, K6_SMEM);

    k1_ln_q  <<<1024, 256, K1_SMEM>>>(x, ln1_g, ln1_b, q_w, q_b);
    k2_sr_kv <<<256, 256, K2_SMEM>>>(sr_w, sr_b, srn_g, srn_b, kv_w, kv_b);
    k2b_pack <<<64, 256>>>(pr_w);
    k3_attn  <<<512, 256, K3_SMEM>>>(x, pr_b);
    k4_ln_fc1<<<2048, 256, K4_SMEM>>>(ln2_g, ln2_b, fc1_w, fc1_b);
    k5_dw_gelu<<<2048, 256, K5_SMEM>>>(dw_w);
    k6_fc2   <<<1024, 256, K6_SMEM>>>(fc2_w, fc2_b, out);
}

// round 9
// speedup vs baseline: 1.9606x; 1.0662x over previous
#include <cuda_runtime.h>
#include <cuda_bf16.h>
#include <math.h>

#define BB   8
#define HH   128
#define WW   128
#define NN   (HH*WW)          // 16384
#define CC   64
#define NR   256
#define HID  256
#define EPSV 1e-5f
#define QSCALE 0.125f

__device__ float g_h  [BB*NN*CC];
__device__ float g_q  [BB*NN*CC];
__device__ float g_k  [BB*NR*CC];
__device__ float g_v  [BB*NR*CC];
__device__ float g_x2 [BB*NN*CC];
__device__ __nv_bfloat16 g_f [(size_t)BB*NN*HID];   // fc1 out (bf16 storage)
__device__ __nv_bfloat16 g_g [(size_t)BB*NN*HID];   // dw+gelu out (bf16 storage)
// fragment-packed operands for k3
__device__ float g_kf [BB*16384];
__device__ float g_vf [BB*16384];
__device__ float g_pwf[4096];

__device__ __forceinline__ float2 ffma2(const float2 a, const float2 b, const float2 c) {
    float2 d;
    asm("fma.rn.f32x2 %0, %1, %2, %3;"
        : "=l"(reinterpret_cast<unsigned long long&>(d))
        : "l"(reinterpret_cast<const unsigned long long&>(a)),
          "l"(reinterpret_cast<const unsigned long long&>(b)),
          "l"(reinterpret_cast<const unsigned long long&>(c)));
    return d;
}
__device__ __forceinline__ float2 dup2(float s) { return make_float2(s, s); }

__device__ __forceinline__ float tf32f(float f) {
    unsigned u;
    asm("cvt.rna.tf32.f32 %0, %1;" : "=r"(u) : "f"(f));
    return __uint_as_float(u);
}

// mma.sync m16n8k8 tf32: D += A(16x8,row) * B(8x8,col)
__device__ __forceinline__ void mma_tf32(float* c, const unsigned* a, float2 b) {
    unsigned b0 = __float_as_uint(b.x), b1 = __float_as_uint(b.y);
    asm volatile("mma.sync.aligned.m16n8k8.row.col.f32.tf32.tf32.f32 "
        "{%0,%1,%2,%3}, {%4,%5,%6,%7}, {%8,%9}, {%0,%1,%2,%3};"
        : "+f"(c[0]), "+f"(c[1]), "+f"(c[2]), "+f"(c[3])
        : "r"(a[0]), "r"(a[1]), "r"(a[2]), "r"(a[3]), "r"(b0), "r"(b1));
}

// =====================================================================
// K1: LN1 (fp32 h out) + q-proj via tf32 mma. grid 1024, block 256.
// =====================================================================
__global__ __launch_bounds__(256) void k1_ln_q(
    const float* __restrict__ x, const float* __restrict__ g1,
    const float* __restrict__ b1, const float* __restrict__ qw,
    const float* __restrict__ qb)
{
    extern __shared__ float sm1[];
    float* WF = sm1;            // [8 nt][8 kc][32 ln][2]
    float* As = sm1 + 4096;     // [128][68]
    int tid = threadIdx.x, warp = tid >> 5, lane = tid & 31;
    int gid = lane >> 2, tig = lane & 3;
    int rowbase = blockIdx.x * 128;

    for (int idx = tid; idx < 4096; idx += 256) {
        int nt = idx >> 9, kc = (idx >> 6) & 7, ln = (idx >> 1) & 31, j = idx & 1;
        int k = kc*8 + (ln & 3) + j*4;
        int col = nt*8 + (ln >> 2);
        WF[idx] = tf32f(qw[k*64 + col]);
    }

    float2 gg = ((const float2*)g1)[lane];
    float2 bbv = ((const float2*)b1)[lane];
    #pragma unroll
    for (int i = 0; i < 16; ++i) {
        int lr = warp*16 + i;
        int row = rowbase + lr;
        float2 v = ((const float2*)x)[row*32 + lane];
        float s = v.x + v.y, ss = v.x*v.x + v.y*v.y;
        #pragma unroll
        for (int o = 16; o; o >>= 1) {
            s  += __shfl_xor_sync(0xffffffffu, s,  o);
            ss += __shfl_xor_sync(0xffffffffu, ss, o);
        }
        float mean = s * (1.f/64.f);
        float rstd = rsqrtf(ss*(1.f/64.f) - mean*mean + EPSV);
        float2 hv;
        hv.x = (v.x - mean)*rstd*gg.x + bbv.x;
        hv.y = (v.y - mean)*rstd*gg.y + bbv.y;
        ((float2*)g_h)[row*32 + lane] = hv;
        float2 st = make_float2(tf32f(hv.x), tf32f(hv.y));
        *(float2*)&As[lr*68 + 2*lane] = st;
    }
    __syncthreads();

    float acc[8][4];
    #pragma unroll
    for (int nt = 0; nt < 8; ++nt)
        #pragma unroll
        for (int r = 0; r < 4; ++r) acc[nt][r] = 0.f;
    #pragma unroll
    for (int kc = 0; kc < 8; ++kc) {
        unsigned a[4];
        const float* ap = As + (warp*16 + gid)*68 + kc*8;
        a[0] = __float_as_uint(ap[tig]);
        a[1] = __float_as_uint(ap[8*68 + tig]);
        a[2] = __float_as_uint(ap[tig + 4]);
        a[3] = __float_as_uint(ap[8*68 + tig + 4]);
        #pragma unroll
        for (int nt = 0; nt < 8; ++nt) {
            float2 bv = *(const float2*)&WF[(nt*8 + kc)*64 + lane*2];
            mma_tf32(acc[nt], a, bv);
        }
    }

    #pragma unroll
    for (int nt = 0; nt < 8; ++nt) {
        int col = nt*8 + tig*2;
        float2 qbv = *(const float2*)&qb[col];
        int row = rowbase + warp*16 + gid;
        float2 o0 = make_float2((acc[nt][0] + qbv.x)*QSCALE, (acc[nt][1] + qbv.y)*QSCALE);
        float2 o1 = make_float2((acc[nt][2] + qbv.x)*QSCALE, (acc[nt][3] + qbv.y)*QSCALE);
        *(float2*)&g_q[(size_t)row*64 + col]     = o0;
        *(float2*)&g_q[(size_t)(row+8)*64 + col] = o1;
    }
}

// =====================================================================
// K2: sr conv (8x8/s8) + LN + kv proj. grid 256, block 256. smem 128 KB.
// =====================================================================
__global__ __launch_bounds__(256) void k2_sr_kv(
    const float* __restrict__ srw, const float* __restrict__ srb,
    const float* __restrict__ sng, const float* __restrict__ snb,
    const float* __restrict__ kvw, const float* __restrict__ kvb)
{
    extern __shared__ float sm[];   // 8 patches x 4096
    int tid = threadIdx.x;
    int basepos = blockIdx.x * 8;
    int b   = basepos >> 8;
    int rem = basepos & 255;
    int oh  = rem >> 4, ow0 = rem & 15;

    for (int r = 0; r < 8; ++r) {
        size_t base4 = (((size_t)b*NN + (size_t)(oh*8)*WW + (size_t)(ow0+r)*8) * CC) >> 2;
        const float4* src = (const float4*)g_h;
        float4* dst = (float4*)(sm + r*4096);
        for (int k4 = tid; k4 < 1024; k4 += 256) {
            int i = k4 >> 7, rk = k4 & 127;
            dst[k4] = src[base4 + (size_t)i*2048 + rk];
        }
    }
    __syncthreads();

    int cp = tid & 31, r = tid >> 5;
    float2 a0 = make_float2(0.f,0.f), a1 = make_float2(0.f,0.f);
    float2 a2 = make_float2(0.f,0.f), a3 = make_float2(0.f,0.f);
    const float2* srw2 = (const float2*)srw;
    const float* ap = sm + r*4096;
    #pragma unroll 4
    for (int t = 0; t < 4096; t += 4) {
        a0 = ffma2(dup2(ap[t]),   srw2[(t)*32 + cp],   a0);
        a1 = ffma2(dup2(ap[t+1]), srw2[(t+1)*32 + cp], a1);
        a2 = ffma2(dup2(ap[t+2]), srw2[(t+2)*32 + cp], a2);
        a3 = ffma2(dup2(ap[t+3]), srw2[(t+3)*32 + cp], a3);
    }
    float2 acc = make_float2(a0.x+a1.x+a2.x+a3.x, a0.y+a1.y+a2.y+a3.y);
    __syncthreads();
    float* xr = sm;
    float2 sbp = ((const float2*)srb)[cp];
    acc.x += sbp.x; acc.y += sbp.y;
    ((float2*)xr)[r*32 + cp] = acc;
    __syncthreads();

    int warp = tid >> 5, lane = tid & 31;
    {
        float2 sg  = ((const float2*)sng)[lane];
        float2 sbb = ((const float2*)snb)[lane];
        float2 v = ((float2*)xr)[warp*32 + lane];
        float s = v.x + v.y, ss = v.x*v.x + v.y*v.y;
        #pragma unroll
        for (int o = 16; o; o >>= 1) {
            s  += __shfl_xor_sync(0xffffffffu, s,  o);
            ss += __shfl_xor_sync(0xffffffffu, ss, o);
        }
        float mean = s*(1.f/64.f);
        float rstd = rsqrtf(ss*(1.f/64.f) - mean*mean + EPSV);
        float2 nv;
        nv.x = (v.x-mean)*rstd*sg.x + sbb.x;
        nv.y = (v.y-mean)*rstd*sg.y + sbb.y;
        ((float2*)xr)[warp*32 + lane] = nv;
    }
    __syncthreads();

    int ch = tid & 127, rh = tid >> 7;
    float ak[4];
    float kb = kvb[ch];
    #pragma unroll
    for (int rr = 0; rr < 4; ++rr) ak[rr] = kb;
    #pragma unroll 4
    for (int j = 0; j < 64; ++j) {
        float w = kvw[j*128 + ch];
        #pragma unroll
        for (int rr = 0; rr < 4; ++rr) ak[rr] += xr[(rh*4+rr)*64 + j] * w;
    }
    #pragma unroll
    for (int rr = 0; rr < 4; ++rr) {
        int pos = basepos + rh*4 + rr;
        if (ch < 64) g_k[pos*64 + ch]      = ak[rr];
        else         g_v[pos*64 + ch - 64] = ak[rr];
    }
}

// =====================================================================
// K2b: repack K, V, proj_w into mma B-fragment order. grid 64, block 256.
// =====================================================================
__global__ __launch_bounds__(256) void k2b_pack(const float* __restrict__ pw)
{
    int t = blockIdx.x*256 + threadIdx.x;   // 0..16383
    {   // KF: [nt32][kc8][ln32][2]
        int j = t & 1, ln = (t>>1)&31, kc = (t>>6)&7, nt = t>>9;
        int key = nt*8 + (ln>>2), d = kc*8 + (ln&3) + 4*j;
        #pragma unroll
        for (int b = 0; b < 8; ++b)
            g_kf[b*16384 + t] = g_k[(b*256+key)*64 + d];
    }
    {   // VF: [nt8][kc32][ln32][2]
        int j = t & 1, ln = (t>>1)&31, kc = (t>>6)&31, nt = t>>11;
        int key = kc*8 + (ln&3) + 4*j, col = nt*8 + (ln>>2);
        #pragma unroll
        for (int b = 0; b < 8; ++b)
            g_vf[b*16384 + t] = g_v[(b*256+key)*64 + col];
    }
    if (t < 4096) {  // PWF: [nt8][kc8][ln32][2]
        int j = t & 1, ln = (t>>1)&31, kc = (t>>6)&7, nt = t>>9;
        int k = kc*8 + (ln&3) + 4*j, col = nt*8 + (ln>>2);
        g_pwf[t] = pw[k*64 + col];
    }
}

// =====================================================================
// K3: attention via tf32 mma, 4 query-tiles per block.
// grid 512 (8 b x 64 groups), block 512 (16 warps).
// warp tiles: QK m16n64 (wy=warp>>2, wx=warp&3), PV/proj m16n16.
// smem floats: KF 16384 | VF 16384 | WF 4096 | S 64*260 | Qs 64*68
// =====================================================================
__global__ __launch_bounds__(512) void k3_attn(
    const float* __restrict__ x, const float* __restrict__ pb)
{
    extern __shared__ float sm3[];
    float* KF = sm3;                  // 16384
    float* VF = sm3 + 16384;          // 16384
    float* WF = sm3 + 32768;          // 4096
    float* S  = sm3 + 36864;          // [64][260]
    float* Qs = sm3 + 36864 + 16640;  // [64][68], reused as Os

    int tid = threadIdx.x, warp = tid >> 5, lane = tid & 31;
    int gid = lane >> 2, tig = lane & 3;
    int b = blockIdx.x >> 6, grp = blockIdx.x & 63;
    float* Os = Qs;

    // ---- stage KF, VF, WF once ----
    {
        const float4* kf4 = (const float4*)(g_kf + b*16384);
        const float4* vf4 = (const float4*)(g_vf + b*16384);
        float4* KF4 = (float4*)KF;
        float4* VF4 = (float4*)VF;
        #pragma unroll 4
        for (int i = tid; i < 4096; i += 512) { KF4[i] = kf4[i]; VF4[i] = vf4[i]; }
        const float4* w4 = (const float4*)g_pwf;
        float4* WF4 = (float4*)WF;
        #pragma unroll
        for (int i = tid; i < 1024; i += 512) WF4[i] = w4[i];
    }

    int wy = warp >> 2, wx = warp & 3;

    for (int it = 0; it < 4; ++it) {
        int q0 = (grp*4 + it) * 64;
        __syncthreads();
        // ---- stage Q tile ----
        {
            const float4* q4 = (const float4*)(g_q + ((size_t)b*NN + q0)*64);
            #pragma unroll
            for (int i = tid; i < 1024; i += 512) {
                int r = i >> 4, c = i & 15;
                *(float4*)&Qs[r*68 + c*4] = q4[i];
            }
        }
        __syncthreads();

        // ---- QK: warp tile m16 x n64 ----
        {
            float acc[8][4];
            #pragma unroll
            for (int nt = 0; nt < 8; ++nt)
                #pragma unroll
                for (int r = 0; r < 4; ++r) acc[nt][r] = 0.f;
            #pragma unroll
            for (int kc = 0; kc < 8; ++kc) {
                unsigned a[4];
                const float* ap = Qs + (wy*16 + gid)*68 + kc*8;
                a[0] = __float_as_uint(ap[tig]);
                a[1] = __float_as_uint(ap[8*68 + tig]);
                a[2] = __float_as_uint(ap[tig + 4]);
                a[3] = __float_as_uint(ap[8*68 + tig + 4]);
                #pragma unroll
                for (int nt = 0; nt < 8; ++nt) {
                    float2 bv = *(const float2*)&KF[((wx*8 + nt)*8 + kc)*64 + lane*2];
                    mma_tf32(acc[nt], a, bv);
                }
            }
            int r0 = wy*16 + gid;
            #pragma unroll
            for (int nt = 0; nt < 8; ++nt) {
                int cb = wx*64 + nt*8 + tig*2;
                *(float2*)&S[r0*260 + cb]     = make_float2(acc[nt][0], acc[nt][1]);
                *(float2*)&S[(r0+8)*260 + cb] = make_float2(acc[nt][2], acc[nt][3]);
            }
        }
        __syncthreads();

        // ---- softmax over 256 cols (warp per 4 rows) ----
        {
            float4* S4 = (float4*)S;       // row stride 65 float4
            #pragma unroll
            for (int i = 0; i < 4; ++i) {
                int r = warp*4 + i;
                float4 v0 = S4[r*65 + lane*2];
                float4 v1 = S4[r*65 + lane*2 + 1];
                float mx = fmaxf(fmaxf(fmaxf(v0.x, v0.y), fmaxf(v0.z, v0.w)),
                                 fmaxf(fmaxf(v1.x, v1.y), fmaxf(v1.z, v1.w)));
                #pragma unroll
                for (int o = 16; o; o >>= 1) mx = fmaxf(mx, __shfl_xor_sync(0xffffffffu, mx, o));
                v0.x = __expf(v0.x - mx); v0.y = __expf(v0.y - mx);
                v0.z = __expf(v0.z - mx); v0.w = __expf(v0.w - mx);
                v1.x = __expf(v1.x - mx); v1.y = __expf(v1.y - mx);
                v1.z = __expf(v1.z - mx); v1.w = __expf(v1.w - mx);
                float sum = v0.x + v0.y + v0.z + v0.w + v1.x + v1.y + v1.z + v1.w;
                #pragma unroll
                for (int o = 16; o; o >>= 1) sum += __shfl_xor_sync(0xffffffffu, sum, o);
                float inv = __frcp_rn(sum);
                v0.x *= inv; v0.y *= inv; v0.z *= inv; v0.w *= inv;
                v1.x *= inv; v1.y *= inv; v1.z *= inv; v1.w *= inv;
                S4[r*65 + lane*2]     = v0;
                S4[r*65 + lane*2 + 1] = v1;
            }
        }
        __syncthreads();

        // ---- PV: warp tile m16 x n16, K=256 ----
        float accO[2][4];
        #pragma unroll
        for (int nt = 0; nt < 2; ++nt)
            #pragma unroll
            for (int r = 0; r < 4; ++r) accO[nt][r] = 0.f;
        #pragma unroll 4
        for (int kc = 0; kc < 32; ++kc) {
            unsigned a[4];
            const float* ap = S + (wy*16 + gid)*260 + kc*8;
            a[0] = __float_as_uint(ap[tig]);
            a[1] = __float_as_uint(ap[8*260 + tig]);
            a[2] = __float_as_uint(ap[tig + 4]);
            a[3] = __float_as_uint(ap[8*260 + tig + 4]);
            #pragma unroll
            for (int nt = 0; nt < 2; ++nt) {
                float2 bv = *(const float2*)&VF[((wx*2 + nt)*32 + kc)*64 + lane*2];
                mma_tf32(accO[nt], a, bv);
            }
        }
        __syncthreads();
        {
            int r0 = wy*16 + gid;
            #pragma unroll
            for (int nt = 0; nt < 2; ++nt) {
                int cb = wx*16 + nt*8 + tig*2;
                *(float2*)&Os[r0*68 + cb]     = make_float2(accO[nt][0], accO[nt][1]);
                *(float2*)&Os[(r0+8)*68 + cb] = make_float2(accO[nt][2], accO[nt][3]);
            }
        }
        __syncthreads();

        // ---- proj: warp tile m16 x n16, K=64 ----
        float accP[2][4];
        #pragma unroll
        for (int nt = 0; nt < 2; ++nt)
            #pragma unroll
            for (int r = 0; r < 4; ++r) accP[nt][r] = 0.f;
        #pragma unroll
        for (int kc = 0; kc < 8; ++kc) {
            unsigned a[4];
            const float* ap = Os + (wy*16 + gid)*68 + kc*8;
            a[0] = __float_as_uint(ap[tig]);
            a[1] = __float_as_uint(ap[8*68 + tig]);
            a[2] = __float_as_uint(ap[tig + 4]);
            a[3] = __float_as_uint(ap[8*68 + tig + 4]);
            #pragma unroll
            for (int nt = 0; nt < 2; ++nt) {
                float2 bv = *(const float2*)&WF[((wx*2 + nt)*8 + kc)*64 + lane*2];
                mma_tf32(accP[nt], a, bv);
            }
        }

        // ---- epilogue: residual + bias ----
        #pragma unroll
        for (int nt = 0; nt < 2; ++nt) {
            int col = wx*16 + nt*8 + tig*2;
            float2 pbv = *(const float2*)&pb[col];
            size_t rowA = (size_t)b*NN + q0 + wy*16 + gid;
            size_t rowB = rowA + 8;
            float2 xa = *(const float2*)&x[rowA*64 + col];
            float2 xb = *(const float2*)&x[rowB*64 + col];
            float2 oa = make_float2(xa.x + accP[nt][0] + pbv.x, xa.y + accP[nt][1] + pbv.y);
            float2 ob = make_float2(xb.x + accP[nt][2] + pbv.x, xb.y + accP[nt][3] + pbv.y);
            *(float2*)&g_x2[rowA*64 + col] = oa;
            *(float2*)&g_x2[rowB*64 + col] = ob;
        }
    }
}

// =====================================================================
// K4: LN2 + fc1 via tf32 mma, bf16 output. grid 2048, block 256.
// =====================================================================
__global__ __launch_bounds__(256) void k4_ln_fc1(
    const float* __restrict__ g2, const float* __restrict__ b2,
    const float* __restrict__ w1, const float* __restrict__ fb1)
{
    extern __shared__ float sm4[];
    float* WF = sm4;            // [16 nt][8 kc][32 ln][2]
    float* As = sm4 + 8192;     // [128][68]
    int tid = threadIdx.x, warp = tid >> 5, lane = tid & 31;
    int gid = lane >> 2, tig = lane & 3;
    int cb = blockIdx.x & 1;
    int rowbase = (blockIdx.x >> 1) * 128;

    for (int idx = tid; idx < 8192; idx += 256) {
        int nt = idx >> 9, kc = (idx >> 6) & 7, ln = (idx >> 1) & 31, j = idx & 1;
        int k = kc*8 + (ln & 3) + j*4;
        int col = cb*128 + nt*8 + (ln >> 2);
        WF[idx] = tf32f(w1[k*256 + col]);
    }

    float2 gg = ((const float2*)g2)[lane];
    float2 bb = ((const float2*)b2)[lane];
    #pragma unroll
    for (int i = 0; i < 16; ++i) {
        int lr = warp*16 + i;
        int row = rowbase + lr;
        float2 v = ((const float2*)g_x2)[row*32 + lane];
        float s = v.x + v.y, ss = v.x*v.x + v.y*v.y;
        #pragma unroll
        for (int o = 16; o; o >>= 1) {
            s  += __shfl_xor_sync(0xffffffffu, s,  o);
            ss += __shfl_xor_sync(0xffffffffu, ss, o);
        }
        float mean = s*(1.f/64.f);
        float rstd = rsqrtf(ss*(1.f/64.f) - mean*mean + EPSV);
        float2 st;
        st.x = tf32f((v.x-mean)*rstd*gg.x + bb.x);
        st.y = tf32f((v.y-mean)*rstd*gg.y + bb.y);
        *(float2*)&As[lr*68 + 2*lane] = st;
    }
    __syncthreads();

    int wy = warp >> 1, wx = warp & 1;
    float acc[2][8][4];
    #pragma unroll
    for (int mt = 0; mt < 2; ++mt)
        #pragma unroll
        for (int nt = 0; nt < 8; ++nt)
            #pragma unroll
            for (int r = 0; r < 4; ++r) acc[mt][nt][r] = 0.f;

    #pragma unroll
    for (int kc = 0; kc < 8; ++kc) {
        unsigned a[2][4];
        #pragma unroll
        for (int mt = 0; mt < 2; ++mt) {
            const float* ap = As + (wy*32 + mt*16 + gid)*68 + kc*8;
            a[mt][0] = __float_as_uint(ap[tig]);
            a[mt][1] = __float_as_uint(ap[8*68 + tig]);
            a[mt][2] = __float_as_uint(ap[tig + 4]);
            a[mt][3] = __float_as_uint(ap[8*68 + tig + 4]);
        }
        #pragma unroll
        for (int nt = 0; nt < 8; ++nt) {
            float2 bv = *(const float2*)&WF[((wx*8 + nt)*8 + kc)*64 + lane*2];
            mma_tf32(acc[0][nt], a[0], bv);
            mma_tf32(acc[1][nt], a[1], bv);
        }
    }

    #pragma unroll
    for (int mt = 0; mt < 2; ++mt)
        #pragma unroll
        for (int nt = 0; nt < 8; ++nt) {
            int col = cb*128 + (wx*8 + nt)*8 + tig*2;
            float2 fbv = *(const float2*)&fb1[col];
            int row = rowbase + wy*32 + mt*16 + gid;
            float2 o0 = make_float2(acc[mt][nt][0] + fbv.x, acc[mt][nt][1] + fbv.y);
            float2 o1 = make_float2(acc[mt][nt][2] + fbv.x, acc[mt][nt][3] + fbv.y);
            *(__nv_bfloat162*)&g_f[(size_t)row*HID + col]     = __float22bfloat162_rn(o0);
            *(__nv_bfloat162*)&g_f[(size_t)(row+8)*HID + col] = __float22bfloat162_rn(o1);
        }
}

// =====================================================================
// K5: depthwise 3x3 SAME + GELU, bf16 in/out, smem-tiled rolling conv.
// grid 2048, block 256. smem 6*128*32*2 = 49152 B.
// =====================================================================
__global__ __launch_bounds__(256) void k5_dw_gelu(const float* __restrict__ dww)
{
    extern __shared__ __nv_bfloat16 s5b[];   // [6][128][32] bf16
    int tid = threadIdx.x;
    int blk = blockIdx.x;
    int ct = blk & 7, ht = (blk >> 3) & 31, b = blk >> 8;
    int c0 = ct * 32, h0 = ht * 4;
    #pragma unroll
    for (int r = 0; r < 6; ++r) {
        int h = h0 - 1 + r;
        uint4* dst = (uint4*)(s5b + r*4096);       // 512 x uint4 (8 bf16 each)
        if ((unsigned)h < 128u) {
            const uint4* src = (const uint4*)(g_f + ((size_t)b*NN + (size_t)h*WW)*HID + c0);
            // pixel stride = 256 bf16 = 32 uint4; take 4 uint4 (32 bf16) per pixel
            for (int i = tid; i < 512; i += 256) {
                int px = i >> 2, q = i & 3;
                dst[i] = src[px*32 + q];
            }
        } else {
            uint4 z = make_uint4(0u,0u,0u,0u);
            for (int i = tid; i < 512; i += 256) dst[i] = z;
        }
    }
    __syncthreads();

    int cp = tid & 15, wi = tid >> 4;
    float2 wt[9];
    #pragma unroll
    for (int t = 0; t < 9; ++t)
        wt[t] = *(const float2*)&dww[t*HID + c0 + 2*cp];

    const __nv_bfloat162* s5p = (const __nv_bfloat162*)s5b;  // pair units; row = 2048 pairs

    #pragma unroll
    for (int ro = 0; ro < 4; ++ro) {
        const __nv_bfloat162* r0p = s5p + ro*2048 + cp;
        const __nv_bfloat162* r1p = r0p + 2048;
        const __nv_bfloat162* r2p = r1p + 2048;
        int w = wi * 8;
        float2 L0, L1, L2, C0, C1, C2;
        if (w == 0) {
            L0 = L1 = L2 = make_float2(0.f, 0.f);
        } else {
            L0 = __bfloat1622float2(r0p[(w-1)*16]);
            L1 = __bfloat1622float2(r1p[(w-1)*16]);
            L2 = __bfloat1622float2(r2p[(w-1)*16]);
        }
        C0 = __bfloat1622float2(r0p[w*16]);
        C1 = __bfloat1622float2(r1p[w*16]);
        C2 = __bfloat1622float2(r2p[w*16]);
        #pragma unroll
        for (int k = 0; k < 8; ++k) {
            float2 N0, N1, N2;
            if (w + 1 < 128) {
                N0 = __bfloat1622float2(r0p[(w+1)*16]);
                N1 = __bfloat1622float2(r1p[(w+1)*16]);
                N2 = __bfloat1622float2(r2p[(w+1)*16]);
            } else {
                N0 = N1 = N2 = make_float2(0.f, 0.f);
            }
            float2 acc = make_float2(0.f, 0.f);
            acc = ffma2(L0, wt[0], acc); acc = ffma2(C0, wt[1], acc); acc = ffma2(N0, wt[2], acc);
            acc = ffma2(L1, wt[3], acc); acc = ffma2(C1, wt[4], acc); acc = ffma2(N1, wt[5], acc);
            acc = ffma2(L2, wt[6], acc); acc = ffma2(C2, wt[7], acc); acc = ffma2(N2, wt[8], acc);
            float2 o;
            o.x = acc.x * normcdff(acc.x);
            o.y = acc.y * normcdff(acc.y);
            *(__nv_bfloat162*)&g_g[((size_t)b*NN + (size_t)(h0+ro)*WW + w)*HID + c0 + 2*cp] =
                __float22bfloat162_rn(o);
            L0 = C0; L1 = C1; L2 = C2;
            C0 = N0; C1 = N1; C2 = N2;
            ++w;
        }
    }
}

// =====================================================================
// K6: fc2 (256->64) + residual via tf32 mma, bf16 A input. grid 1024, block 256.
// =====================================================================
__global__ __launch_bounds__(256) void k6_fc2(
    const float* __restrict__ w2, const float* __restrict__ b2,
    float* __restrict__ out)
{
    extern __shared__ float sm6[];
    float* WF = sm6;             // [8 nt][32 kc][32 ln][2] = 16384
    float* As = sm6 + 16384;     // [128][68]
    int tid = threadIdx.x, warp = tid >> 5, lane = tid & 31;
    int gid = lane >> 2, tig = lane & 3;
    int rowbase = blockIdx.x * 128;

    for (int idx = tid; idx < 16384; idx += 256) {
        int nt = idx >> 11, kc = (idx >> 6) & 31, ln = (idx >> 1) & 31, j = idx & 1;
        int k = kc*8 + (ln & 3) + j*4;
        int col = nt*8 + (ln >> 2);
        WF[idx] = tf32f(w2[k*64 + col]);
    }

    float acc[8][4];
    #pragma unroll
    for (int nt = 0; nt < 8; ++nt)
        #pragma unroll
        for (int r = 0; r < 4; ++r) acc[nt][r] = 0.f;

    for (int kblk = 0; kblk < 4; ++kblk) {
        __syncthreads();
        // stage 128 rows x 64 bf16 cols -> fp32 (bf16 subset of tf32, exact)
        for (int i = tid; i < 1024; i += 256) {
            int row = i >> 3, q = i & 7;
            uint4 u = *(const uint4*)&g_g[(size_t)(rowbase+row)*HID + kblk*64 + q*8];
            float2 f0 = __bfloat1622float2(*(__nv_bfloat162*)&u.x);
            float2 f1 = __bfloat1622float2(*(__nv_bfloat162*)&u.y);
            float2 f2 = __bfloat1622float2(*(__nv_bfloat162*)&u.z);
            float2 f3 = __bfloat1622float2(*(__nv_bfloat162*)&u.w);
            float* dp = &As[row*68 + q*8];
            dp[0] = f0.x; dp[1] = f0.y; dp[2] = f1.x; dp[3] = f1.y;
            dp[4] = f2.x; dp[5] = f2.y; dp[6] = f3.x; dp[7] = f3.y;
        }
        __syncthreads();
        #pragma unroll
        for (int kc = 0; kc < 8; ++kc) {
            unsigned a[4];
            const float* ap = As + (warp*16 + gid)*68 + kc*8;
            a[0] = __float_as_uint(ap[tig]);
            a[1] = __float_as_uint(ap[8*68 + tig]);
            a[2] = __float_as_uint(ap[tig + 4]);
            a[3] = __float_as_uint(ap[8*68 + tig + 4]);
            #pragma unroll
            for (int nt = 0; nt < 8; ++nt) {
                float2 bv = *(const float2*)&WF[(nt*32 + kblk*8 + kc)*64 + lane*2];
                mma_tf32(acc[nt], a, bv);
            }
        }
    }

    #pragma unroll
    for (int nt = 0; nt < 8; ++nt) {
        int col = nt*8 + tig*2;
        float2 bbv = *(const float2*)&b2[col];
        int row = rowbase + warp*16 + gid;
        float2 r0 = *(const float2*)&g_x2[(size_t)row*CC + col];
        float2 r1 = *(const float2*)&g_x2[(size_t)(row+8)*CC + col];
        float2 o0 = make_float2(r0.x + acc[nt][0] + bbv.x, r0.y + acc[nt][1] + bbv.y);
        float2 o1 = make_float2(r1.x + acc[nt][2] + bbv.x, r1.y + acc[nt][3] + bbv.y);
        *(float2*)&out[(size_t)row*CC + col]     = o0;
        *(float2*)&out[(size_t)(row+8)*CC + col] = o1;
    }
}

// =====================================================================
extern "C" void kernel_launch(void* const* d_in, const int* in_sizes, int n_in,
                              void* d_out, int out_size)
{
    const float* x     = (const float*)d_in[0];
    const float* ln1_g = (const float*)d_in[3];
    const float* ln1_b = (const float*)d_in[4];
    const float* q_w   = (const float*)d_in[5];
    const float* q_b   = (const float*)d_in[6];
    const float* kv_w  = (const float*)d_in[7];
    const float* kv_b  = (const float*)d_in[8];
    const float* pr_w  = (const float*)d_in[9];
    const float* pr_b  = (const float*)d_in[10];
    const float* sr_w  = (const float*)d_in[11];
    const float* sr_b  = (const float*)d_in[12];
    const float* srn_g = (const float*)d_in[13];
    const float* srn_b = (const float*)d_in[14];
    const float* ln2_g = (const float*)d_in[15];
    const float* ln2_b = (const float*)d_in[16];
    const float* fc1_w = (const float*)d_in[17];
    const float* fc1_b = (const float*)d_in[18];
    const float* dw_w  = (const float*)d_in[19];
    const float* fc2_w = (const float*)d_in[20];
    const float* fc2_b = (const float*)d_in[21];
    float* out = (float*)d_out;

    const int K1_SMEM = (4096 + 128*68) * 4;                    // 51200
    const int K2_SMEM = 8*4096*4;                               // 131072
    const int K3_SMEM = (16384 + 16384 + 4096 + 64*260 + 64*68) * 4;  // 231424
    const int K4_SMEM = (8192 + 128*68) * 4;                    // 67584
    const int K5_SMEM = 6*128*32*2;                             // 49152
    const int K6_SMEM = (16384 + 128*68) * 4;                   // 100352

    cudaFuncSetAttribute(k1_ln_q,   cudaFuncAttributeMaxDynamicSharedMemorySize, K1_SMEM);
    cudaFuncSetAttribute(k2_sr_kv,  cudaFuncAttributeMaxDynamicSharedMemorySize, K2_SMEM);
    cudaFuncSetAttribute(k3_attn,   cudaFuncAttributeMaxDynamicSharedMemorySize, K3_SMEM);
    cudaFuncSetAttribute(k4_ln_fc1, cudaFuncAttributeMaxDynamicSharedMemorySize, K4_SMEM);
    cudaFuncSetAttribute(k5_dw_gelu,cudaFuncAttributeMaxDynamicSharedMemorySize, K5_SMEM);
    cudaFuncSetAttribute(k6_fc2,    cudaFuncAttributeMaxDynamicSharedMemorySize, K6_SMEM);

    k1_ln_q  <<<1024, 256, K1_SMEM>>>(x, ln1_g, ln1_b, q_w, q_b);
    k2_sr_kv <<<256, 256, K2_SMEM>>>(sr_w, sr_b, srn_g, srn_b, kv_w, kv_b);
    k2b_pack <<<64, 256>>>(pr_w);
    k3_attn  <<<512, 512, K3_SMEM>>>(x, pr_b);
    k4_ln_fc1<<<2048, 256, K4_SMEM>>>(ln2_g, ln2_b, fc1_w, fc1_b);
    k5_dw_gelu<<<2048, 256, K5_SMEM>>>(dw_w);
    k6_fc2   <<<1024, 256, K6_SMEM>>>(fc2_w, fc2_b, out);
}

// round 14
// speedup vs baseline: 2.9257x; 1.4922x over previous
#include <cuda_runtime.h>
#include <cuda_bf16.h>
#include <math.h>

#define BB   8
#define HH   128
#define WW   128
#define NN   (HH*WW)          // 16384
#define CC   64
#define NR   256
#define HID  256
#define EPSV 1e-5f
#define QSCALE 0.125f

__device__ float g_h  [BB*NN*CC];
__device__ float g_q  [BB*NN*CC];
__device__ float g_k  [BB*NR*CC];
__device__ float g_v  [BB*NR*CC];
__device__ float g_x2 [BB*NN*CC];
__device__ __nv_bfloat16 g_f [(size_t)BB*NN*HID];   // fc1 out (bf16 storage)
__device__ __nv_bfloat16 g_g [(size_t)BB*NN*HID];   // dw+gelu out (bf16 storage)
// fragment-packed operands
__device__ float g_kf [BB*16384];
__device__ float g_vf [BB*16384];
__device__ float g_pwf[4096];
__device__ float g_srwfT[262144];                   // sr_w tf32 B-fragments (1 MB)

__device__ __forceinline__ float2 ffma2(const float2 a, const float2 b, const float2 c) {
    float2 d;
    asm("fma.rn.f32x2 %0, %1, %2, %3;"
        : "=l"(reinterpret_cast<unsigned long long&>(d))
        : "l"(reinterpret_cast<const unsigned long long&>(a)),
          "l"(reinterpret_cast<const unsigned long long&>(b)),
          "l"(reinterpret_cast<const unsigned long long&>(c)));
    return d;
}
__device__ __forceinline__ float2 dup2(float s) { return make_float2(s, s); }

__device__ __forceinline__ float tf32f(float f) {
    unsigned u;
    asm("cvt.rna.tf32.f32 %0, %1;" : "=r"(u) : "f"(f));
    return __uint_as_float(u);
}

// mma.sync m16n8k8 tf32
__device__ __forceinline__ void mma_tf32(float* c, const unsigned* a, float2 b) {
    unsigned b0 = __float_as_uint(b.x), b1 = __float_as_uint(b.y);
    asm volatile("mma.sync.aligned.m16n8k8.row.col.f32.tf32.tf32.f32 "
        "{%0,%1,%2,%3}, {%4,%5,%6,%7}, {%8,%9}, {%0,%1,%2,%3};"
        : "+f"(c[0]), "+f"(c[1]), "+f"(c[2]), "+f"(c[3])
        : "r"(a[0]), "r"(a[1]), "r"(a[2]), "r"(a[3]), "r"(b0), "r"(b1));
}

// =====================================================================
// K1: LN1 (fp32 h out) + q-proj via tf32 mma. grid 1024, block 256.
// =====================================================================
__global__ __launch_bounds__(256) void k1_ln_q(
    const float* __restrict__ x, const float* __restrict__ g1,
    const float* __restrict__ b1, const float* __restrict__ qw,
    const float* __restrict__ qb)
{
    extern __shared__ float sm1[];
    float* WF = sm1;            // [8 nt][8 kc][32 ln][2]
    float* As = sm1 + 4096;     // [128][68]
    int tid = threadIdx.x, warp = tid >> 5, lane = tid & 31;
    int gid = lane >> 2, tig = lane & 3;
    int rowbase = blockIdx.x * 128;

    for (int idx = tid; idx < 4096; idx += 256) {
        int nt = idx >> 9, kc = (idx >> 6) & 7, ln = (idx >> 1) & 31, j = idx & 1;
        int k = kc*8 + (ln & 3) + j*4;
        int col = nt*8 + (ln >> 2);
        WF[idx] = tf32f(qw[k*64 + col]);
    }

    float2 gg = ((const float2*)g1)[lane];
    float2 bbv = ((const float2*)b1)[lane];
    #pragma unroll
    for (int i = 0; i < 16; ++i) {
        int lr = warp*16 + i;
        int row = rowbase + lr;
        float2 v = ((const float2*)x)[row*32 + lane];
        float s = v.x + v.y, ss = v.x*v.x + v.y*v.y;
        #pragma unroll
        for (int o = 16; o; o >>= 1) {
            s  += __shfl_xor_sync(0xffffffffu, s,  o);
            ss += __shfl_xor_sync(0xffffffffu, ss, o);
        }
        float mean = s * (1.f/64.f);
        float rstd = rsqrtf(ss*(1.f/64.f) - mean*mean + EPSV);
        float2 hv;
        hv.x = (v.x - mean)*rstd*gg.x + bbv.x;
        hv.y = (v.y - mean)*rstd*gg.y + bbv.y;
        ((float2*)g_h)[row*32 + lane] = hv;
        float2 st = make_float2(tf32f(hv.x), tf32f(hv.y));
        *(float2*)&As[lr*68 + 2*lane] = st;
    }
    __syncthreads();

    float acc[8][4];
    #pragma unroll
    for (int nt = 0; nt < 8; ++nt)
        #pragma unroll
        for (int r = 0; r < 4; ++r) acc[nt][r] = 0.f;
    #pragma unroll
    for (int kc = 0; kc < 8; ++kc) {
        unsigned a[4];
        const float* ap = As + (warp*16 + gid)*68 + kc*8;
        a[0] = __float_as_uint(ap[tig]);
        a[1] = __float_as_uint(ap[8*68 + tig]);
        a[2] = __float_as_uint(ap[tig + 4]);
        a[3] = __float_as_uint(ap[8*68 + tig + 4]);
        #pragma unroll
        for (int nt = 0; nt < 8; ++nt) {
            float2 bv = *(const float2*)&WF[(nt*8 + kc)*64 + lane*2];
            mma_tf32(acc[nt], a, bv);
        }
    }

    #pragma unroll
    for (int nt = 0; nt < 8; ++nt) {
        int col = nt*8 + tig*2;
        float2 qbv = *(const float2*)&qb[col];
        int row = rowbase + warp*16 + gid;
        float2 o0 = make_float2((acc[nt][0] + qbv.x)*QSCALE, (acc[nt][1] + qbv.y)*QSCALE);
        float2 o1 = make_float2((acc[nt][2] + qbv.x)*QSCALE, (acc[nt][3] + qbv.y)*QSCALE);
        *(float2*)&g_q[(size_t)row*64 + col]     = o0;
        *(float2*)&g_q[(size_t)(row+8)*64 + col] = o1;
    }
}

// =====================================================================
// K2w: pack sr_w (4096x64 fp32) into tf32 m16n8k8 B-fragments.
// word t = ((kc*8 + nt)*32 + ln)*2 + j :
//   k = kc*8 + (ln&3) + 4j, col = nt*8 + (ln>>2)
// grid 1024, block 256.
// =====================================================================
__global__ __launch_bounds__(256) void k2w_pack(const float* __restrict__ srw)
{
    int t = blockIdx.x*256 + threadIdx.x;  // 0..262143
    int j  = t & 1;
    int ln = (t >> 1) & 31;
    int nt = (t >> 6) & 7;
    int kc = t >> 9;
    int k   = kc*8 + (ln & 3) + 4*j;
    int col = nt*8 + (ln >> 2);
    g_srwfT[t] = tf32f(srw[(size_t)k*64 + col]);
}

// =====================================================================
// K2: sr conv via tf32 mma, A direct from g_h (L1-cached across warps).
// 16 positions/block (one oh row). grid 128, block 256 (warp = n8 tile).
// smem: xr fp32 [16][68] = 4352 B only.
// =====================================================================
__global__ __launch_bounds__(256) void k2_sr_kv(
    const float* __restrict__ srb,
    const float* __restrict__ sng, const float* __restrict__ snb,
    const float* __restrict__ kvw, const float* __restrict__ kvb)
{
    extern __shared__ float xr[];                        // [16][68]
    int tid = threadIdx.x, warp = tid >> 5, lane = tid & 31;
    int gid = lane >> 2, tig = lane & 3;

    int basepos = blockIdx.x * 16;
    int b  = basepos >> 8;
    int oh = (basepos & 255) >> 4;      // this block covers ow = 0..15 of row oh

    // ---- conv: m16 (positions) x n8 (out-ch tile = warp) x k4096 ----
    {
        float acc[4] = {0.f, 0.f, 0.f, 0.f};
        const float* hb = g_h + ((size_t)b*NN + (size_t)oh*8*WW)*64;
        const float2* bw = (const float2*)g_srwfT;
        int nt = warp;
        int pos0 = gid, pos1 = gid + 8;
        #pragma unroll 8
        for (int kc = 0; kc < 512; ++kc) {
            int i0 = kc >> 6;
            int p0 = (kc >> 3) & 7;
            int c0 = (kc & 7)*8 + tig;
            int off = (i0*WW + p0)*64 + c0;
            unsigned a[4];
            a[0] = __float_as_uint(tf32f(hb[off + pos0*512]));
            a[1] = __float_as_uint(tf32f(hb[off + pos1*512]));
            a[2] = __float_as_uint(tf32f(hb[off + pos0*512 + 4]));
            a[3] = __float_as_uint(tf32f(hb[off + pos1*512 + 4]));
            float2 bv = bw[(kc*8 + nt)*32 + lane];
            mma_tf32(acc, a, bv);
        }
        float2 sb2 = *(const float2*)&srb[nt*8 + 2*tig];
        int col = nt*8 + 2*tig;
        *(float2*)&xr[gid*68 + col]     = make_float2(acc[0] + sb2.x, acc[1] + sb2.y);
        *(float2*)&xr[(gid+8)*68 + col] = make_float2(acc[2] + sb2.x, acc[3] + sb2.y);
    }
    __syncthreads();

    // ---- LN over each of 16 rows (warp per 2 rows) ----
    {
        float2 sg  = ((const float2*)sng)[lane];
        float2 sbb = ((const float2*)snb)[lane];
        #pragma unroll
        for (int rr = 0; rr < 2; ++rr) {
            int r = warp*2 + rr;
            float2 v = ((float2*)xr)[r*34 + lane];
            float s = v.x + v.y, ss = v.x*v.x + v.y*v.y;
            #pragma unroll
            for (int o = 16; o; o >>= 1) {
                s  += __shfl_xor_sync(0xffffffffu, s,  o);
                ss += __shfl_xor_sync(0xffffffffu, ss, o);
            }
            float mean = s*(1.f/64.f);
            float rstd = rsqrtf(ss*(1.f/64.f) - mean*mean + EPSV);
            float2 nv;
            nv.x = (v.x-mean)*rstd*sg.x + sbb.x;
            nv.y = (v.y-mean)*rstd*sg.y + sbb.y;
            ((float2*)xr)[r*34 + lane] = nv;
        }
    }
    __syncthreads();

    // ---- kv proj: thread = kv channel (0..127) x row-half ----
    {
        int ch = tid & 127, rh = tid >> 7;
        float ak[8];
        float kb = kvb[ch];
        #pragma unroll
        for (int r = 0; r < 8; ++r) ak[r] = kb;
        #pragma unroll 4
        for (int j = 0; j < 64; ++j) {
            float w = kvw[j*128 + ch];
            #pragma unroll
            for (int r = 0; r < 8; ++r) ak[r] += xr[(rh*8 + r)*68 + j] * w;
        }
        #pragma unroll
        for (int r = 0; r < 8; ++r) {
            int pos = basepos + rh*8 + r;
            if (ch < 64) g_k[pos*64 + ch]      = ak[r];
            else         g_v[pos*64 + ch - 64] = ak[r];
        }
    }
}

// =====================================================================
// K2b: repack K, V, proj_w into tf32 mma B-fragment order. grid 64, block 256.
// =====================================================================
__global__ __launch_bounds__(256) void k2b_pack(const float* __restrict__ pw)
{
    int t = blockIdx.x*256 + threadIdx.x;   // 0..16383
    {   // KF: [nt32][kc8][ln32][2]
        int j = t & 1, ln = (t>>1)&31, kc = (t>>6)&7, nt = t>>9;
        int key = nt*8 + (ln>>2), d = kc*8 + (ln&3) + 4*j;
        #pragma unroll
        for (int b = 0; b < 8; ++b)
            g_kf[b*16384 + t] = g_k[(b*256+key)*64 + d];
    }
    {   // VF: [nt8][kc32][ln32][2]
        int j = t & 1, ln = (t>>1)&31, kc = (t>>6)&31, nt = t>>11;
        int key = kc*8 + (ln&3) + 4*j, col = nt*8 + (ln>>2);
        #pragma unroll
        for (int b = 0; b < 8; ++b)
            g_vf[b*16384 + t] = g_v[(b*256+key)*64 + col];
    }
    if (t < 4096) {  // PWF: [nt8][kc8][ln32][2]
        int j = t & 1, ln = (t>>1)&31, kc = (t>>6)&7, nt = t>>9;
        int k = kc*8 + (ln&3) + 4*j, col = nt*8 + (ln>>2);
        g_pwf[t] = pw[k*64 + col];
    }
}

// =====================================================================
// K3: attention via tf32 mma, 4 query-tiles per block.
// grid 512 (8 b x 64 groups), block 512 (16 warps).
// =====================================================================
__global__ __launch_bounds__(512) void k3_attn(
    const float* __restrict__ x, const float* __restrict__ pb)
{
    extern __shared__ float sm3[];
    float* KF = sm3;                  // 16384
    float* VF = sm3 + 16384;          // 16384
    float* WF = sm3 + 32768;          // 4096
    float* S  = sm3 + 36864;          // [64][260]
    float* Qs = sm3 + 36864 + 16640;  // [64][68], reused as Os

    int tid = threadIdx.x, warp = tid >> 5, lane = tid & 31;
    int gid = lane >> 2, tig = lane & 3;
    int b = blockIdx.x >> 6, grp = blockIdx.x & 63;
    float* Os = Qs;

    {
        const float4* kf4 = (const float4*)(g_kf + b*16384);
        const float4* vf4 = (const float4*)(g_vf + b*16384);
        float4* KF4 = (float4*)KF;
        float4* VF4 = (float4*)VF;
        #pragma unroll 4
        for (int i = tid; i < 4096; i += 512) { KF4[i] = kf4[i]; VF4[i] = vf4[i]; }
        const float4* w4 = (const float4*)g_pwf;
        float4* WF4 = (float4*)WF;
        #pragma unroll
        for (int i = tid; i < 1024; i += 512) WF4[i] = w4[i];
    }

    int wy = warp >> 2, wx = warp & 3;

    for (int it = 0; it < 4; ++it) {
        int q0 = (grp*4 + it) * 64;
        __syncthreads();
        {
            const float4* q4 = (const float4*)(g_q + ((size_t)b*NN + q0)*64);
            #pragma unroll
            for (int i = tid; i < 1024; i += 512) {
                int r = i >> 4, c = i & 15;
                *(float4*)&Qs[r*68 + c*4] = q4[i];
            }
        }
        __syncthreads();

        // ---- QK: warp tile m16 x n64 ----
        {
            float acc[8][4];
            #pragma unroll
            for (int nt = 0; nt < 8; ++nt)
                #pragma unroll
                for (int r = 0; r < 4; ++r) acc[nt][r] = 0.f;
            #pragma unroll
            for (int kc = 0; kc < 8; ++kc) {
                unsigned a[4];
                const float* ap = Qs + (wy*16 + gid)*68 + kc*8;
                a[0] = __float_as_uint(ap[tig]);
                a[1] = __float_as_uint(ap[8*68 + tig]);
                a[2] = __float_as_uint(ap[tig + 4]);
                a[3] = __float_as_uint(ap[8*68 + tig + 4]);
                #pragma unroll
                for (int nt = 0; nt < 8; ++nt) {
                    float2 bv = *(const float2*)&KF[((wx*8 + nt)*8 + kc)*64 + lane*2];
                    mma_tf32(acc[nt], a, bv);
                }
            }
            int r0 = wy*16 + gid;
            #pragma unroll
            for (int nt = 0; nt < 8; ++nt) {
                int cb = wx*64 + nt*8 + tig*2;
                *(float2*)&S[r0*260 + cb]     = make_float2(acc[nt][0], acc[nt][1]);
                *(float2*)&S[(r0+8)*260 + cb] = make_float2(acc[nt][2], acc[nt][3]);
            }
        }
        __syncthreads();

        // ---- softmax over 256 cols (warp per 4 rows) ----
        {
            float4* S4 = (float4*)S;       // row stride 65 float4
            #pragma unroll
            for (int i = 0; i < 4; ++i) {
                int r = warp*4 + i;
                float4 v0 = S4[r*65 + lane*2];
                float4 v1 = S4[r*65 + lane*2 + 1];
                float mx = fmaxf(fmaxf(fmaxf(v0.x, v0.y), fmaxf(v0.z, v0.w)),
                                 fmaxf(fmaxf(v1.x, v1.y), fmaxf(v1.z, v1.w)));
                #pragma unroll
                for (int o = 16; o; o >>= 1) mx = fmaxf(mx, __shfl_xor_sync(0xffffffffu, mx, o));
                v0.x = __expf(v0.x - mx); v0.y = __expf(v0.y - mx);
                v0.z = __expf(v0.z - mx); v0.w = __expf(v0.w - mx);
                v1.x = __expf(v1.x - mx); v1.y = __expf(v1.y - mx);
                v1.z = __expf(v1.z - mx); v1.w = __expf(v1.w - mx);
                float sum = v0.x + v0.y + v0.z + v0.w + v1.x + v1.y + v1.z + v1.w;
                #pragma unroll
                for (int o = 16; o; o >>= 1) sum += __shfl_xor_sync(0xffffffffu, sum, o);
                float inv = __frcp_rn(sum);
                v0.x *= inv; v0.y *= inv; v0.z *= inv; v0.w *= inv;
                v1.x *= inv; v1.y *= inv; v1.z *= inv; v1.w *= inv;
                S4[r*65 + lane*2]     = v0;
                S4[r*65 + lane*2 + 1] = v1;
            }
        }
        __syncthreads();

        // ---- PV: warp tile m16 x n16, K=256 ----
        float accO[2][4];
        #pragma unroll
        for (int nt = 0; nt < 2; ++nt)
            #pragma unroll
            for (int r = 0; r < 4; ++r) accO[nt][r] = 0.f;
        #pragma unroll 4
        for (int kc = 0; kc < 32; ++kc) {
            unsigned a[4];
            const float* ap = S + (wy*16 + gid)*260 + kc*8;
            a[0] = __float_as_uint(ap[tig]);
            a[1] = __float_as_uint(ap[8*260 + tig]);
            a[2] = __float_as_uint(ap[tig + 4]);
            a[3] = __float_as_uint(ap[8*260 + tig + 4]);
            #pragma unroll
            for (int nt = 0; nt < 2; ++nt) {
                float2 bv = *(const float2*)&VF[((wx*2 + nt)*32 + kc)*64 + lane*2];
                mma_tf32(accO[nt], a, bv);
            }
        }
        __syncthreads();
        {
            int r0 = wy*16 + gid;
            #pragma unroll
            for (int nt = 0; nt < 2; ++nt) {
                int cb = wx*16 + nt*8 + tig*2;
                *(float2*)&Os[r0*68 + cb]     = make_float2(accO[nt][0], accO[nt][1]);
                *(float2*)&Os[(r0+8)*68 + cb] = make_float2(accO[nt][2], accO[nt][3]);
            }
        }
        __syncthreads();

        // ---- proj: warp tile m16 x n16, K=64 ----
        float accP[2][4];
        #pragma unroll
        for (int nt = 0; nt < 2; ++nt)
            #pragma unroll
            for (int r = 0; r < 4; ++r) accP[nt][r] = 0.f;
        #pragma unroll
        for (int kc = 0; kc < 8; ++kc) {
            unsigned a[4];
            const float* ap = Os + (wy*16 + gid)*68 + kc*8;
            a[0] = __float_as_uint(ap[tig]);
            a[1] = __float_as_uint(ap[8*68 + tig]);
            a[2] = __float_as_uint(ap[tig + 4]);
            a[3] = __float_as_uint(ap[8*68 + tig + 4]);
            #pragma unroll
            for (int nt = 0; nt < 2; ++nt) {
                float2 bv = *(const float2*)&WF[((wx*2 + nt)*8 + kc)*64 + lane*2];
                mma_tf32(accP[nt], a, bv);
            }
        }

        #pragma unroll
        for (int nt = 0; nt < 2; ++nt) {
            int col = wx*16 + nt*8 + tig*2;
            float2 pbv = *(const float2*)&pb[col];
            size_t rowA = (size_t)b*NN + q0 + wy*16 + gid;
            size_t rowB = rowA + 8;
            float2 xa = *(const float2*)&x[rowA*64 + col];
            float2 xb = *(const float2*)&x[rowB*64 + col];
            float2 oa = make_float2(xa.x + accP[nt][0] + pbv.x, xa.y + accP[nt][1] + pbv.y);
            float2 ob = make_float2(xb.x + accP[nt][2] + pbv.x, xb.y + accP[nt][3] + pbv.y);
            *(float2*)&g_x2[rowA*64 + col] = oa;
            *(float2*)&g_x2[rowB*64 + col] = ob;
        }
    }
}

// =====================================================================
// K4: LN2 + fc1 via tf32 mma, bf16 output. grid 2048, block 256.
// =====================================================================
__global__ __launch_bounds__(256) void k4_ln_fc1(
    const float* __restrict__ g2, const float* __restrict__ b2,
    const float* __restrict__ w1, const float* __restrict__ fb1)
{
    extern __shared__ float sm4[];
    float* WF = sm4;            // [16 nt][8 kc][32 ln][2]
    float* As = sm4 + 8192;     // [128][68]
    int tid = threadIdx.x, warp = tid >> 5, lane = tid & 31;
    int gid = lane >> 2, tig = lane & 3;
    int cb = blockIdx.x & 1;
    int rowbase = (blockIdx.x >> 1) * 128;

    for (int idx = tid; idx < 8192; idx += 256) {
        int nt = idx >> 9, kc = (idx >> 6) & 7, ln = (idx >> 1) & 31, j = idx & 1;
        int k = kc*8 + (ln & 3) + j*4;
        int col = cb*128 + nt*8 + (ln >> 2);
        WF[idx] = tf32f(w1[k*256 + col]);
    }

    float2 gg = ((const float2*)g2)[lane];
    float2 bb = ((const float2*)b2)[lane];
    #pragma unroll
    for (int i = 0; i < 16; ++i) {
        int lr = warp*16 + i;
        int row = rowbase + lr;
        float2 v = ((const float2*)g_x2)[row*32 + lane];
        float s = v.x + v.y, ss = v.x*v.x + v.y*v.y;
        #pragma unroll
        for (int o = 16; o; o >>= 1) {
            s  += __shfl_xor_sync(0xffffffffu, s,  o);
            ss += __shfl_xor_sync(0xffffffffu, ss, o);
        }
        float mean = s*(1.f/64.f);
        float rstd = rsqrtf(ss*(1.f/64.f) - mean*mean + EPSV);
        float2 st;
        st.x = tf32f((v.x-mean)*rstd*gg.x + bb.x);
        st.y = tf32f((v.y-mean)*rstd*gg.y + bb.y);
        *(float2*)&As[lr*68 + 2*lane] = st;
    }
    __syncthreads();

    int wy = warp >> 1, wx = warp & 1;
    float acc[2][8][4];
    #pragma unroll
    for (int mt = 0; mt < 2; ++mt)
        #pragma unroll
        for (int nt = 0; nt < 8; ++nt)
            #pragma unroll
            for (int r = 0; r < 4; ++r) acc[mt][nt][r] = 0.f;

    #pragma unroll
    for (int kc = 0; kc < 8; ++kc) {
        unsigned a[2][4];
        #pragma unroll
        for (int mt = 0; mt < 2; ++mt) {
            const float* ap = As + (wy*32 + mt*16 + gid)*68 + kc*8;
            a[mt][0] = __float_as_uint(ap[tig]);
            a[mt][1] = __float_as_uint(ap[8*68 + tig]);
            a[mt][2] = __float_as_uint(ap[tig + 4]);
            a[mt][3] = __float_as_uint(ap[8*68 + tig + 4]);
        }
        #pragma unroll
        for (int nt = 0; nt < 8; ++nt) {
            float2 bv = *(const float2*)&WF[((wx*8 + nt)*8 + kc)*64 + lane*2];
            mma_tf32(acc[0][nt], a[0], bv);
            mma_tf32(acc[1][nt], a[1], bv);
        }
    }

    #pragma unroll
    for (int mt = 0; mt < 2; ++mt)
        #pragma unroll
        for (int nt = 0; nt < 8; ++nt) {
            int col = cb*128 + (wx*8 + nt)*8 + tig*2;
            float2 fbv = *(const float2*)&fb1[col];
            int row = rowbase + wy*32 + mt*16 + gid;
            float2 o0 = make_float2(acc[mt][nt][0] + fbv.x, acc[mt][nt][1] + fbv.y);
            float2 o1 = make_float2(acc[mt][nt][2] + fbv.x, acc[mt][nt][3] + fbv.y);
            *(__nv_bfloat162*)&g_f[(size_t)row*HID + col]     = __float22bfloat162_rn(o0);
            *(__nv_bfloat162*)&g_f[(size_t)(row+8)*HID + col] = __float22bfloat162_rn(o1);
        }
}

// =====================================================================
// K5: depthwise 3x3 SAME + GELU, bf16, smem-tiled rolling conv.
// block = (b, 8 h-rows, 32 channels). grid 1024, block 256. smem 81920 B.
// =====================================================================
__global__ __launch_bounds__(256) void k5_dw_gelu(const float* __restrict__ dww)
{
    extern __shared__ __nv_bfloat16 s5b[];   // [10][128][32] bf16
    int tid = threadIdx.x;
    int blk = blockIdx.x;
    int ct = blk & 7, ht = (blk >> 3) & 15, b = blk >> 7;
    int c0 = ct * 32, h0 = ht * 8;
    #pragma unroll
    for (int r = 0; r < 10; ++r) {
        int h = h0 - 1 + r;
        uint4* dst = (uint4*)(s5b + r*4096);       // 512 x uint4 (8 bf16 each)
        if ((unsigned)h < 128u) {
            const uint4* src = (const uint4*)(g_f + ((size_t)b*NN + (size_t)h*WW)*HID + c0);
            for (int i = tid; i < 512; i += 256) {
                int px = i >> 2, q = i & 3;
                dst[i] = src[px*32 + q];
            }
        } else {
            uint4 z = make_uint4(0u,0u,0u,0u);
            for (int i = tid; i < 512; i += 256) dst[i] = z;
        }
    }
    __syncthreads();

    int cp = tid & 15, wi = tid >> 4;
    float2 wt[9];
    #pragma unroll
    for (int t = 0; t < 9; ++t)
        wt[t] = *(const float2*)&dww[t*HID + c0 + 2*cp];

    const __nv_bfloat162* s5p = (const __nv_bfloat162*)s5b;  // pair units; row = 2048 pairs

    #pragma unroll
    for (int ro = 0; ro < 8; ++ro) {
        const __nv_bfloat162* r0p = s5p + ro*2048 + cp;
        const __nv_bfloat162* r1p = r0p + 2048;
        const __nv_bfloat162* r2p = r1p + 2048;
        int w = wi * 8;
        float2 L0, L1, L2, C0, C1, C2;
        if (w == 0) {
            L0 = L1 = L2 = make_float2(0.f, 0.f);
        } else {
            L0 = __bfloat1622float2(r0p[(w-1)*16]);
            L1 = __bfloat1622float2(r1p[(w-1)*16]);
            L2 = __bfloat1622float2(r2p[(w-1)*16]);
        }
        C0 = __bfloat1622float2(r0p[w*16]);
        C1 = __bfloat1622float2(r1p[w*16]);
        C2 = __bfloat1622float2(r2p[w*16]);
        #pragma unroll
        for (int k = 0; k < 8; ++k) {
            float2 N0, N1, N2;
            if (w + 1 < 128) {
                N0 = __bfloat1622float2(r0p[(w+1)*16]);
                N1 = __bfloat1622float2(r1p[(w+1)*16]);
                N2 = __bfloat1622float2(r2p[(w+1)*16]);
            } else {
                N0 = N1 = N2 = make_float2(0.f, 0.f);
            }
            float2 acc = make_float2(0.f, 0.f);
            acc = ffma2(L0, wt[0], acc); acc = ffma2(C0, wt[1], acc); acc = ffma2(N0, wt[2], acc);
            acc = ffma2(L1, wt[3], acc); acc = ffma2(C1, wt[4], acc); acc = ffma2(N1, wt[5], acc);
            acc = ffma2(L2, wt[6], acc); acc = ffma2(C2, wt[7], acc); acc = ffma2(N2, wt[8], acc);
            float2 o;
            o.x = acc.x * normcdff(acc.x);
            o.y = acc.y * normcdff(acc.y);
            *(__nv_bfloat162*)&g_g[((size_t)b*NN + (size_t)(h0+ro)*WW + w)*HID + c0 + 2*cp] =
                __float22bfloat162_rn(o);
            L0 = C0; L1 = C1; L2 = C2;
            C0 = N0; C1 = N1; C2 = N2;
            ++w;
        }
    }
}

// =====================================================================
// K6: fc2 (256->64) + residual via tf32 mma, bf16 A input. grid 1024, block 256.
// =====================================================================
__global__ __launch_bounds__(256) void k6_fc2(
    const float* __restrict__ w2, const float* __restrict__ b2,
    float* __restrict__ out)
{
    extern __shared__ float sm6[];
    float* WF = sm6;             // [8 nt][32 kc][32 ln][2] = 16384
    float* As = sm6 + 16384;     // [128][68]
    int tid = threadIdx.x, warp = tid >> 5, lane = tid & 31;
    int gid = lane >> 2, tig = lane & 3;
    int rowbase = blockIdx.x * 128;

    for (int idx = tid; idx < 16384; idx += 256) {
        int nt = idx >> 11, kc = (idx >> 6) & 31, ln = (idx >> 1) & 31, j = idx & 1;
        int k = kc*8 + (ln & 3) + j*4;
        int col = nt*8 + (ln >> 2);
        WF[idx] = tf32f(w2[k*64 + col]);
    }

    float acc[8][4];
    #pragma unroll
    for (int nt = 0; nt < 8; ++nt)
        #pragma unroll
        for (int r = 0; r < 4; ++r) acc[nt][r] = 0.f;

    for (int kblk = 0; kblk < 4; ++kblk) {
        __syncthreads();
        for (int i = tid; i < 1024; i += 256) {
            int row = i >> 3, q = i & 7;
            uint4 u = *(const uint4*)&g_g[(size_t)(rowbase+row)*HID + kblk*64 + q*8];
            float2 f0 = __bfloat1622float2(*(__nv_bfloat162*)&u.x);
            float2 f1 = __bfloat1622float2(*(__nv_bfloat162*)&u.y);
            float2 f2 = __bfloat1622float2(*(__nv_bfloat162*)&u.z);
            float2 f3 = __bfloat1622float2(*(__nv_bfloat162*)&u.w);
            float* dp = &As[row*68 + q*8];
            dp[0] = f0.x; dp[1] = f0.y; dp[2] = f1.x; dp[3] = f1.y;
            dp[4] = f2.x; dp[5] = f2.y; dp[6] = f3.x; dp[7] = f3.y;
        }
        __syncthreads();
        #pragma unroll
        for (int kc = 0; kc < 8; ++kc) {
            unsigned a[4];
            const float* ap = As + (warp*16 + gid)*68 + kc*8;
            a[0] = __float_as_uint(ap[tig]);
            a[1] = __float_as_uint(ap[8*68 + tig]);
            a[2] = __float_as_uint(ap[tig + 4]);
            a[3] = __float_as_uint(ap[8*68 + tig + 4]);
            #pragma unroll
            for (int nt = 0; nt < 8; ++nt) {
                float2 bv = *(const float2*)&WF[(nt*32 + kblk*8 + kc)*64 + lane*2];
                mma_tf32(acc[nt], a, bv);
            }
        }
    }

    #pragma unroll
    for (int nt = 0; nt < 8; ++nt) {
        int col = nt*8 + tig*2;
        float2 bbv = *(const float2*)&b2[col];
        int row = rowbase + warp*16 + gid;
        float2 r0 = *(const float2*)&g_x2[(size_t)row*CC + col];
        float2 r1 = *(const float2*)&g_x2[(size_t)(row+8)*CC + col];
        float2 o0 = make_float2(r0.x + acc[nt][0] + bbv.x, r0.y + acc[nt][1] + bbv.y);
        float2 o1 = make_float2(r1.x + acc[nt][2] + bbv.x, r1.y + acc[nt][3] + bbv.y);
        *(float2*)&out[(size_t)row*CC + col]     = o0;
        *(float2*)&out[(size_t)(row+8)*CC + col] = o1;
    }
}

// =====================================================================
extern "C" void kernel_launch(void* const* d_in, const int* in_sizes, int n_in,
                              void* d_out, int out_size)
{
    const float* x     = (const float*)d_in[0];
    const float* ln1_g = (const float*)d_in[3];
    const float* ln1_b = (const float*)d_in[4];
    const float* q_w   = (const float*)d_in[5];
    const float* q_b   = (const float*)d_in[6];
    const float* kv_w  = (const float*)d_in[7];
    const float* kv_b  = (const float*)d_in[8];
    const float* pr_w  = (const float*)d_in[9];
    const float* pr_b  = (const float*)d_in[10];
    const float* sr_w  = (const float*)d_in[11];
    const float* sr_b  = (const float*)d_in[12];
    const float* srn_g = (const float*)d_in[13];
    const float* srn_b = (const float*)d_in[14];
    const float* ln2_g = (const float*)d_in[15];
    const float* ln2_b = (const float*)d_in[16];
    const float* fc1_w = (const float*)d_in[17];
    const float* fc1_b = (const float*)d_in[18];
    const float* dw_w  = (const float*)d_in[19];
    const float* fc2_w = (const float*)d_in[20];
    const float* fc2_b = (const float*)d_in[21];
    float* out = (float*)d_out;

    const int K1_SMEM = (4096 + 128*68) * 4;                    // 51200
    const int K2_SMEM = 16*68*4;                                // 4352
    const int K3_SMEM = (16384 + 16384 + 4096 + 64*260 + 64*68) * 4;  // 231424
    const int K4_SMEM = (8192 + 128*68) * 4;                    // 67584
    const int K5_SMEM = 10*128*32*2;                            // 81920
    const int K6_SMEM = (16384 + 128*68) * 4;                   // 100352

    cudaFuncSetAttribute(k1_ln_q,   cudaFuncAttributeMaxDynamicSharedMemorySize, K1_SMEM);
    cudaFuncSetAttribute(k3_attn,   cudaFuncAttributeMaxDynamicSharedMemorySize, K3_SMEM);
    cudaFuncSetAttribute(k4_ln_fc1, cudaFuncAttributeMaxDynamicSharedMemorySize, K4_SMEM);
    cudaFuncSetAttribute(k5_dw_gelu,cudaFuncAttributeMaxDynamicSharedMemorySize, K5_SMEM);
    cudaFuncSetAttribute(k6_fc2,    cudaFuncAttributeMaxDynamicSharedMemorySize, K6_SMEM);

    k1_ln_q  <<<1024, 256, K1_SMEM>>>(x, ln1_g, ln1_b, q_w, q_b);
    k2w_pack <<<1024, 256>>>(sr_w);
    k2_sr_kv <<<128, 256, K2_SMEM>>>(sr_b, srn_g, srn_b, kv_w, kv_b);
    k2b_pack <<<64, 256>>>(pr_w);
    k3_attn  <<<512, 512, K3_SMEM>>>(x, pr_b);
    k4_ln_fc1<<<2048, 256, K4_SMEM>>>(ln2_g, ln2_b, fc1_w, fc1_b);
    k5_dw_gelu<<<1024, 256, K5_SMEM>>>(dw_w);
    k6_fc2   <<<1024, 256, K6_SMEM>>>(fc2_w, fc2_b, out);
}